// round 5
// baseline (speedup 1.0000x reference)
#include <cuda_runtime.h>
#include <cuda_bf16.h>
#include <cstdint>
#include <math.h>

#define Bsz  2
#define Nseq 2048
#define Dm   512
#define Hh   8
#define DHd  512
#define Ff   4096
#define Mrows 4096   // Bsz*Nseq
#define BH   16      // Bsz*Hh

// ======================= scratch (device globals) ===========================
__device__ __align__(16) __nv_bfloat16 g_Xh[(size_t)Mrows * Dm];
__device__ __align__(16) __nv_bfloat16 g_Xl[(size_t)Mrows * Dm];
__device__ __align__(16) __nv_bfloat16 g_WTh[3 * (size_t)Ff * Dm];   // [mode][n][k]
__device__ __align__(16) __nv_bfloat16 g_WTl[3 * (size_t)Ff * Dm];
__device__ __align__(16) __nv_bfloat16 g_WoTh[(size_t)Dm * Dm];
__device__ __align__(16) __nv_bfloat16 g_WoTl[(size_t)Dm * Dm];
__device__ __align__(16) __nv_bfloat16 g_Qh[(size_t)Mrows * Ff];
__device__ __align__(16) __nv_bfloat16 g_Ql[(size_t)Mrows * Ff];
__device__ __align__(16) __nv_bfloat16 g_Kh[(size_t)Mrows * Ff];
__device__ __align__(16) __nv_bfloat16 g_Kl[(size_t)Mrows * Ff];
__device__ __align__(16) __nv_bfloat16 g_Vh[(size_t)Mrows * Ff];
__device__ __align__(16) __nv_bfloat16 g_Vl[(size_t)Mrows * Ff];
__device__ __align__(16) float         g_YH[(size_t)BH * Nseq * Dm];
__device__ __align__(16) __nv_bfloat16 g_Gh[(size_t)Mrows * Dm];
__device__ __align__(16) __nv_bfloat16 g_Gl[(size_t)Mrows * Dm];

// ======================= helpers ===========================================
__device__ __forceinline__ uint32_t smem_to_u32(const void* p) {
    uint32_t a;
    asm("{ .reg .u64 t; cvta.to.shared.u64 t, %1; cvt.u32.u64 %0, t; }" : "=r"(a) : "l"(p));
    return a;
}
#define SWZ(b) ((b) ^ (((b) >> 3) & 0x70))

#define LDSM_X4(r, addr) \
    asm volatile("ldmatrix.sync.aligned.m8n8.x4.shared.b16 {%0,%1,%2,%3}, [%4];" \
        : "=r"((r)[0]), "=r"((r)[1]), "=r"((r)[2]), "=r"((r)[3]) : "r"(addr))
#define LDSM_X4_T(r, addr) \
    asm volatile("ldmatrix.sync.aligned.m8n8.x4.trans.shared.b16 {%0,%1,%2,%3}, [%4];" \
        : "=r"((r)[0]), "=r"((r)[1]), "=r"((r)[2]), "=r"((r)[3]) : "r"(addr))

#define MMA_BF16(d, a, b0, b1) \
    asm volatile("mma.sync.aligned.m16n8k16.row.col.f32.bf16.bf16.f32 " \
        "{%0,%1,%2,%3}, {%4,%5,%6,%7}, {%8,%9}, {%0,%1,%2,%3};" \
        : "+f"((d)[0]), "+f"((d)[1]), "+f"((d)[2]), "+f"((d)[3]) \
        : "r"((a)[0]), "r"((a)[1]), "r"((a)[2]), "r"((a)[3]), "r"(b0), "r"(b1))

#define CP_ASYNC16(dst, src) \
    asm volatile("cp.async.cg.shared.global [%0], [%1], 16;" :: "r"(dst), "l"(src))
#define CP_COMMIT() asm volatile("cp.async.commit_group;")
#define CP_WAIT1()  asm volatile("cp.async.wait_group 1;")
#define CP_WAIT0()  asm volatile("cp.async.wait_group 0;")

// ======================= bf16 split helpers =================================
__device__ __forceinline__ unsigned bf2(float a, float b) {
    return (unsigned)__bfloat16_as_ushort(__float2bfloat16(a)) |
           ((unsigned)__bfloat16_as_ushort(__float2bfloat16(b)) << 16);
}
__device__ __forceinline__ void split_pair(float a, float b, unsigned& h, unsigned& l) {
    __nv_bfloat16 ah = __float2bfloat16(a), bh = __float2bfloat16(b);
    h = (unsigned)__bfloat16_as_ushort(ah) | ((unsigned)__bfloat16_as_ushort(bh) << 16);
    l = bf2(a - __bfloat162float(ah), b - __bfloat162float(bh));
}
__device__ __forceinline__ void split1(float a, __nv_bfloat16& h, __nv_bfloat16& l) {
    h = __float2bfloat16(a);
    l = __float2bfloat16(a - __bfloat162float(h));
}

// ======================= templated mma.sync GEMM core =======================
// CTA tile: AR x 128 (AR = 256 for proj, 128 for out), threads = 2*AR.
// Stage: Ah[AR*128B] Al[AR*128B] Bh[16KB] Bl[16KB]; 2 stages double-buffered.
template<int AR>
__device__ __forceinline__ void mma_chunkT(uint32_t sst, int lane, int wm, int wn,
                                           float (&acc)[4][4][4]) {
    const uint32_t aH = sst, aL = sst + AR * 128;
    const uint32_t bB = sst + 2 * AR * 128, bL = bB + 16384;
#pragma unroll
    for (int kk = 0; kk < 4; kk++) {
        uint32_t ah[4][4], al[4][4], bh[2][4], bl[2][4];
        const int arow = wm * 64 + (lane & 15);
        const int acolb = kk * 32 + ((lane >> 4) << 4);
#pragma unroll
        for (int mi = 0; mi < 4; mi++) {
            uint32_t off = SWZ(((arow + mi * 16) << 7) + acolb);
            LDSM_X4(ah[mi], aH + off);
            LDSM_X4(al[mi], aL + off);
        }
        const int brow = wn * 32 + (lane & 7) + ((lane >> 4) << 3);
        const int bcolb = kk * 32 + (((lane >> 3) & 1) << 4);
#pragma unroll
        for (int nb = 0; nb < 2; nb++) {
            uint32_t off = SWZ(((brow + nb * 16) << 7) + bcolb);
            LDSM_X4(bh[nb], bB + off);
            LDSM_X4(bl[nb], bL + off);
        }
#pragma unroll
        for (int mi = 0; mi < 4; mi++)
#pragma unroll
            for (int ni = 0; ni < 4; ni++) {
                const int nb = ni >> 1, p = (ni & 1) << 1;
                MMA_BF16(acc[mi][ni], ah[mi], bh[nb][p], bh[nb][p + 1]);
                MMA_BF16(acc[mi][ni], ah[mi], bl[nb][p], bl[nb][p + 1]);
                MMA_BF16(acc[mi][ni], al[mi], bh[nb][p], bh[nb][p + 1]);
            }
    }
}

template<int AR>
__device__ __forceinline__ void issue_chunkT(
    uint32_t sbase, int c, int t,
    const __nv_bfloat16* Ah, const __nv_bfloat16* Al, size_t sA,
    const __nv_bfloat16* Bh, const __nv_bfloat16* Bl, size_t sB)
{
    constexpr int STG = 2 * AR * 128 + 32768;
    constexpr int T = 2 * AR;
    const uint32_t sst = sbase + (uint32_t)(c & 1) * STG;
    const __nv_bfloat16* ah = Ah + (c << 6);
    const __nv_bfloat16* al = Al + (c << 6);
    const __nv_bfloat16* bhp = Bh + (c << 6);
    const __nv_bfloat16* blp = Bl + (c << 6);
#pragma unroll
    for (int i = 0; i < 4; i++) {                 // A: AR*8 units16 each (hi,lo)
        int u = t + i * T, r = u >> 3, cu = u & 7;
        uint32_t d = sst + SWZ((r << 7) + (cu << 4));
        CP_ASYNC16(d, ah + (size_t)r * sA + (cu << 3));
        CP_ASYNC16(d + AR * 128, al + (size_t)r * sA + (cu << 3));
    }
#pragma unroll
    for (int i = 0; i < 1024 / T; i++) {          // B: 1024 units16 each (hi,lo)
        int u = t + i * T, r = u >> 3, cu = u & 7;
        uint32_t d = sst + 2 * AR * 128 + SWZ((r << 7) + (cu << 4));
        CP_ASYNC16(d, bhp + (size_t)r * sB + (cu << 3));
        CP_ASYNC16(d + 16384, blp + (size_t)r * sB + (cu << 3));
    }
    CP_COMMIT();
}

template<int AR>
__device__ __forceinline__ void gemm_mmaT(
    const __nv_bfloat16* Ah, const __nv_bfloat16* Al, size_t sA,
    const __nv_bfloat16* Bh, const __nv_bfloat16* Bl, size_t sB,
    int K, uint32_t sbase, float (&acc)[4][4][4])
{
    constexpr int STG = 2 * AR * 128 + 32768;
    constexpr int WM = AR / 64;
    const int t = threadIdx.x;
    const int lane = t & 31, w = t >> 5, wm = w % WM, wn = w / WM;
#pragma unroll
    for (int mi = 0; mi < 4; mi++)
#pragma unroll
        for (int ni = 0; ni < 4; ni++)
#pragma unroll
            for (int r = 0; r < 4; r++) acc[mi][ni][r] = 0.f;

    const int NC = K >> 6;
    issue_chunkT<AR>(sbase, 0, t, Ah, Al, sA, Bh, Bl, sB);
    for (int c = 0; c < NC; c++) {
        if (c + 1 < NC) {
            issue_chunkT<AR>(sbase, c + 1, t, Ah, Al, sA, Bh, Bl, sB);
            CP_WAIT1();
        } else {
            CP_WAIT0();
        }
        __syncthreads();
        mma_chunkT<AR>(sbase + (uint32_t)(c & 1) * STG, lane, wm, wn, acc);
        __syncthreads();
    }
}

#define PROJ_SMEM (2 * (2 * 256 * 128 + 32768))   // 196608
#define OUT_SMEM  (2 * (2 * 128 * 128 + 32768))   // 131072

// ======================= prep kernels =======================================
__global__ __launch_bounds__(256) void xc_kernel(const float* __restrict__ x) {
    int i = blockIdx.x * 256 + threadIdx.x;
    float4 v = ((const float4*)x)[i];
    unsigned h0, l0, h1, l1;
    split_pair(v.x, v.y, h0, l0);
    split_pair(v.z, v.w, h1, l1);
    ((uint2*)g_Xh)[i] = make_uint2(h0, h1);
    ((uint2*)g_Xl)[i] = make_uint2(l0, l1);
}

__global__ void wt_kernel(const float* __restrict__ src, __nv_bfloat16* dh,
                          __nv_bfloat16* dl, int K, int NC) {
    __shared__ float tile[32][33];
    int n0 = blockIdx.x * 32, k0 = blockIdx.y * 32;
    int tx = threadIdx.x, ty = threadIdx.y;        // ty 0..7
#pragma unroll
    for (int r = 0; r < 4; r++)
        tile[ty + 8 * r][tx] = src[(size_t)(k0 + ty + 8 * r) * NC + n0 + tx];
    __syncthreads();
#pragma unroll
    for (int r = 0; r < 4; r++) {
        float v = tile[tx][ty + 8 * r];
        __nv_bfloat16 h, l;
        split1(v, h, l);
        size_t di = (size_t)(n0 + ty + 8 * r) * K + k0 + tx;
        dh[di] = h; dl[di] = l;
    }
}

// ======================= 1) QKV projection GEMM (256x128 tile) ==============
__global__ __launch_bounds__(512) void mm_proj_kernel(
    const float* __restrict__ cosr, const float* __restrict__ sinr,
    const float* __restrict__ bv)
{
    extern __shared__ __align__(128) char smem[];
    uint32_t sb = smem_to_u32(smem);
    const int mode = blockIdx.z;
    const int bm = blockIdx.y * 256, bn = blockIdx.x * 128;
    const __nv_bfloat16* Ah = g_Xh + (size_t)bm * Dm;
    const __nv_bfloat16* Al = g_Xl + (size_t)bm * Dm;
    const __nv_bfloat16* Bh = g_WTh + ((size_t)mode * Ff + bn) * Dm;
    const __nv_bfloat16* Bl = g_WTl + ((size_t)mode * Ff + bn) * Dm;
    float acc[4][4][4];
    gemm_mmaT<256>(Ah, Al, Dm, Bh, Bl, Dm, Dm, sb, acc);

    const int t = threadIdx.x, lane = t & 31, w = t >> 5, wm = w & 3, wn = w >> 2;
    if (mode == 2) {
#pragma unroll
        for (int mi = 0; mi < 4; mi++)
#pragma unroll
            for (int ni = 0; ni < 4; ni++) {
                int m = bm + wm * 64 + mi * 16 + (lane >> 2);
                int c = bn + wn * 32 + ni * 8 + ((lane & 3) << 1);
                float b0 = bv[c], b1 = bv[c + 1];
#pragma unroll
                for (int half = 0; half < 2; half++) {
                    int mm = m + half * 8;
                    unsigned hw, lw;
                    split_pair(acc[mi][ni][half * 2] + b0, acc[mi][ni][half * 2 + 1] + b1, hw, lw);
                    *(unsigned*)&g_Vh[(size_t)mm * Ff + c] = hw;
                    *(unsigned*)&g_Vl[(size_t)mm * Ff + c] = lw;
                }
            }
    } else {
        __nv_bfloat16* OH = (mode == 0) ? g_Qh : g_Kh;
        __nv_bfloat16* OL = (mode == 0) ? g_Ql : g_Kl;
#pragma unroll
        for (int mi = 0; mi < 4; mi++)
#pragma unroll
            for (int ni = 0; ni < 4; ni++) {
                int m0 = bm + wm * 64 + mi * 16 + (lane >> 2);
                int c = bn + wn * 32 + ni * 8 + ((lane & 3) << 1);
#pragma unroll
                for (int half = 0; half < 2; half++) {
                    int m = m0 + half * 8;
                    int n = m & (Nseq - 1);
                    float cr0 = cosr[(size_t)n * Ff + c];
                    float sr0 = sinr[(size_t)n * Ff + c];
                    float cr1 = cosr[(size_t)n * Ff + c + 1];
                    float sr1 = sinr[(size_t)n * Ff + c + 1];
                    float e = acc[mi][ni][half * 2];
                    float o = acc[mi][ni][half * 2 + 1];
                    float oe = e * cr0 - o * sr0;
                    float oo = o * cr1 + e * sr1;
                    unsigned hw, lw;
                    split_pair(oe, oo, hw, lw);
                    *(unsigned*)&OH[(size_t)m * Ff + c] = hw;
                    *(unsigned*)&OL[(size_t)m * Ff + c] = lw;
                }
            }
    }
}

// ======================= 2) fused flash attention (resident Q) ==============
#define IB 64
#define OFF_M    0
#define OFF_L    256
#define OFF_MRED 512
#define OFF_LRED 1536
#define OFF_P    3072      // 32KB: P hi panels, lo at +16384
#define OFF_Q    35840     // 128KB: Qh 8 panels * 8192, Ql at +65536
#define OFF_KV   166912    // 64KB: 2 stages * 32768 (K hi/lo or V hi/lo)
#define FUSED_SMEM 232448  // sm_10x max per block (227KB)

__device__ __forceinline__ void issue_Q(uint32_t qb, int t,
    const __nv_bfloat16* Qh0, const __nv_bfloat16* Ql0)
{
#pragma unroll
    for (int i = 0; i < 16; i++) {
        int u = t + (i << 8);
        int c = u >> 9, w2 = u & 511, r = w2 >> 3, cu = w2 & 7;
        uint32_t d = qb + c * 8192 + SWZ((r << 7) + (cu << 4));
        CP_ASYNC16(d, Qh0 + (size_t)r * Ff + c * 64 + (cu << 3));
        CP_ASYNC16(d + 65536, Ql0 + (size_t)r * Ff + c * 64 + (cu << 3));
    }
}

__device__ __forceinline__ void issue_K_chunk(uint32_t kst, int t,
    const __nv_bfloat16* Kh, const __nv_bfloat16* Kl)
{
#pragma unroll
    for (int i = 0; i < 4; i++) {
        int u = t + (i << 8), r = u >> 3, cu = u & 7;
        uint32_t d = kst + SWZ((r << 7) + (cu << 4));
        CP_ASYNC16(d, Kh + (size_t)r * Ff + (cu << 3));
        CP_ASYNC16(d + 16384, Kl + (size_t)r * Ff + (cu << 3));
    }
}

// V chunk: 16 tokens x 512 dh (hi+lo) = 32KB; layout [hi/lo][panel 8][tok 16][128B]
__device__ __forceinline__ void issue_V_chunk(uint32_t vst, int t,
    const __nv_bfloat16* Vh, const __nv_bfloat16* Vl)
{
#pragma unroll
    for (int i = 0; i < 4; i++) {
        int u = t + (i << 8);
        int panel = u >> 7, r = (u >> 3) & 15, cu = u & 7;
        uint32_t d = vst + panel * 2048 + SWZ((r << 7) + (cu << 4));
        CP_ASYNC16(d, Vh + (size_t)r * Ff + panel * 64 + (cu << 3));
        CP_ASYNC16(d + 16384, Vl + (size_t)r * Ff + panel * 64 + (cu << 3));
    }
}

__device__ __forceinline__ void s_mma_chunkQ(uint32_t qh_pan, uint32_t ql_pan,
                                             uint32_t kst, int lane, int wm, int wn,
                                             float (&acc)[2][4][4]) {
    const uint32_t kh = kst, kl = kst + 16384;
#pragma unroll
    for (int kk = 0; kk < 4; kk++) {
        uint32_t ah[2][4], al[2][4], bh[2][4], bl[2][4];
        const int acb = kk * 32 + ((lane >> 4) << 4);
#pragma unroll
        for (int mi = 0; mi < 2; mi++) {
            uint32_t off = SWZ(((wm * 32 + mi * 16 + (lane & 15)) << 7) + acb);
            LDSM_X4(ah[mi], qh_pan + off);
            LDSM_X4(al[mi], ql_pan + off);
        }
        const int brow = wn * 32 + (lane & 7) + ((lane >> 4) << 3);
        const int bcb = kk * 32 + (((lane >> 3) & 1) << 4);
#pragma unroll
        for (int nb = 0; nb < 2; nb++) {
            uint32_t off = SWZ(((brow + nb * 16) << 7) + bcb);
            LDSM_X4(bh[nb], kh + off);
            LDSM_X4(bl[nb], kl + off);
        }
#pragma unroll
        for (int mi = 0; mi < 2; mi++)
#pragma unroll
            for (int ni = 0; ni < 4; ni++) {
                const int nb = ni >> 1, p = (ni & 1) << 1;
                MMA_BF16(acc[mi][ni], ah[mi], bh[nb][p], bh[nb][p + 1]);
                MMA_BF16(acc[mi][ni], ah[mi], bl[nb][p], bl[nb][p + 1]);
                MMA_BF16(acc[mi][ni], al[mi], bh[nb][p], bh[nb][p + 1]);
            }
    }
}

__device__ __forceinline__ void pv_mma_chunk(uint32_t sb, uint32_t vst, int vc,
                                             int lane, int wm, int wn,
                                             float (&accO)[2][16][4]) {
    uint32_t ah[2][4], al[2][4];
    const int pp = vc >> 2;
    const int pcb = (vc & 3) * 32 + ((lane >> 4) << 4);
#pragma unroll
    for (int mi = 0; mi < 2; mi++) {
        uint32_t off = SWZ(((wm * 32 + mi * 16 + (lane & 15)) << 7) + pcb);
        LDSM_X4(ah[mi], sb + OFF_P + pp * 8192 + off);
        LDSM_X4(al[mi], sb + OFF_P + 16384 + pp * 8192 + off);
    }
    const int tok = (lane & 7) + ((lane >> 3) & 1) * 8;
#pragma unroll
    for (int np = 0; np < 8; np++) {
        const int panel = 2 * wn + (np >> 2);
        const int dhb = (np & 3) * 16 + ((lane >> 4) << 3);
        uint32_t off = panel * 2048 + SWZ((tok << 7) + (dhb << 1));
        uint32_t vbh[4], vbl[4];
        LDSM_X4_T(vbh, vst + off);
        LDSM_X4_T(vbl, vst + 16384 + off);
#pragma unroll
        for (int mi = 0; mi < 2; mi++)
#pragma unroll
            for (int q = 0; q < 2; q++) {
                float* d = accO[mi][np * 2 + q];
                MMA_BF16(d, ah[mi], vbh[q * 2], vbh[q * 2 + 1]);
                MMA_BF16(d, ah[mi], vbl[q * 2], vbl[q * 2 + 1]);
                MMA_BF16(d, al[mi], vbh[q * 2], vbh[q * 2 + 1]);
            }
    }
}

__global__ __launch_bounds__(256, 1) void fused_attn_kernel() {
    extern __shared__ __align__(128) char smem[];
    const uint32_t sb = smem_to_u32(smem);
    float* sm_m = (float*)(smem + OFF_M);
    float* sm_l = (float*)(smem + OFF_L);
    float* mred = (float*)(smem + OFF_MRED);
    float* lred = (float*)(smem + OFF_LRED);

    const int ib = 31 - blockIdx.x;            // heavy blocks first
    const int bh = blockIdx.y;
    const int b = bh >> 3, h = bh & 7;
    const int i0 = ib * IB;
    const int jlast = ib >> 1;
    const int t = threadIdx.x, lane = t & 31, w = t >> 5;
    const int wm = w & 1, wn = w >> 1;

    if (t < 64) { sm_m[t] = -1e30f; sm_l[t] = 0.f; }
    __syncthreads();

    const size_t colQ = (size_t)h * DHd;
    const __nv_bfloat16* Qh0 = g_Qh + (size_t)(b * Nseq + i0) * Ff + colQ;
    const __nv_bfloat16* Ql0 = g_Ql + (size_t)(b * Nseq + i0) * Ff + colQ;

    issue_Q(sb + OFF_Q, t, Qh0, Ql0);
    CP_COMMIT();

    float accO[2][16][4];
#pragma unroll
    for (int mi = 0; mi < 2; mi++)
#pragma unroll
        for (int ni = 0; ni < 16; ni++)
#pragma unroll
            for (int v = 0; v < 4; v++) accO[mi][ni][v] = 0.f;

    const int r0 = wm * 32 + (lane >> 2);

    for (int jb = 0; jb <= jlast; jb++) {
        const int j0 = jb << 7;
        const size_t krow0 = (size_t)(b * Nseq + j0);
        const __nv_bfloat16* Kh0 = g_Kh + krow0 * Ff + colQ;
        const __nv_bfloat16* Kl0 = g_Kl + krow0 * Ff + colQ;
        const __nv_bfloat16* Vh0 = g_Vh + krow0 * Ff + colQ;
        const __nv_bfloat16* Vl0 = g_Vl + krow0 * Ff + colQ;

        float accS[2][4][4];
#pragma unroll
        for (int mi = 0; mi < 2; mi++)
#pragma unroll
            for (int ni = 0; ni < 4; ni++)
#pragma unroll
                for (int v = 0; v < 4; v++) accS[mi][ni][v] = 0.f;

        // ---- S = Q K^T over 8 K-chunks of 64 (Q resident, K streamed) ----
        issue_K_chunk(sb + OFF_KV, t, Kh0, Kl0);
        CP_COMMIT();
        for (int c = 0; c < 8; c++) {
            if (c + 1 < 8) {
                issue_K_chunk(sb + OFF_KV + ((c + 1) & 1) * 32768, t,
                              Kh0 + ((c + 1) << 6), Kl0 + ((c + 1) << 6));
                CP_COMMIT();
                CP_WAIT1();
            } else {
                CP_WAIT0();
            }
            __syncthreads();
            s_mma_chunkQ(sb + OFF_Q + c * 8192, sb + OFF_Q + 65536 + c * 8192,
                         sb + OFF_KV + (c & 1) * 32768, lane, wm, wn, accS);
            __syncthreads();
        }

        // prefetch first two V chunks into the (now free) KV stages
        issue_V_chunk(sb + OFF_KV, t, Vh0, Vl0);
        CP_COMMIT();
        issue_V_chunk(sb + OFF_KV + 32768, t, Vh0 + (size_t)16 * Ff, Vl0 + (size_t)16 * Ff);
        CP_COMMIT();

        // ---- causal mask (diagonal j-block only) ----
        if (jb == jlast) {
#pragma unroll
            for (int mi = 0; mi < 2; mi++)
#pragma unroll
                for (int ni = 0; ni < 4; ni++)
#pragma unroll
                    for (int v = 0; v < 4; v++) {
                        int rg = i0 + wm * 32 + mi * 16 + (lane >> 2) + ((v >> 1) << 3);
                        int cg = j0 + wn * 32 + ni * 8 + ((lane & 3) << 1) + (v & 1);
                        if (cg > rg) accS[mi][ni][v] = -1e30f;
                    }
        }

        // ---- online softmax ----
        float lmax[4];
#pragma unroll
        for (int rs = 0; rs < 4; rs++) {
            const int mi = rs >> 1, hf = rs & 1;
            float m = -1e30f;
#pragma unroll
            for (int ni = 0; ni < 4; ni++)
                m = fmaxf(m, fmaxf(accS[mi][ni][hf * 2], accS[mi][ni][hf * 2 + 1]));
            lmax[rs] = m;
        }
#pragma unroll
        for (int x = 1; x <= 2; x <<= 1)
#pragma unroll
            for (int rs = 0; rs < 4; rs++)
                lmax[rs] = fmaxf(lmax[rs], __shfl_xor_sync(0xffffffffu, lmax[rs], x));
        if ((lane & 3) == 0) {
#pragma unroll
            for (int rs = 0; rs < 4; rs++)
                mred[wn * 64 + r0 + (rs >> 1) * 16 + (rs & 1) * 8] = lmax[rs];
        }
        __syncthreads();

        float Mn[4], alpha[4];
#pragma unroll
        for (int rs = 0; rs < 4; rs++) {
            const int r = r0 + (rs >> 1) * 16 + (rs & 1) * 8;
            float bm = fmaxf(fmaxf(mred[r], mred[64 + r]), fmaxf(mred[128 + r], mred[192 + r]));
            float mo = sm_m[r];
            float mn = fmaxf(mo, bm);
            Mn[rs] = mn;
            alpha[rs] = __expf(mo - mn);
        }

        float lsum[4] = {0.f, 0.f, 0.f, 0.f};
#pragma unroll
        for (int mi = 0; mi < 2; mi++)
#pragma unroll
            for (int ni = 0; ni < 4; ni++)
#pragma unroll
                for (int hf = 0; hf < 2; hf++) {
                    const int rs = mi * 2 + hf;
                    float p0 = __expf(accS[mi][ni][hf * 2] - Mn[rs]);
                    float p1 = __expf(accS[mi][ni][hf * 2 + 1] - Mn[rs]);
                    lsum[rs] += p0 + p1;
                    const int row = r0 + mi * 16 + hf * 8;
                    const int col = wn * 32 + ni * 8 + ((lane & 3) << 1);
                    const int panel = col >> 6, cc = col & 63;
                    unsigned hw, lw;
                    split_pair(p0, p1, hw, lw);
                    uint32_t off = SWZ((row << 7) + cc * 2);
                    *(unsigned*)(smem + OFF_P + panel * 8192 + off) = hw;
                    *(unsigned*)(smem + OFF_P + 16384 + panel * 8192 + off) = lw;
                }
#pragma unroll
        for (int x = 1; x <= 2; x <<= 1)
#pragma unroll
            for (int rs = 0; rs < 4; rs++)
                lsum[rs] += __shfl_xor_sync(0xffffffffu, lsum[rs], x);
        if ((lane & 3) == 0) {
#pragma unroll
            for (int rs = 0; rs < 4; rs++)
                lred[wn * 64 + r0 + (rs >> 1) * 16 + (rs & 1) * 8] = lsum[rs];
        }
        // rescale O
#pragma unroll
        for (int mi = 0; mi < 2; mi++)
#pragma unroll
            for (int ni = 0; ni < 16; ni++)
#pragma unroll
                for (int v = 0; v < 4; v++)
                    accO[mi][ni][v] *= alpha[mi * 2 + (v >> 1)];
        __syncthreads();
        if (wn == 0 && (lane & 3) == 0) {
#pragma unroll
            for (int rs = 0; rs < 4; rs++) {
                const int r = r0 + (rs >> 1) * 16 + (rs & 1) * 8;
                sm_m[r] = Mn[rs];
                sm_l[r] = sm_l[r] * alpha[rs] +
                          (lred[r] + lred[64 + r] + lred[128 + r] + lred[192 + r]);
            }
        }

        // ---- PV: O += P @ V over 8 token-chunks of 16 ----
        for (int vc = 0; vc < 8; vc++) {
            if (vc < 7) CP_WAIT1(); else CP_WAIT0();
            __syncthreads();
            pv_mma_chunk(sb, sb + OFF_KV + (vc & 1) * 32768, vc, lane, wm, wn, accO);
            __syncthreads();
            if (vc + 2 < 8) {
                issue_V_chunk(sb + OFF_KV + (vc & 1) * 32768, t,
                              Vh0 + (size_t)(vc + 2) * 16 * Ff,
                              Vl0 + (size_t)(vc + 2) * 16 * Ff);
                CP_COMMIT();
            }
        }
    }

    __syncthreads();
    float invl[4];
#pragma unroll
    for (int rs = 0; rs < 4; rs++)
        invl[rs] = 1.0f / sm_l[r0 + (rs >> 1) * 16 + (rs & 1) * 8];
#pragma unroll
    for (int mi = 0; mi < 2; mi++)
#pragma unroll
        for (int ni = 0; ni < 16; ni++)
#pragma unroll
            for (int hf = 0; hf < 2; hf++) {
                const int rs = mi * 2 + hf;
                const int row = i0 + r0 + mi * 16 + hf * 8;
                const int col = wn * 128 + ni * 8 + ((lane & 3) << 1);
                float2 o = make_float2(accO[mi][ni][hf * 2] * invl[rs],
                                       accO[mi][ni][hf * 2 + 1] * invl[rs]);
                *(float2*)&g_YH[((size_t)bh * Nseq + row) * Dm + col] = o;
            }
}

// ======================= 5) head-sum + QuickGELU + split ====================
__global__ __launch_bounds__(256) void reduce_kernel() {
    int idx = blockIdx.x * 256 + threadIdx.x;
    int m = idx >> 7;
    int c4 = (idx & 127) * 4;
    int b = m >> 11, n = m & (Nseq - 1);
    float4 s = make_float4(0.f, 0.f, 0.f, 0.f);
#pragma unroll
    for (int h = 0; h < Hh; h++) {
        const float4 v = *(const float4*)(g_YH + (size_t)((b * Hh + h) * Nseq + n) * Dm + c4);
        s.x += v.x; s.y += v.y; s.z += v.z; s.w += v.w;
    }
    s.x = s.x / (1.f + expf(-1.702f * s.x));
    s.y = s.y / (1.f + expf(-1.702f * s.y));
    s.z = s.z / (1.f + expf(-1.702f * s.z));
    s.w = s.w / (1.f + expf(-1.702f * s.w));
    unsigned h0, l0, h1, l1;
    split_pair(s.x, s.y, h0, l0);
    split_pair(s.z, s.w, h1, l1);
    *(uint2*)(g_Gh + (size_t)m * Dm + c4) = make_uint2(h0, h1);
    *(uint2*)(g_Gl + (size_t)m * Dm + c4) = make_uint2(l0, l1);
}

// ======================= 6) output projection ===============================
__global__ __launch_bounds__(256) void mm_out_kernel(const float* __restrict__ bo,
                                                     float* __restrict__ Outp) {
    extern __shared__ __align__(128) char smem[];
    uint32_t sb = smem_to_u32(smem);
    const int bm = blockIdx.y * 128, bn = blockIdx.x * 128;
    const __nv_bfloat16* Ah = g_Gh + (size_t)bm * Dm;
    const __nv_bfloat16* Al = g_Gl + (size_t)bm * Dm;
    const __nv_bfloat16* Bh = g_WoTh + (size_t)bn * Dm;
    const __nv_bfloat16* Bl = g_WoTl + (size_t)bn * Dm;
    float acc[4][4][4];
    gemm_mmaT<128>(Ah, Al, Dm, Bh, Bl, Dm, Dm, sb, acc);

    const int t = threadIdx.x, lane = t & 31, w = t >> 5, wm = w & 1, wn = w >> 1;
#pragma unroll
    for (int mi = 0; mi < 4; mi++)
#pragma unroll
        for (int ni = 0; ni < 4; ni++) {
            int m = bm + wm * 64 + mi * 16 + (lane >> 2);
            int c = bn + wn * 32 + ni * 8 + ((lane & 3) << 1);
            float b0 = bo[c], b1 = bo[c + 1];
            *(float2*)&Outp[(size_t)m * Dm + c] =
                make_float2(acc[mi][ni][0] + b0, acc[mi][ni][1] + b1);
            *(float2*)&Outp[(size_t)(m + 8) * Dm + c] =
                make_float2(acc[mi][ni][2] + b0, acc[mi][ni][3] + b1);
        }
}

// ======================= launch =============================================
extern "C" void kernel_launch(void* const* d_in, const int* in_sizes, int n_in,
                              void* d_out, int out_size)
{
    const float* x    = (const float*)d_in[0];
    const float* cosr = (const float*)d_in[1];
    const float* sinr = (const float*)d_in[2];
    // d_in[3] = target_mask (causal tril; handled analytically)
    const float* Wq   = (const float*)d_in[4];
    const float* Wk   = (const float*)d_in[5];
    const float* Wv   = (const float*)d_in[6];
    const float* bv   = (const float*)d_in[7];
    const float* Wo   = (const float*)d_in[8];
    const float* bo   = (const float*)d_in[9];
    float* out = (float*)d_out;

    cudaFuncSetAttribute(mm_proj_kernel,   cudaFuncAttributeMaxDynamicSharedMemorySize, PROJ_SMEM);
    cudaFuncSetAttribute(fused_attn_kernel, cudaFuncAttributeMaxDynamicSharedMemorySize, FUSED_SMEM);
    cudaFuncSetAttribute(mm_out_kernel,    cudaFuncAttributeMaxDynamicSharedMemorySize, OUT_SMEM);

    __nv_bfloat16 *wth, *wtl, *woth, *wotl;
    cudaGetSymbolAddress((void**)&wth,  g_WTh);
    cudaGetSymbolAddress((void**)&wtl,  g_WTl);
    cudaGetSymbolAddress((void**)&woth, g_WoTh);
    cudaGetSymbolAddress((void**)&wotl, g_WoTl);

    xc_kernel<<<2048, 256>>>(x);
    wt_kernel<<<dim3(128, 16), dim3(32, 8)>>>(Wq, wth + 0 * (size_t)Ff * Dm,
                                              wtl + 0 * (size_t)Ff * Dm, Dm, Ff);
    wt_kernel<<<dim3(128, 16), dim3(32, 8)>>>(Wk, wth + 1 * (size_t)Ff * Dm,
                                              wtl + 1 * (size_t)Ff * Dm, Dm, Ff);
    wt_kernel<<<dim3(128, 16), dim3(32, 8)>>>(Wv, wth + 2 * (size_t)Ff * Dm,
                                              wtl + 2 * (size_t)Ff * Dm, Dm, Ff);
    wt_kernel<<<dim3(16, 16), dim3(32, 8)>>>(Wo, woth, wotl, Dm, Dm);

    mm_proj_kernel<<<dim3(32, 16, 3), 512, PROJ_SMEM>>>(cosr, sinr, bv);
    fused_attn_kernel<<<dim3(32, BH), 256, FUSED_SMEM>>>();
    reduce_kernel<<<2048, 256>>>();
    mm_out_kernel<<<dim3(4, 32), 256, OUT_SMEM>>>(bo, out);
}

// round 6
// speedup vs baseline: 1.6201x; 1.6201x over previous
#include <cuda_runtime.h>
#include <cuda_bf16.h>
#include <cstdint>
#include <math.h>

#define Bsz  2
#define Nseq 2048
#define Dm   512
#define Hh   8
#define DHd  512
#define Ff   4096
#define Mrows 4096   // Bsz*Nseq
#define BH   16      // Bsz*Hh

// ======================= scratch (device globals) ===========================
__device__ __align__(16) __nv_bfloat16 g_Xh[(size_t)Mrows * Dm];
__device__ __align__(16) __nv_bfloat16 g_Xl[(size_t)Mrows * Dm];
__device__ __align__(16) __nv_bfloat16 g_WTh[3 * (size_t)Ff * Dm];   // [mode][n][k]
__device__ __align__(16) __nv_bfloat16 g_WTl[3 * (size_t)Ff * Dm];
__device__ __align__(16) __nv_bfloat16 g_WoTh[(size_t)Dm * Dm];
__device__ __align__(16) __nv_bfloat16 g_WoTl[(size_t)Dm * Dm];
__device__ __align__(16) __nv_bfloat16 g_Qh[(size_t)Mrows * Ff];
__device__ __align__(16) __nv_bfloat16 g_Ql[(size_t)Mrows * Ff];
__device__ __align__(16) __nv_bfloat16 g_Kh[(size_t)Mrows * Ff];
__device__ __align__(16) __nv_bfloat16 g_Kl[(size_t)Mrows * Ff];
__device__ __align__(16) float         g_V [(size_t)Mrows * Ff];
__device__ __align__(16) __nv_bfloat16 g_VTh[(size_t)BH * DHd * Nseq]; // [bh][f][tok]
__device__ __align__(16) __nv_bfloat16 g_VTl[(size_t)BH * DHd * Nseq];
__device__ __align__(16) float         g_S [(size_t)BH * Nseq * Nseq];
__device__ __align__(16) __nv_bfloat16 g_Ph[(size_t)BH * Nseq * Nseq];
__device__ __align__(16) __nv_bfloat16 g_Pl[(size_t)BH * Nseq * Nseq];
__device__ __align__(16) float         g_YH[(size_t)BH * Nseq * Dm];
__device__ __align__(16) __nv_bfloat16 g_Gh[(size_t)Mrows * Dm];
__device__ __align__(16) __nv_bfloat16 g_Gl[(size_t)Mrows * Dm];

// ======================= helpers ===========================================
__device__ __forceinline__ uint32_t smem_to_u32(const void* p) {
    uint32_t a;
    asm("{ .reg .u64 t; cvta.to.shared.u64 t, %1; cvt.u32.u64 %0, t; }" : "=r"(a) : "l"(p));
    return a;
}
// SW64 swizzle for 64-byte rows (8 rows x 64B atom)
#define SWZ64(b) ((b) ^ (((b) >> 3) & 0x30))

#define LDSM_X4(r, addr) \
    asm volatile("ldmatrix.sync.aligned.m8n8.x4.shared.b16 {%0,%1,%2,%3}, [%4];" \
        : "=r"((r)[0]), "=r"((r)[1]), "=r"((r)[2]), "=r"((r)[3]) : "r"(addr))

#define MMA_BF16(d, a, b0, b1) \
    asm volatile("mma.sync.aligned.m16n8k16.row.col.f32.bf16.bf16.f32 " \
        "{%0,%1,%2,%3}, {%4,%5,%6,%7}, {%8,%9}, {%0,%1,%2,%3};" \
        : "+f"((d)[0]), "+f"((d)[1]), "+f"((d)[2]), "+f"((d)[3]) \
        : "r"((a)[0]), "r"((a)[1]), "r"((a)[2]), "r"((a)[3]), "r"(b0), "r"(b1))

#define CP_ASYNC16(dst, src) \
    asm volatile("cp.async.cg.shared.global [%0], [%1], 16;" :: "r"(dst), "l"(src))
#define CP_COMMIT() asm volatile("cp.async.commit_group;")
#define CP_WAIT2()  asm volatile("cp.async.wait_group 2;")
#define CP_WAIT1()  asm volatile("cp.async.wait_group 1;")
#define CP_WAIT0()  asm volatile("cp.async.wait_group 0;")

// ======================= bf16 split helpers =================================
__device__ __forceinline__ unsigned bf2(float a, float b) {
    return (unsigned)__bfloat16_as_ushort(__float2bfloat16(a)) |
           ((unsigned)__bfloat16_as_ushort(__float2bfloat16(b)) << 16);
}
__device__ __forceinline__ void split_pair(float a, float b, unsigned& h, unsigned& l) {
    __nv_bfloat16 ah = __float2bfloat16(a), bh = __float2bfloat16(b);
    h = (unsigned)__bfloat16_as_ushort(ah) | ((unsigned)__bfloat16_as_ushort(bh) << 16);
    l = bf2(a - __bfloat162float(ah), b - __bfloat162float(bh));
}
__device__ __forceinline__ void split1(float a, __nv_bfloat16& h, __nv_bfloat16& l) {
    h = __float2bfloat16(a);
    l = __float2bfloat16(a - __bfloat162float(h));
}

// ======================= mma.sync GEMM core (K-chunk 32, 3-stage) ===========
// C[128x128] = Ah*Bh + Ah*Bl + Al*Bh over K (multiple of 32).
// A row-major [m][k], B row-major [n][k]. Stage 32KB: aH|aL|bH|bL (8KB each,
// 64B rows, SW64). 3 stages = 96KB -> 2 CTAs/SM. Warps 2(M) x 4(N), 64x32.
#define STG32 32768
#define GEMM_SMEM (3 * STG32)

__device__ __forceinline__ void mma_chunk32(uint32_t sst, int lane, int wm, int wn,
                                            float (&acc)[4][4][4]) {
    const uint32_t aH = sst, aL = sst + 8192, bB = sst + 16384, bL = sst + 24576;
#pragma unroll
    for (int kk = 0; kk < 2; kk++) {
        uint32_t bh[2][4], bl[2][4];
        const int brow = wn * 32 + (lane & 7) + ((lane >> 4) << 3);
        const int bcb = kk * 32 + (((lane >> 3) & 1) << 4);
#pragma unroll
        for (int nb = 0; nb < 2; nb++) {
            uint32_t off = SWZ64(((brow + nb * 16) << 6) + bcb);
            LDSM_X4(bh[nb], bB + off);
            LDSM_X4(bl[nb], bL + off);
        }
        const int acb = kk * 32 + ((lane >> 4) << 4);
#pragma unroll
        for (int mi = 0; mi < 4; mi++) {
            uint32_t ah[4], al[4];
            uint32_t off = SWZ64(((wm * 64 + mi * 16 + (lane & 15)) << 6) + acb);
            LDSM_X4(ah, aH + off);
            LDSM_X4(al, aL + off);
#pragma unroll
            for (int ni = 0; ni < 4; ni++) {
                const int nb = ni >> 1, p = (ni & 1) << 1;
                MMA_BF16(acc[mi][ni], ah, bh[nb][p], bh[nb][p + 1]);
                MMA_BF16(acc[mi][ni], ah, bl[nb][p], bl[nb][p + 1]);
                MMA_BF16(acc[mi][ni], al, bh[nb][p], bh[nb][p + 1]);
            }
        }
    }
}

__device__ __forceinline__ void issue_chunk32(
    uint32_t sbase, int c, int t,
    const __nv_bfloat16* Ah, const __nv_bfloat16* Al, size_t sA,
    const __nv_bfloat16* Bh, const __nv_bfloat16* Bl, size_t sB)
{
    const uint32_t sst = sbase + (uint32_t)(c % 3) * STG32;
    const __nv_bfloat16* ah = Ah + (c << 5);
    const __nv_bfloat16* al = Al + (c << 5);
    const __nv_bfloat16* bhp = Bh + (c << 5);
    const __nv_bfloat16* blp = Bl + (c << 5);
#pragma unroll
    for (int i = 0; i < 2; i++) {           // 512 units16 per tensor
        int u = t + (i << 8), r = u >> 2, cu = u & 3;
        uint32_t d = sst + SWZ64((r << 6) + (cu << 4));
        const size_t so = (size_t)r * sA + (cu << 3);
        CP_ASYNC16(d, ah + so);
        CP_ASYNC16(d + 8192, al + so);
    }
#pragma unroll
    for (int i = 0; i < 2; i++) {
        int u = t + (i << 8), r = u >> 2, cu = u & 3;
        uint32_t d = sst + 16384 + SWZ64((r << 6) + (cu << 4));
        const size_t so = (size_t)r * sB + (cu << 3);
        CP_ASYNC16(d, bhp + so);
        CP_ASYNC16(d + 8192, blp + so);
    }
    CP_COMMIT();
}

__device__ __forceinline__ void gemm_mma(
    const __nv_bfloat16* Ah, const __nv_bfloat16* Al, size_t sA,
    const __nv_bfloat16* Bh, const __nv_bfloat16* Bl, size_t sB,
    int K, uint32_t sbase, float (&acc)[4][4][4])
{
    const int t = threadIdx.x;
    const int lane = t & 31, w = t >> 5, wm = w & 1, wn = w >> 1;
#pragma unroll
    for (int mi = 0; mi < 4; mi++)
#pragma unroll
        for (int ni = 0; ni < 4; ni++)
#pragma unroll
            for (int r = 0; r < 4; r++) acc[mi][ni][r] = 0.f;

    const int NC = K >> 5;
    issue_chunk32(sbase, 0, t, Ah, Al, sA, Bh, Bl, sB);
    if (NC > 1) issue_chunk32(sbase, 1, t, Ah, Al, sA, Bh, Bl, sB);
    for (int c = 0; c < NC; c++) {
        if (c + 2 < NC) {
            issue_chunk32(sbase, c + 2, t, Ah, Al, sA, Bh, Bl, sB);
            CP_WAIT2();
        } else if (c + 1 < NC) {
            CP_WAIT1();
        } else {
            CP_WAIT0();
        }
        __syncthreads();
        mma_chunk32(sbase + (uint32_t)(c % 3) * STG32, lane, wm, wn, acc);
        __syncthreads();
    }
}

// ======================= prep kernels =======================================
__global__ __launch_bounds__(256) void xc_kernel(const float* __restrict__ x) {
    int i = blockIdx.x * 256 + threadIdx.x;
    float4 v = ((const float4*)x)[i];
    unsigned h0, l0, h1, l1;
    split_pair(v.x, v.y, h0, l0);
    split_pair(v.z, v.w, h1, l1);
    ((uint2*)g_Xh)[i] = make_uint2(h0, h1);
    ((uint2*)g_Xl)[i] = make_uint2(l0, l1);
}

__global__ void wt_kernel(const float* __restrict__ src, __nv_bfloat16* dh,
                          __nv_bfloat16* dl, int K, int NC) {
    __shared__ float tile[32][33];
    int n0 = blockIdx.x * 32, k0 = blockIdx.y * 32;
    int tx = threadIdx.x, ty = threadIdx.y;        // ty 0..7
#pragma unroll
    for (int r = 0; r < 4; r++)
        tile[ty + 8 * r][tx] = src[(size_t)(k0 + ty + 8 * r) * NC + n0 + tx];
    __syncthreads();
#pragma unroll
    for (int r = 0; r < 4; r++) {
        float v = tile[tx][ty + 8 * r];
        __nv_bfloat16 h, l;
        split1(v, h, l);
        size_t di = (size_t)(n0 + ty + 8 * r) * K + k0 + tx;
        dh[di] = h; dl[di] = l;
    }
}

// V [b][tok][F] (head slice) -> VT[bh][f][tok] hi/lo
__global__ void vt_kernel() {
    __shared__ float tile[32][33];
    int tok0 = blockIdx.x * 32, f0 = blockIdx.y * 32;
    int bh = blockIdx.z, b = bh >> 3, h = bh & 7;
    int tx = threadIdx.x, ty = threadIdx.y;        // ty 0..7
#pragma unroll
    for (int r = 0; r < 4; r++)
        tile[ty + 8 * r][tx] = g_V[(size_t)(b * Nseq + tok0 + ty + 8 * r) * Ff + h * DHd + f0 + tx];
    __syncthreads();
#pragma unroll
    for (int r = 0; r < 4; r++) {
        float v = tile[tx][ty + 8 * r];
        __nv_bfloat16 hh, ll;
        split1(v, hh, ll);
        size_t di = (size_t)bh * DHd * Nseq + (size_t)(f0 + ty + 8 * r) * Nseq + tok0 + tx;
        g_VTh[di] = hh; g_VTl[di] = ll;
    }
}

// ======================= 1) QKV projection GEMM + RoPE/bias epilogue ========
__global__ __launch_bounds__(256, 2) void mm_proj_kernel(
    const float* __restrict__ cosr, const float* __restrict__ sinr,
    const float* __restrict__ bv)
{
    extern __shared__ __align__(128) char smem[];
    uint32_t sb = smem_to_u32(smem);
    const int mode = blockIdx.z;
    const int bm = blockIdx.y * 128, bn = blockIdx.x * 128;
    const __nv_bfloat16* Ah = g_Xh + (size_t)bm * Dm;
    const __nv_bfloat16* Al = g_Xl + (size_t)bm * Dm;
    const __nv_bfloat16* Bh = g_WTh + ((size_t)mode * Ff + bn) * Dm;
    const __nv_bfloat16* Bl = g_WTl + ((size_t)mode * Ff + bn) * Dm;
    float acc[4][4][4];
    gemm_mma(Ah, Al, Dm, Bh, Bl, Dm, Dm, sb, acc);

    const int t = threadIdx.x, lane = t & 31, w = t >> 5, wm = w & 1, wn = w >> 1;
    if (mode == 2) {
#pragma unroll
        for (int mi = 0; mi < 4; mi++)
#pragma unroll
            for (int ni = 0; ni < 4; ni++) {
                int m = bm + wm * 64 + mi * 16 + (lane >> 2);
                int c = bn + wn * 32 + ni * 8 + ((lane & 3) << 1);
                float b0 = bv[c], b1 = bv[c + 1];
                *(float2*)&g_V[(size_t)m * Ff + c] =
                    make_float2(acc[mi][ni][0] + b0, acc[mi][ni][1] + b1);
                *(float2*)&g_V[(size_t)(m + 8) * Ff + c] =
                    make_float2(acc[mi][ni][2] + b0, acc[mi][ni][3] + b1);
            }
    } else {
        __nv_bfloat16* OH = (mode == 0) ? g_Qh : g_Kh;
        __nv_bfloat16* OL = (mode == 0) ? g_Ql : g_Kl;
#pragma unroll
        for (int mi = 0; mi < 4; mi++)
#pragma unroll
            for (int ni = 0; ni < 4; ni++) {
                int m0 = bm + wm * 64 + mi * 16 + (lane >> 2);
                int c = bn + wn * 32 + ni * 8 + ((lane & 3) << 1);
#pragma unroll
                for (int half = 0; half < 2; half++) {
                    int m = m0 + half * 8;
                    int n = m & (Nseq - 1);
                    float cr0 = cosr[(size_t)n * Ff + c];
                    float sr0 = sinr[(size_t)n * Ff + c];
                    float cr1 = cosr[(size_t)n * Ff + c + 1];
                    float sr1 = sinr[(size_t)n * Ff + c + 1];
                    float e = acc[mi][ni][half * 2];
                    float o = acc[mi][ni][half * 2 + 1];
                    float oe = e * cr0 - o * sr0;
                    float oo = o * cr1 + e * sr1;
                    unsigned hw, lw;
                    split_pair(oe, oo, hw, lw);
                    *(unsigned*)&OH[(size_t)m * Ff + c] = hw;
                    *(unsigned*)&OL[(size_t)m * Ff + c] = lw;
                }
            }
    }
}

// ======================= 2) S = Q K^T ======================================
__global__ __launch_bounds__(256, 2) void mm_score_kernel() {
    if (blockIdx.x > blockIdx.y) return;
    extern __shared__ __align__(128) char smem[];
    uint32_t sb = smem_to_u32(smem);
    const int bh = blockIdx.z, b = bh >> 3, h = bh & 7;
    const int i0 = blockIdx.y * 128, j0 = blockIdx.x * 128;
    const __nv_bfloat16* Ah = g_Qh + (size_t)(b * Nseq + i0) * Ff + h * DHd;
    const __nv_bfloat16* Al = g_Ql + (size_t)(b * Nseq + i0) * Ff + h * DHd;
    const __nv_bfloat16* Bh = g_Kh + (size_t)(b * Nseq + j0) * Ff + h * DHd;
    const __nv_bfloat16* Bl = g_Kl + (size_t)(b * Nseq + j0) * Ff + h * DHd;
    float acc[4][4][4];
    gemm_mma(Ah, Al, Ff, Bh, Bl, Ff, DHd, sb, acc);

    const int t = threadIdx.x, lane = t & 31, w = t >> 5, wm = w & 1, wn = w >> 1;
    float* Sp = g_S + (size_t)bh * Nseq * Nseq;
#pragma unroll
    for (int mi = 0; mi < 4; mi++)
#pragma unroll
        for (int ni = 0; ni < 4; ni++) {
            int m = i0 + wm * 64 + mi * 16 + (lane >> 2);
            int nn = j0 + wn * 32 + ni * 8 + ((lane & 3) << 1);
            *(float2*)&Sp[(size_t)m * Nseq + nn] = make_float2(acc[mi][ni][0], acc[mi][ni][1]);
            *(float2*)&Sp[(size_t)(m + 8) * Nseq + nn] = make_float2(acc[mi][ni][2], acc[mi][ni][3]);
        }
}

// ======================= 3) causal row softmax -> P hi/lo ===================
__global__ __launch_bounds__(256) void softmax_kernel() {
    const int rgl = blockIdx.x;
    const int bh = rgl >> 11, i = rgl & (Nseq - 1);
    const size_t base = (size_t)bh * Nseq * Nseq + (size_t)i * Nseq;
    const float* row = g_S + base;
    const int L = i + 1;
    const int Lz = ((i >> 7) + 1) << 7;
    const int t = threadIdx.x;

    float v[8];
    int cnt = 0;
    float mx = -1e30f;
    for (int j = t; j < L; j += 256) { float x = row[j]; v[cnt++] = x; mx = fmaxf(mx, x); }

    __shared__ float red[256];
    red[t] = mx; __syncthreads();
    for (int s = 128; s > 0; s >>= 1) { if (t < s) red[t] = fmaxf(red[t], red[t + s]); __syncthreads(); }
    mx = red[0]; __syncthreads();

    float sum = 0.f;
    for (int k = 0; k < cnt; k++) { v[k] = expf(v[k] - mx); sum += v[k]; }
    red[t] = sum; __syncthreads();
    for (int s = 128; s > 0; s >>= 1) { if (t < s) red[t] += red[t + s]; __syncthreads(); }
    const float inv = 1.0f / red[0];

    cnt = 0;
    for (int j = t; j < L; j += 256) {
        float p = v[cnt++] * inv;
        __nv_bfloat16 h, l;
        split1(p, h, l);
        g_Ph[base + j] = h; g_Pl[base + j] = l;
    }
    const __nv_bfloat16 z = __float2bfloat16(0.f);
    for (int j = t; j < Lz; j += 256)
        if (j >= L) { g_Ph[base + j] = z; g_Pl[base + j] = z; }
}

// ======================= 4) Yh = P @ V ======================================
__global__ __launch_bounds__(256, 2) void mm_pv_kernel() {
    extern __shared__ __align__(128) char smem[];
    uint32_t sb = smem_to_u32(smem);
    const int bh = blockIdx.z;
    const int i0 = blockIdx.y * 128, n0 = blockIdx.x * 128;
    const __nv_bfloat16* Ah = g_Ph + (size_t)bh * Nseq * Nseq + (size_t)i0 * Nseq;
    const __nv_bfloat16* Al = g_Pl + (size_t)bh * Nseq * Nseq + (size_t)i0 * Nseq;
    const __nv_bfloat16* Bh = g_VTh + (size_t)bh * DHd * Nseq + (size_t)n0 * Nseq;
    const __nv_bfloat16* Bl = g_VTl + (size_t)bh * DHd * Nseq + (size_t)n0 * Nseq;
    float acc[4][4][4];
    gemm_mma(Ah, Al, Nseq, Bh, Bl, Nseq, i0 + 128, sb, acc);

    const int t = threadIdx.x, lane = t & 31, w = t >> 5, wm = w & 1, wn = w >> 1;
    float* Yp = g_YH + (size_t)bh * Nseq * Dm;
#pragma unroll
    for (int mi = 0; mi < 4; mi++)
#pragma unroll
        for (int ni = 0; ni < 4; ni++) {
            int m = i0 + wm * 64 + mi * 16 + (lane >> 2);
            int nn = n0 + wn * 32 + ni * 8 + ((lane & 3) << 1);
            *(float2*)&Yp[(size_t)m * Dm + nn] = make_float2(acc[mi][ni][0], acc[mi][ni][1]);
            *(float2*)&Yp[(size_t)(m + 8) * Dm + nn] = make_float2(acc[mi][ni][2], acc[mi][ni][3]);
        }
}

// ======================= 5) head-sum + QuickGELU + split ====================
__global__ __launch_bounds__(256) void reduce_kernel() {
    int idx = blockIdx.x * 256 + threadIdx.x;
    int m = idx >> 7;
    int c4 = (idx & 127) * 4;
    int b = m >> 11, n = m & (Nseq - 1);
    float4 s = make_float4(0.f, 0.f, 0.f, 0.f);
#pragma unroll
    for (int h = 0; h < Hh; h++) {
        const float4 v = *(const float4*)(g_YH + (size_t)((b * Hh + h) * Nseq + n) * Dm + c4);
        s.x += v.x; s.y += v.y; s.z += v.z; s.w += v.w;
    }
    s.x = s.x / (1.f + expf(-1.702f * s.x));
    s.y = s.y / (1.f + expf(-1.702f * s.y));
    s.z = s.z / (1.f + expf(-1.702f * s.z));
    s.w = s.w / (1.f + expf(-1.702f * s.w));
    unsigned h0, l0, h1, l1;
    split_pair(s.x, s.y, h0, l0);
    split_pair(s.z, s.w, h1, l1);
    *(uint2*)(g_Gh + (size_t)m * Dm + c4) = make_uint2(h0, h1);
    *(uint2*)(g_Gl + (size_t)m * Dm + c4) = make_uint2(l0, l1);
}

// ======================= 6) output projection ===============================
__global__ __launch_bounds__(256, 2) void mm_out_kernel(const float* __restrict__ bo,
                                                        float* __restrict__ Outp) {
    extern __shared__ __align__(128) char smem[];
    uint32_t sb = smem_to_u32(smem);
    const int bm = blockIdx.y * 128, bn = blockIdx.x * 128;
    const __nv_bfloat16* Ah = g_Gh + (size_t)bm * Dm;
    const __nv_bfloat16* Al = g_Gl + (size_t)bm * Dm;
    const __nv_bfloat16* Bh = g_WoTh + (size_t)bn * Dm;
    const __nv_bfloat16* Bl = g_WoTl + (size_t)bn * Dm;
    float acc[4][4][4];
    gemm_mma(Ah, Al, Dm, Bh, Bl, Dm, Dm, sb, acc);

    const int t = threadIdx.x, lane = t & 31, w = t >> 5, wm = w & 1, wn = w >> 1;
#pragma unroll
    for (int mi = 0; mi < 4; mi++)
#pragma unroll
        for (int ni = 0; ni < 4; ni++) {
            int m = bm + wm * 64 + mi * 16 + (lane >> 2);
            int c = bn + wn * 32 + ni * 8 + ((lane & 3) << 1);
            float b0 = bo[c], b1 = bo[c + 1];
            *(float2*)&Outp[(size_t)m * Dm + c] =
                make_float2(acc[mi][ni][0] + b0, acc[mi][ni][1] + b1);
            *(float2*)&Outp[(size_t)(m + 8) * Dm + c] =
                make_float2(acc[mi][ni][2] + b0, acc[mi][ni][3] + b1);
        }
}

// ======================= launch =============================================
extern "C" void kernel_launch(void* const* d_in, const int* in_sizes, int n_in,
                              void* d_out, int out_size)
{
    const float* x    = (const float*)d_in[0];
    const float* cosr = (const float*)d_in[1];
    const float* sinr = (const float*)d_in[2];
    // d_in[3] = target_mask (causal tril; handled analytically)
    const float* Wq   = (const float*)d_in[4];
    const float* Wk   = (const float*)d_in[5];
    const float* Wv   = (const float*)d_in[6];
    const float* bv   = (const float*)d_in[7];
    const float* Wo   = (const float*)d_in[8];
    const float* bo   = (const float*)d_in[9];
    float* out = (float*)d_out;

    cudaFuncSetAttribute(mm_proj_kernel,  cudaFuncAttributeMaxDynamicSharedMemorySize, GEMM_SMEM);
    cudaFuncSetAttribute(mm_score_kernel, cudaFuncAttributeMaxDynamicSharedMemorySize, GEMM_SMEM);
    cudaFuncSetAttribute(mm_pv_kernel,    cudaFuncAttributeMaxDynamicSharedMemorySize, GEMM_SMEM);
    cudaFuncSetAttribute(mm_out_kernel,   cudaFuncAttributeMaxDynamicSharedMemorySize, GEMM_SMEM);

    __nv_bfloat16 *wth, *wtl, *woth, *wotl;
    cudaGetSymbolAddress((void**)&wth,  g_WTh);
    cudaGetSymbolAddress((void**)&wtl,  g_WTl);
    cudaGetSymbolAddress((void**)&woth, g_WoTh);
    cudaGetSymbolAddress((void**)&wotl, g_WoTl);

    xc_kernel<<<2048, 256>>>(x);
    wt_kernel<<<dim3(128, 16), dim3(32, 8)>>>(Wq, wth + 0 * (size_t)Ff * Dm,
                                              wtl + 0 * (size_t)Ff * Dm, Dm, Ff);
    wt_kernel<<<dim3(128, 16), dim3(32, 8)>>>(Wk, wth + 1 * (size_t)Ff * Dm,
                                              wtl + 1 * (size_t)Ff * Dm, Dm, Ff);
    wt_kernel<<<dim3(128, 16), dim3(32, 8)>>>(Wv, wth + 2 * (size_t)Ff * Dm,
                                              wtl + 2 * (size_t)Ff * Dm, Dm, Ff);
    wt_kernel<<<dim3(16, 16), dim3(32, 8)>>>(Wo, woth, wotl, Dm, Dm);

    mm_proj_kernel<<<dim3(32, 32, 3), 256, GEMM_SMEM>>>(cosr, sinr, bv);
    vt_kernel<<<dim3(64, 16, BH), dim3(32, 8)>>>();
    mm_score_kernel<<<dim3(16, 16, BH), 256, GEMM_SMEM>>>();
    softmax_kernel<<<BH * Nseq, 256>>>();
    mm_pv_kernel<<<dim3(4, 16, BH), 256, GEMM_SMEM>>>();
    reduce_kernel<<<2048, 256>>>();
    mm_out_kernel<<<dim3(4, 32), 256, GEMM_SMEM>>>(bo, out);
}

// round 8
// speedup vs baseline: 1.7421x; 1.0753x over previous
#include <cuda_runtime.h>
#include <cuda_bf16.h>
#include <cuda_fp16.h>
#include <cstdint>
#include <math.h>

#define Bsz  2
#define Nseq 2048
#define Dm   512
#define Hh   8
#define DHd  512
#define Ff   4096
#define Mrows 4096   // Bsz*Nseq
#define BH   16      // Bsz*Hh

// ======================= scratch (device globals) ===========================
__device__ __align__(16) __nv_bfloat16 g_Xh[(size_t)Mrows * Dm];
__device__ __align__(16) __nv_bfloat16 g_Xl[(size_t)Mrows * Dm];
__device__ __align__(16) __nv_bfloat16 g_WTh[3 * (size_t)Ff * Dm];   // [mode][n][k]
__device__ __align__(16) __nv_bfloat16 g_WTl[3 * (size_t)Ff * Dm];
__device__ __align__(16) __nv_bfloat16 g_WoTh[(size_t)Dm * Dm];
__device__ __align__(16) __nv_bfloat16 g_WoTl[(size_t)Dm * Dm];
__device__ __align__(16) __nv_bfloat16 g_Qh[(size_t)Mrows * Ff];
__device__ __align__(16) __nv_bfloat16 g_Ql[(size_t)Mrows * Ff];
__device__ __align__(16) __nv_bfloat16 g_Kh[(size_t)Mrows * Ff];
__device__ __align__(16) __nv_bfloat16 g_Kl[(size_t)Mrows * Ff];
__device__ __align__(16) float         g_V [(size_t)Mrows * Ff];
__device__ __align__(16) __half        g_VT[(size_t)BH * DHd * Nseq]; // [bh][f][tok], fp16
__device__ __align__(16) float         g_S [(size_t)BH * Nseq * Nseq];
__device__ __align__(16) __half        g_Ph[(size_t)BH * Nseq * Nseq];
__device__ __align__(16) __half        g_Pl[(size_t)BH * Nseq * Nseq];
__device__ __align__(16) float         g_YH[(size_t)BH * Nseq * Dm];
__device__ __align__(16) __nv_bfloat16 g_Gh[(size_t)Mrows * Dm];
__device__ __align__(16) __nv_bfloat16 g_Gl[(size_t)Mrows * Dm];

// ======================= helpers ===========================================
__device__ __forceinline__ uint32_t smem_to_u32(const void* p) {
    uint32_t a;
    asm("{ .reg .u64 t; cvta.to.shared.u64 t, %1; cvt.u32.u64 %0, t; }" : "=r"(a) : "l"(p));
    return a;
}
// SW64 swizzle for 64-byte rows (8 rows x 64B atom)
#define SWZ64(b) ((b) ^ (((b) >> 3) & 0x30))

#define LDSM_X4(r, addr) \
    asm volatile("ldmatrix.sync.aligned.m8n8.x4.shared.b16 {%0,%1,%2,%3}, [%4];" \
        : "=r"((r)[0]), "=r"((r)[1]), "=r"((r)[2]), "=r"((r)[3]) : "r"(addr))

#define MMA_BF16(d, a, b0, b1) \
    asm volatile("mma.sync.aligned.m16n8k16.row.col.f32.bf16.bf16.f32 " \
        "{%0,%1,%2,%3}, {%4,%5,%6,%7}, {%8,%9}, {%0,%1,%2,%3};" \
        : "+f"((d)[0]), "+f"((d)[1]), "+f"((d)[2]), "+f"((d)[3]) \
        : "r"((a)[0]), "r"((a)[1]), "r"((a)[2]), "r"((a)[3]), "r"(b0), "r"(b1))

#define MMA_F16(d, a, b0, b1) \
    asm volatile("mma.sync.aligned.m16n8k16.row.col.f32.f16.f16.f32 " \
        "{%0,%1,%2,%3}, {%4,%5,%6,%7}, {%8,%9}, {%0,%1,%2,%3};" \
        : "+f"((d)[0]), "+f"((d)[1]), "+f"((d)[2]), "+f"((d)[3]) \
        : "r"((a)[0]), "r"((a)[1]), "r"((a)[2]), "r"((a)[3]), "r"(b0), "r"(b1))

#define CP_ASYNC16(dst, src) \
    asm volatile("cp.async.cg.shared.global [%0], [%1], 16;" :: "r"(dst), "l"(src))
#define CP_COMMIT() asm volatile("cp.async.commit_group;")
#define CP_WAIT2()  asm volatile("cp.async.wait_group 2;")
#define CP_WAIT1()  asm volatile("cp.async.wait_group 1;")
#define CP_WAIT0()  asm volatile("cp.async.wait_group 0;")

// ======================= split helpers ======================================
__device__ __forceinline__ unsigned bf2(float a, float b) {
    return (unsigned)__bfloat16_as_ushort(__float2bfloat16(a)) |
           ((unsigned)__bfloat16_as_ushort(__float2bfloat16(b)) << 16);
}
__device__ __forceinline__ void split_pair(float a, float b, unsigned& h, unsigned& l) {
    __nv_bfloat16 ah = __float2bfloat16(a), bh = __float2bfloat16(b);
    h = (unsigned)__bfloat16_as_ushort(ah) | ((unsigned)__bfloat16_as_ushort(bh) << 16);
    l = bf2(a - __bfloat162float(ah), b - __bfloat162float(bh));
}
__device__ __forceinline__ void split1(float a, __nv_bfloat16& h, __nv_bfloat16& l) {
    h = __float2bfloat16(a);
    l = __float2bfloat16(a - __bfloat162float(h));
}
__device__ __forceinline__ void split1h(float a, __half& h, __half& l) {
    h = __float2half_rn(a);
    l = __float2half_rn(a - __half2float(h));
}

// ======================= mma.sync GEMM core (K-chunk 32, 3-stage) ===========
// C[128x128] = Ah*Bh + Ah*Bl + Al*Bh over K. Stage 32KB: aH|aL|bH|bL (8KB,
// 64B rows, SW64). 3 stages = 96KB -> 2 CTAs/SM. Warps 2(M) x 4(N), 64x32.
#define STG32 32768
#define GEMM_SMEM (3 * STG32)

__device__ __forceinline__ void mma_chunk32(uint32_t sst, int lane, int wm, int wn,
                                            float (&acc)[4][4][4]) {
    const uint32_t aH = sst, aL = sst + 8192, bB = sst + 16384, bL = sst + 24576;
#pragma unroll
    for (int kk = 0; kk < 2; kk++) {
        uint32_t bh[2][4], bl[2][4];
        const int brow = wn * 32 + (lane & 7) + ((lane >> 4) << 3);
        const int bcb = kk * 32 + (((lane >> 3) & 1) << 4);
#pragma unroll
        for (int nb = 0; nb < 2; nb++) {
            uint32_t off = SWZ64(((brow + nb * 16) << 6) + bcb);
            LDSM_X4(bh[nb], bB + off);
            LDSM_X4(bl[nb], bL + off);
        }
        const int acb = kk * 32 + ((lane >> 4) << 4);
#pragma unroll
        for (int mi = 0; mi < 4; mi++) {
            uint32_t ah[4], al[4];
            uint32_t off = SWZ64(((wm * 64 + mi * 16 + (lane & 15)) << 6) + acb);
            LDSM_X4(ah, aH + off);
            LDSM_X4(al, aL + off);
#pragma unroll
            for (int ni = 0; ni < 4; ni++) {
                const int nb = ni >> 1, p = (ni & 1) << 1;
                MMA_BF16(acc[mi][ni], ah, bh[nb][p], bh[nb][p + 1]);
                MMA_BF16(acc[mi][ni], ah, bl[nb][p], bl[nb][p + 1]);
                MMA_BF16(acc[mi][ni], al, bh[nb][p], bh[nb][p + 1]);
            }
        }
    }
}

__device__ __forceinline__ void issue_chunk32(
    uint32_t sbase, int c, int t,
    const __nv_bfloat16* Ah, const __nv_bfloat16* Al, size_t sA,
    const __nv_bfloat16* Bh, const __nv_bfloat16* Bl, size_t sB)
{
    const uint32_t sst = sbase + (uint32_t)(c % 3) * STG32;
    const __nv_bfloat16* ah = Ah + (c << 5);
    const __nv_bfloat16* al = Al + (c << 5);
    const __nv_bfloat16* bhp = Bh + (c << 5);
    const __nv_bfloat16* blp = Bl + (c << 5);
#pragma unroll
    for (int i = 0; i < 2; i++) {
        int u = t + (i << 8), r = u >> 2, cu = u & 3;
        uint32_t d = sst + SWZ64((r << 6) + (cu << 4));
        const size_t so = (size_t)r * sA + (cu << 3);
        CP_ASYNC16(d, ah + so);
        CP_ASYNC16(d + 8192, al + so);
    }
#pragma unroll
    for (int i = 0; i < 2; i++) {
        int u = t + (i << 8), r = u >> 2, cu = u & 3;
        uint32_t d = sst + 16384 + SWZ64((r << 6) + (cu << 4));
        const size_t so = (size_t)r * sB + (cu << 3);
        CP_ASYNC16(d, bhp + so);
        CP_ASYNC16(d + 8192, blp + so);
    }
    CP_COMMIT();
}

__device__ __forceinline__ void gemm_mma(
    const __nv_bfloat16* Ah, const __nv_bfloat16* Al, size_t sA,
    const __nv_bfloat16* Bh, const __nv_bfloat16* Bl, size_t sB,
    int K, uint32_t sbase, float (&acc)[4][4][4])
{
    const int t = threadIdx.x;
    const int lane = t & 31, w = t >> 5, wm = w & 1, wn = w >> 1;
#pragma unroll
    for (int mi = 0; mi < 4; mi++)
#pragma unroll
        for (int ni = 0; ni < 4; ni++)
#pragma unroll
            for (int r = 0; r < 4; r++) acc[mi][ni][r] = 0.f;

    const int NC = K >> 5;
    issue_chunk32(sbase, 0, t, Ah, Al, sA, Bh, Bl, sB);
    if (NC > 1) issue_chunk32(sbase, 1, t, Ah, Al, sA, Bh, Bl, sB);
    for (int c = 0; c < NC; c++) {
        if (c + 2 < NC) {
            issue_chunk32(sbase, c + 2, t, Ah, Al, sA, Bh, Bl, sB);
            CP_WAIT2();
        } else if (c + 1 < NC) {
            CP_WAIT1();
        } else {
            CP_WAIT0();
        }
        __syncthreads();
        mma_chunk32(sbase + (uint32_t)(c % 3) * STG32, lane, wm, wn, acc);
        __syncthreads();
    }
}

// ======================= PV fp16 2-pass core (stage 24KB: Ph|Pl|V) ==========
#define STG24 24576
#define PV_SMEM (3 * STG24)

__device__ __forceinline__ void mma_chunk32_pv(uint32_t sst, int lane, int wm, int wn,
                                               float (&acc)[4][4][4]) {
    const uint32_t aH = sst, aL = sst + 8192, bB = sst + 16384;
#pragma unroll
    for (int kk = 0; kk < 2; kk++) {
        uint32_t bh[2][4];
        const int brow = wn * 32 + (lane & 7) + ((lane >> 4) << 3);
        const int bcb = kk * 32 + (((lane >> 3) & 1) << 4);
#pragma unroll
        for (int nb = 0; nb < 2; nb++) {
            uint32_t off = SWZ64(((brow + nb * 16) << 6) + bcb);
            LDSM_X4(bh[nb], bB + off);
        }
        const int acb = kk * 32 + ((lane >> 4) << 4);
#pragma unroll
        for (int mi = 0; mi < 4; mi++) {
            uint32_t ah[4], al[4];
            uint32_t off = SWZ64(((wm * 64 + mi * 16 + (lane & 15)) << 6) + acb);
            LDSM_X4(ah, aH + off);
            LDSM_X4(al, aL + off);
#pragma unroll
            for (int ni = 0; ni < 4; ni++) {
                const int nb = ni >> 1, p = (ni & 1) << 1;
                MMA_F16(acc[mi][ni], ah, bh[nb][p], bh[nb][p + 1]);
                MMA_F16(acc[mi][ni], al, bh[nb][p], bh[nb][p + 1]);
            }
        }
    }
}

__device__ __forceinline__ void issue_chunk32_pv(
    uint32_t sbase, int c, int t,
    const __half* Ph, const __half* Pl, size_t sA,
    const __half* Vv, size_t sB)
{
    const uint32_t sst = sbase + (uint32_t)(c % 3) * STG24;
    const __half* ph = Ph + (c << 5);
    const __half* pl = Pl + (c << 5);
    const __half* vp = Vv + (c << 5);
#pragma unroll
    for (int i = 0; i < 2; i++) {
        int u = t + (i << 8), r = u >> 2, cu = u & 3;
        uint32_t d = sst + SWZ64((r << 6) + (cu << 4));
        const size_t so = (size_t)r * sA + (cu << 3);
        CP_ASYNC16(d, ph + so);
        CP_ASYNC16(d + 8192, pl + so);
    }
#pragma unroll
    for (int i = 0; i < 2; i++) {
        int u = t + (i << 8), r = u >> 2, cu = u & 3;
        uint32_t d = sst + 16384 + SWZ64((r << 6) + (cu << 4));
        CP_ASYNC16(d, vp + (size_t)r * sB + (cu << 3));
    }
    CP_COMMIT();
}

__device__ __forceinline__ void gemm_mma_pv(
    const __half* Ph, const __half* Pl, size_t sA,
    const __half* Vv, size_t sB,
    int K, uint32_t sbase, float (&acc)[4][4][4])
{
    const int t = threadIdx.x;
    const int lane = t & 31, w = t >> 5, wm = w & 1, wn = w >> 1;
#pragma unroll
    for (int mi = 0; mi < 4; mi++)
#pragma unroll
        for (int ni = 0; ni < 4; ni++)
#pragma unroll
            for (int r = 0; r < 4; r++) acc[mi][ni][r] = 0.f;

    const int NC = K >> 5;
    issue_chunk32_pv(sbase, 0, t, Ph, Pl, sA, Vv, sB);
    if (NC > 1) issue_chunk32_pv(sbase, 1, t, Ph, Pl, sA, Vv, sB);
    for (int c = 0; c < NC; c++) {
        if (c + 2 < NC) {
            issue_chunk32_pv(sbase, c + 2, t, Ph, Pl, sA, Vv, sB);
            CP_WAIT2();
        } else if (c + 1 < NC) {
            CP_WAIT1();
        } else {
            CP_WAIT0();
        }
        __syncthreads();
        mma_chunk32_pv(sbase + (uint32_t)(c % 3) * STG24, lane, wm, wn, acc);
        __syncthreads();
    }
}

// ======================= prep kernels =======================================
__global__ __launch_bounds__(256) void xc_kernel(const float* __restrict__ x) {
    int i = blockIdx.x * 256 + threadIdx.x;
    float4 v = ((const float4*)x)[i];
    unsigned h0, l0, h1, l1;
    split_pair(v.x, v.y, h0, l0);
    split_pair(v.z, v.w, h1, l1);
    ((uint2*)g_Xh)[i] = make_uint2(h0, h1);
    ((uint2*)g_Xl)[i] = make_uint2(l0, l1);
}

__global__ void wt_kernel(const float* __restrict__ src, __nv_bfloat16* dh,
                          __nv_bfloat16* dl, int K, int NC) {
    __shared__ float tile[32][33];
    int n0 = blockIdx.x * 32, k0 = blockIdx.y * 32;
    int tx = threadIdx.x, ty = threadIdx.y;        // ty 0..7
#pragma unroll
    for (int r = 0; r < 4; r++)
        tile[ty + 8 * r][tx] = src[(size_t)(k0 + ty + 8 * r) * NC + n0 + tx];
    __syncthreads();
#pragma unroll
    for (int r = 0; r < 4; r++) {
        float v = tile[tx][ty + 8 * r];
        __nv_bfloat16 h, l;
        split1(v, h, l);
        size_t di = (size_t)(n0 + ty + 8 * r) * K + k0 + tx;
        dh[di] = h; dl[di] = l;
    }
}

// V [b][tok][F] (head slice) -> VT[bh][f][tok] fp16 single
__global__ void vt_kernel() {
    __shared__ float tile[32][33];
    int tok0 = blockIdx.x * 32, f0 = blockIdx.y * 32;
    int bh = blockIdx.z, b = bh >> 3, h = bh & 7;
    int tx = threadIdx.x, ty = threadIdx.y;        // ty 0..7
#pragma unroll
    for (int r = 0; r < 4; r++)
        tile[ty + 8 * r][tx] = g_V[(size_t)(b * Nseq + tok0 + ty + 8 * r) * Ff + h * DHd + f0 + tx];
    __syncthreads();
#pragma unroll
    for (int r = 0; r < 4; r++) {
        float v = tile[tx][ty + 8 * r];
        size_t di = (size_t)bh * DHd * Nseq + (size_t)(f0 + ty + 8 * r) * Nseq + tok0 + tx;
        g_VT[di] = __float2half_rn(v);
    }
}

// ======================= 1) QKV projection GEMM + RoPE/bias epilogue ========
__global__ __launch_bounds__(256, 2) void mm_proj_kernel(
    const float* __restrict__ cosr, const float* __restrict__ sinr,
    const float* __restrict__ bv)
{
    extern __shared__ __align__(128) char smem[];
    uint32_t sb = smem_to_u32(smem);
    const int mode = blockIdx.z;
    const int bm = blockIdx.y * 128, bn = blockIdx.x * 128;
    const __nv_bfloat16* Ah = g_Xh + (size_t)bm * Dm;
    const __nv_bfloat16* Al = g_Xl + (size_t)bm * Dm;
    const __nv_bfloat16* Bh = g_WTh + ((size_t)mode * Ff + bn) * Dm;
    const __nv_bfloat16* Bl = g_WTl + ((size_t)mode * Ff + bn) * Dm;
    float acc[4][4][4];
    gemm_mma(Ah, Al, Dm, Bh, Bl, Dm, Dm, sb, acc);

    const int t = threadIdx.x, lane = t & 31, w = t >> 5, wm = w & 1, wn = w >> 1;
    if (mode == 2) {
#pragma unroll
        for (int mi = 0; mi < 4; mi++)
#pragma unroll
            for (int ni = 0; ni < 4; ni++) {
                int m = bm + wm * 64 + mi * 16 + (lane >> 2);
                int c = bn + wn * 32 + ni * 8 + ((lane & 3) << 1);
                float b0 = bv[c], b1 = bv[c + 1];
                *(float2*)&g_V[(size_t)m * Ff + c] =
                    make_float2(acc[mi][ni][0] + b0, acc[mi][ni][1] + b1);
                *(float2*)&g_V[(size_t)(m + 8) * Ff + c] =
                    make_float2(acc[mi][ni][2] + b0, acc[mi][ni][3] + b1);
            }
    } else {
        __nv_bfloat16* OH = (mode == 0) ? g_Qh : g_Kh;
        __nv_bfloat16* OL = (mode == 0) ? g_Ql : g_Kl;
#pragma unroll
        for (int mi = 0; mi < 4; mi++)
#pragma unroll
            for (int ni = 0; ni < 4; ni++) {
                int m0 = bm + wm * 64 + mi * 16 + (lane >> 2);
                int c = bn + wn * 32 + ni * 8 + ((lane & 3) << 1);
#pragma unroll
                for (int half = 0; half < 2; half++) {
                    int m = m0 + half * 8;
                    int n = m & (Nseq - 1);
                    float cr0 = cosr[(size_t)n * Ff + c];
                    float sr0 = sinr[(size_t)n * Ff + c];
                    float cr1 = cosr[(size_t)n * Ff + c + 1];
                    float sr1 = sinr[(size_t)n * Ff + c + 1];
                    float e = acc[mi][ni][half * 2];
                    float o = acc[mi][ni][half * 2 + 1];
                    float oe = e * cr0 - o * sr0;
                    float oo = o * cr1 + e * sr1;
                    unsigned hw, lw;
                    split_pair(oe, oo, hw, lw);
                    *(unsigned*)&OH[(size_t)m * Ff + c] = hw;
                    *(unsigned*)&OL[(size_t)m * Ff + c] = lw;
                }
            }
    }
}

// ======================= 2) S = Q K^T ======================================
__global__ __launch_bounds__(256, 2) void mm_score_kernel() {
    if (blockIdx.x > blockIdx.y) return;
    extern __shared__ __align__(128) char smem[];
    uint32_t sb = smem_to_u32(smem);
    const int bh = blockIdx.z, b = bh >> 3, h = bh & 7;
    const int i0 = blockIdx.y * 128, j0 = blockIdx.x * 128;
    const __nv_bfloat16* Ah = g_Qh + (size_t)(b * Nseq + i0) * Ff + h * DHd;
    const __nv_bfloat16* Al = g_Ql + (size_t)(b * Nseq + i0) * Ff + h * DHd;
    const __nv_bfloat16* Bh = g_Kh + (size_t)(b * Nseq + j0) * Ff + h * DHd;
    const __nv_bfloat16* Bl = g_Kl + (size_t)(b * Nseq + j0) * Ff + h * DHd;
    float acc[4][4][4];
    gemm_mma(Ah, Al, Ff, Bh, Bl, Ff, DHd, sb, acc);

    const int t = threadIdx.x, lane = t & 31, w = t >> 5, wm = w & 1, wn = w >> 1;
    float* Sp = g_S + (size_t)bh * Nseq * Nseq;
#pragma unroll
    for (int mi = 0; mi < 4; mi++)
#pragma unroll
        for (int ni = 0; ni < 4; ni++) {
            int m = i0 + wm * 64 + mi * 16 + (lane >> 2);
            int nn = j0 + wn * 32 + ni * 8 + ((lane & 3) << 1);
            *(float2*)&Sp[(size_t)m * Nseq + nn] = make_float2(acc[mi][ni][0], acc[mi][ni][1]);
            *(float2*)&Sp[(size_t)(m + 8) * Nseq + nn] = make_float2(acc[mi][ni][2], acc[mi][ni][3]);
        }
}

// ======================= 3) causal row softmax -> P fp16 hi/lo ==============
__global__ __launch_bounds__(256) void softmax_kernel() {
    const int rgl = blockIdx.x;
    const int bh = rgl >> 11, i = rgl & (Nseq - 1);
    const size_t base = (size_t)bh * Nseq * Nseq + (size_t)i * Nseq;
    const float* row = g_S + base;
    const int L = i + 1;
    const int Lz = ((i >> 7) + 1) << 7;
    const int t = threadIdx.x;

    float v[8];
    int cnt = 0;
    float mx = -1e30f;
    for (int j = t; j < L; j += 256) { float x = row[j]; v[cnt++] = x; mx = fmaxf(mx, x); }

    __shared__ float red[256];
    red[t] = mx; __syncthreads();
    for (int s = 128; s > 0; s >>= 1) { if (t < s) red[t] = fmaxf(red[t], red[t + s]); __syncthreads(); }
    mx = red[0]; __syncthreads();

    float sum = 0.f;
    for (int k = 0; k < cnt; k++) { v[k] = expf(v[k] - mx); sum += v[k]; }
    red[t] = sum; __syncthreads();
    for (int s = 128; s > 0; s >>= 1) { if (t < s) red[t] += red[t + s]; __syncthreads(); }
    const float inv = 1.0f / red[0];

    cnt = 0;
    for (int j = t; j < L; j += 256) {
        float p = v[cnt++] * inv;
        __half h, l;
        split1h(p, h, l);
        g_Ph[base + j] = h; g_Pl[base + j] = l;
    }
    const __half z = __float2half_rn(0.f);
    for (int j = t; j < Lz; j += 256)
        if (j >= L) { g_Ph[base + j] = z; g_Pl[base + j] = z; }
}

// ======================= 4) Yh = P @ V (fp16 2-pass) ========================
__global__ __launch_bounds__(256, 2) void mm_pv_kernel() {
    extern __shared__ __align__(128) char smem[];
    uint32_t sb = smem_to_u32(smem);
    const int bh = blockIdx.z;
    const int i0 = blockIdx.y * 128, n0 = blockIdx.x * 128;
    const __half* Ph = g_Ph + (size_t)bh * Nseq * Nseq + (size_t)i0 * Nseq;
    const __half* Pl = g_Pl + (size_t)bh * Nseq * Nseq + (size_t)i0 * Nseq;
    const __half* Vv = g_VT + (size_t)bh * DHd * Nseq + (size_t)n0 * Nseq;
    float acc[4][4][4];
    gemm_mma_pv(Ph, Pl, Nseq, Vv, Nseq, i0 + 128, sb, acc);

    const int t = threadIdx.x, lane = t & 31, w = t >> 5, wm = w & 1, wn = w >> 1;
    float* Yp = g_YH + (size_t)bh * Nseq * Dm;
#pragma unroll
    for (int mi = 0; mi < 4; mi++)
#pragma unroll
        for (int ni = 0; ni < 4; ni++) {
            int m = i0 + wm * 64 + mi * 16 + (lane >> 2);
            int nn = n0 + wn * 32 + ni * 8 + ((lane & 3) << 1);
            *(float2*)&Yp[(size_t)m * Dm + nn] = make_float2(acc[mi][ni][0], acc[mi][ni][1]);
            *(float2*)&Yp[(size_t)(m + 8) * Dm + nn] = make_float2(acc[mi][ni][2], acc[mi][ni][3]);
        }
}

// ======================= 5) head-sum + QuickGELU + split ====================
__global__ __launch_bounds__(256) void reduce_kernel() {
    int idx = blockIdx.x * 256 + threadIdx.x;
    int m = idx >> 7;
    int c4 = (idx & 127) * 4;
    int b = m >> 11, n = m & (Nseq - 1);
    float4 s = make_float4(0.f, 0.f, 0.f, 0.f);
#pragma unroll
    for (int h = 0; h < Hh; h++) {
        const float4 v = *(const float4*)(g_YH + (size_t)((b * Hh + h) * Nseq + n) * Dm + c4);
        s.x += v.x; s.y += v.y; s.z += v.z; s.w += v.w;
    }
    s.x = s.x / (1.f + expf(-1.702f * s.x));
    s.y = s.y / (1.f + expf(-1.702f * s.y));
    s.z = s.z / (1.f + expf(-1.702f * s.z));
    s.w = s.w / (1.f + expf(-1.702f * s.w));
    unsigned h0, l0, h1, l1;
    split_pair(s.x, s.y, h0, l0);
    split_pair(s.z, s.w, h1, l1);
    *(uint2*)(g_Gh + (size_t)m * Dm + c4) = make_uint2(h0, h1);
    *(uint2*)(g_Gl + (size_t)m * Dm + c4) = make_uint2(l0, l1);
}

// ======================= 6) output projection ===============================
__global__ __launch_bounds__(256, 2) void mm_out_kernel(const float* __restrict__ bo,
                                                        float* __restrict__ Outp) {
    extern __shared__ __align__(128) char smem[];
    uint32_t sb = smem_to_u32(smem);
    const int bm = blockIdx.y * 128, bn = blockIdx.x * 128;
    const __nv_bfloat16* Ah = g_Gh + (size_t)bm * Dm;
    const __nv_bfloat16* Al = g_Gl + (size_t)bm * Dm;
    const __nv_bfloat16* Bh = g_WoTh + (size_t)bn * Dm;
    const __nv_bfloat16* Bl = g_WoTl + (size_t)bn * Dm;
    float acc[4][4][4];
    gemm_mma(Ah, Al, Dm, Bh, Bl, Dm, Dm, sb, acc);

    const int t = threadIdx.x, lane = t & 31, w = t >> 5, wm = w & 1, wn = w >> 1;
#pragma unroll
    for (int mi = 0; mi < 4; mi++)
#pragma unroll
        for (int ni = 0; ni < 4; ni++) {
            int m = bm + wm * 64 + mi * 16 + (lane >> 2);
            int c = bn + wn * 32 + ni * 8 + ((lane & 3) << 1);
            float b0 = bo[c], b1 = bo[c + 1];
            *(float2*)&Outp[(size_t)m * Dm + c] =
                make_float2(acc[mi][ni][0] + b0, acc[mi][ni][1] + b1);
            *(float2*)&Outp[(size_t)(m + 8) * Dm + c] =
                make_float2(acc[mi][ni][2] + b0, acc[mi][ni][3] + b1);
        }
}

// ======================= launch =============================================
extern "C" void kernel_launch(void* const* d_in, const int* in_sizes, int n_in,
                              void* d_out, int out_size)
{
    const float* x    = (const float*)d_in[0];
    const float* cosr = (const float*)d_in[1];
    const float* sinr = (const float*)d_in[2];
    // d_in[3] = target_mask (causal tril; handled analytically)
    const float* Wq   = (const float*)d_in[4];
    const float* Wk   = (const float*)d_in[5];
    const float* Wv   = (const float*)d_in[6];
    const float* bv   = (const float*)d_in[7];
    const float* Wo   = (const float*)d_in[8];
    const float* bo   = (const float*)d_in[9];
    float* out = (float*)d_out;

    cudaFuncSetAttribute(mm_proj_kernel,  cudaFuncAttributeMaxDynamicSharedMemorySize, GEMM_SMEM);
    cudaFuncSetAttribute(mm_score_kernel, cudaFuncAttributeMaxDynamicSharedMemorySize, GEMM_SMEM);
    cudaFuncSetAttribute(mm_pv_kernel,    cudaFuncAttributeMaxDynamicSharedMemorySize, PV_SMEM);
    cudaFuncSetAttribute(mm_out_kernel,   cudaFuncAttributeMaxDynamicSharedMemorySize, GEMM_SMEM);

    __nv_bfloat16 *wth, *wtl, *woth, *wotl;
    cudaGetSymbolAddress((void**)&wth,  g_WTh);
    cudaGetSymbolAddress((void**)&wtl,  g_WTl);
    cudaGetSymbolAddress((void**)&woth, g_WoTh);
    cudaGetSymbolAddress((void**)&wotl, g_WoTl);

    // Launch order matters for ncu (-s 5 lands on launch #5 = mm_proj).
    xc_kernel<<<2048, 256>>>(x);
    wt_kernel<<<dim3(128, 16), dim3(32, 8)>>>(Wq, wth + 0 * (size_t)Ff * Dm,
                                              wtl + 0 * (size_t)Ff * Dm, Dm, Ff);
    wt_kernel<<<dim3(128, 16), dim3(32, 8)>>>(Wk, wth + 1 * (size_t)Ff * Dm,
                                              wtl + 1 * (size_t)Ff * Dm, Dm, Ff);
    wt_kernel<<<dim3(128, 16), dim3(32, 8)>>>(Wv, wth + 2 * (size_t)Ff * Dm,
                                              wtl + 2 * (size_t)Ff * Dm, Dm, Ff);
    mm_proj_kernel<<<dim3(32, 32, 3), 256, GEMM_SMEM>>>(cosr, sinr, bv);
    mm_score_kernel<<<dim3(16, 16, BH), 256, GEMM_SMEM>>>();
    vt_kernel<<<dim3(64, 16, BH), dim3(32, 8)>>>();
    softmax_kernel<<<BH * Nseq, 256>>>();
    mm_pv_kernel<<<dim3(4, 16, BH), 256, PV_SMEM>>>();
    reduce_kernel<<<2048, 256>>>();
    wt_kernel<<<dim3(16, 16), dim3(32, 8)>>>(Wo, woth, wotl, Dm, Dm);
    mm_out_kernel<<<dim3(4, 32), 256, GEMM_SMEM>>>(bo, out);
}

// round 12
// speedup vs baseline: 1.7597x; 1.0101x over previous
#include <cuda_runtime.h>
#include <cuda_bf16.h>
#include <cuda_fp16.h>
#include <cstdint>
#include <math.h>

#define Bsz  2
#define Nseq 2048
#define Dm   512
#define Hh   8
#define DHd  512
#define Ff   4096
#define Mrows 4096   // Bsz*Nseq
#define BH   16      // Bsz*Hh

// ======================= scratch (device globals) ===========================
__device__ __align__(16) __nv_bfloat16 g_Xh[(size_t)Mrows * Dm];
__device__ __align__(16) __nv_bfloat16 g_Xl[(size_t)Mrows * Dm];
__device__ __align__(16) __nv_bfloat16 g_WTh[3 * (size_t)Ff * Dm];   // [mode][n][k]
__device__ __align__(16) __nv_bfloat16 g_WTl[3 * (size_t)Ff * Dm];
__device__ __align__(16) __nv_bfloat16 g_WoTh[(size_t)Dm * Dm];
__device__ __align__(16) __nv_bfloat16 g_WoTl[(size_t)Dm * Dm];
__device__ __align__(16) __nv_bfloat16 g_Qh[(size_t)Mrows * Ff];
__device__ __align__(16) __nv_bfloat16 g_Ql[(size_t)Mrows * Ff];
__device__ __align__(16) __nv_bfloat16 g_Kh[(size_t)Mrows * Ff];
__device__ __align__(16) __nv_bfloat16 g_Kl[(size_t)Mrows * Ff];
__device__ __align__(16) float         g_V [(size_t)Mrows * Ff];
__device__ __align__(16) __half        g_VT[(size_t)BH * DHd * Nseq]; // [bh][f][tok], fp16
__device__ __align__(16) float         g_S [(size_t)BH * Nseq * Nseq];
__device__ __align__(16) __half        g_Ph[(size_t)BH * Nseq * Nseq];
__device__ __align__(16) __half        g_Pl[(size_t)BH * Nseq * Nseq];
__device__ __align__(16) float         g_YH[(size_t)BH * Nseq * Dm];
__device__ __align__(16) __nv_bfloat16 g_Gh[(size_t)Mrows * Dm];
__device__ __align__(16) __nv_bfloat16 g_Gl[(size_t)Mrows * Dm];

// ======================= helpers ===========================================
__device__ __forceinline__ uint32_t smem_to_u32(const void* p) {
    uint32_t a;
    asm("{ .reg .u64 t; cvta.to.shared.u64 t, %1; cvt.u32.u64 %0, t; }" : "=r"(a) : "l"(p));
    return a;
}
// SW64 swizzle for 64-byte rows (8 rows x 64B atom)
#define SWZ64(b) ((b) ^ (((b) >> 3) & 0x30))

#define LDSM_X4(r, addr) \
    asm volatile("ldmatrix.sync.aligned.m8n8.x4.shared.b16 {%0,%1,%2,%3}, [%4];" \
        : "=r"((r)[0]), "=r"((r)[1]), "=r"((r)[2]), "=r"((r)[3]) : "r"(addr))

#define MMA_BF16(d, a, b0, b1) \
    asm volatile("mma.sync.aligned.m16n8k16.row.col.f32.bf16.bf16.f32 " \
        "{%0,%1,%2,%3}, {%4,%5,%6,%7}, {%8,%9}, {%0,%1,%2,%3};" \
        : "+f"((d)[0]), "+f"((d)[1]), "+f"((d)[2]), "+f"((d)[3]) \
        : "r"((a)[0]), "r"((a)[1]), "r"((a)[2]), "r"((a)[3]), "r"(b0), "r"(b1))

#define MMA_F16(d, a, b0, b1) \
    asm volatile("mma.sync.aligned.m16n8k16.row.col.f32.f16.f16.f32 " \
        "{%0,%1,%2,%3}, {%4,%5,%6,%7}, {%8,%9}, {%0,%1,%2,%3};" \
        : "+f"((d)[0]), "+f"((d)[1]), "+f"((d)[2]), "+f"((d)[3]) \
        : "r"((a)[0]), "r"((a)[1]), "r"((a)[2]), "r"((a)[3]), "r"(b0), "r"(b1))

#define CP_ASYNC16(dst, src) \
    asm volatile("cp.async.cg.shared.global [%0], [%1], 16;" :: "r"(dst), "l"(src))
#define CP_COMMIT() asm volatile("cp.async.commit_group;")
#define CP_WAIT1()  asm volatile("cp.async.wait_group 1;")
#define CP_WAIT0()  asm volatile("cp.async.wait_group 0;")

// ======================= split helpers ======================================
__device__ __forceinline__ unsigned bf2(float a, float b) {
    return (unsigned)__bfloat16_as_ushort(__float2bfloat16(a)) |
           ((unsigned)__bfloat16_as_ushort(__float2bfloat16(b)) << 16);
}
__device__ __forceinline__ void split_pair(float a, float b, unsigned& h, unsigned& l) {
    __nv_bfloat16 ah = __float2bfloat16(a), bh = __float2bfloat16(b);
    h = (unsigned)__bfloat16_as_ushort(ah) | ((unsigned)__bfloat16_as_ushort(bh) << 16);
    l = bf2(a - __bfloat162float(ah), b - __bfloat162float(bh));
}
__device__ __forceinline__ void split1(float a, __nv_bfloat16& h, __nv_bfloat16& l) {
    h = __float2bfloat16(a);
    l = __float2bfloat16(a - __bfloat162float(h));
}
__device__ __forceinline__ void split1h(float a, __half& h, __half& l) {
    h = __float2half_rn(a);
    l = __float2half_rn(a - __half2float(h));
}

// ======================= mma.sync GEMM core (K-chunk 32, 3-stage) ===========
// C[128x128] = Ah*Bh + Ah*Bl + Al*Bh over K. Stage 32KB: aH|aL|bH|bL (8KB,
// 64B rows, SW64). 3 stages = 96KB -> 2 CTAs/SM. Warps 2(M) x 4(N), 64x32.
// Pipeline: ONE __syncthreads per chunk; issue(c+2) overwrites stage (c-1)%3,
// which is safe because the barrier at iter c orders it after all mma(c-1).
#define STG32 32768
#define GEMM_SMEM (3 * STG32)

__device__ __forceinline__ void mma_chunk32(uint32_t sst, int lane, int wm, int wn,
                                            float (&acc)[4][4][4]) {
    const uint32_t aH = sst, aL = sst + 8192, bB = sst + 16384, bL = sst + 24576;
#pragma unroll
    for (int kk = 0; kk < 2; kk++) {
        uint32_t bh[2][4], bl[2][4];
        const int brow = wn * 32 + (lane & 7) + ((lane >> 4) << 3);
        const int bcb = kk * 32 + (((lane >> 3) & 1) << 4);
#pragma unroll
        for (int nb = 0; nb < 2; nb++) {
            uint32_t off = SWZ64(((brow + nb * 16) << 6) + bcb);
            LDSM_X4(bh[nb], bB + off);
            LDSM_X4(bl[nb], bL + off);
        }
        const int acb = kk * 32 + ((lane >> 4) << 4);
#pragma unroll
        for (int mi = 0; mi < 4; mi++) {
            uint32_t ah[4], al[4];
            uint32_t off = SWZ64(((wm * 64 + mi * 16 + (lane & 15)) << 6) + acb);
            LDSM_X4(ah, aH + off);
            LDSM_X4(al, aL + off);
#pragma unroll
            for (int ni = 0; ni < 4; ni++) {
                const int nb = ni >> 1, p = (ni & 1) << 1;
                MMA_BF16(acc[mi][ni], ah, bh[nb][p], bh[nb][p + 1]);
                MMA_BF16(acc[mi][ni], ah, bl[nb][p], bl[nb][p + 1]);
                MMA_BF16(acc[mi][ni], al, bh[nb][p], bh[nb][p + 1]);
            }
        }
    }
}

__device__ __forceinline__ void issue_chunk32(
    uint32_t sbase, int c, int t,
    const __nv_bfloat16* Ah, const __nv_bfloat16* Al, size_t sA,
    const __nv_bfloat16* Bh, const __nv_bfloat16* Bl, size_t sB)
{
    const uint32_t sst = sbase + (uint32_t)(c % 3) * STG32;
    const __nv_bfloat16* ah = Ah + (c << 5);
    const __nv_bfloat16* al = Al + (c << 5);
    const __nv_bfloat16* bhp = Bh + (c << 5);
    const __nv_bfloat16* blp = Bl + (c << 5);
#pragma unroll
    for (int i = 0; i < 2; i++) {
        int u = t + (i << 8), r = u >> 2, cu = u & 3;
        uint32_t d = sst + SWZ64((r << 6) + (cu << 4));
        const size_t so = (size_t)r * sA + (cu << 3);
        CP_ASYNC16(d, ah + so);
        CP_ASYNC16(d + 8192, al + so);
    }
#pragma unroll
    for (int i = 0; i < 2; i++) {
        int u = t + (i << 8), r = u >> 2, cu = u & 3;
        uint32_t d = sst + 16384 + SWZ64((r << 6) + (cu << 4));
        const size_t so = (size_t)r * sB + (cu << 3);
        CP_ASYNC16(d, bhp + so);
        CP_ASYNC16(d + 8192, blp + so);
    }
    CP_COMMIT();
}

__device__ __forceinline__ void gemm_mma(
    const __nv_bfloat16* Ah, const __nv_bfloat16* Al, size_t sA,
    const __nv_bfloat16* Bh, const __nv_bfloat16* Bl, size_t sB,
    int K, uint32_t sbase, float (&acc)[4][4][4])
{
    const int t = threadIdx.x;
    const int lane = t & 31, w = t >> 5, wm = w & 1, wn = w >> 1;
#pragma unroll
    for (int mi = 0; mi < 4; mi++)
#pragma unroll
        for (int ni = 0; ni < 4; ni++)
#pragma unroll
            for (int r = 0; r < 4; r++) acc[mi][ni][r] = 0.f;

    const int NC = K >> 5;
    issue_chunk32(sbase, 0, t, Ah, Al, sA, Bh, Bl, sB);
    if (NC > 1) issue_chunk32(sbase, 1, t, Ah, Al, sA, Bh, Bl, sB);
    for (int c = 0; c < NC; c++) {
        if (c + 1 < NC) CP_WAIT1(); else CP_WAIT0();
        __syncthreads();
        if (c + 2 < NC) issue_chunk32(sbase, c + 2, t, Ah, Al, sA, Bh, Bl, sB);
        mma_chunk32(sbase + (uint32_t)(c % 3) * STG32, lane, wm, wn, acc);
    }
}

// ======================= PV fp16 2-pass core (stage 24KB: Ph|Pl|V) ==========
#define STG24 24576
#define PV_SMEM (3 * STG24)

__device__ __forceinline__ void mma_chunk32_pv(uint32_t sst, int lane, int wm, int wn,
                                               float (&acc)[4][4][4]) {
    const uint32_t aH = sst, aL = sst + 8192, bB = sst + 16384;
#pragma unroll
    for (int kk = 0; kk < 2; kk++) {
        uint32_t bh[2][4];
        const int brow = wn * 32 + (lane & 7) + ((lane >> 4) << 3);
        const int bcb = kk * 32 + (((lane >> 3) & 1) << 4);
#pragma unroll
        for (int nb = 0; nb < 2; nb++) {
            uint32_t off = SWZ64(((brow + nb * 16) << 6) + bcb);
            LDSM_X4(bh[nb], bB + off);
        }
        const int acb = kk * 32 + ((lane >> 4) << 4);
#pragma unroll
        for (int mi = 0; mi < 4; mi++) {
            uint32_t ah[4], al[4];
            uint32_t off = SWZ64(((wm * 64 + mi * 16 + (lane & 15)) << 6) + acb);
            LDSM_X4(ah, aH + off);
            LDSM_X4(al, aL + off);
#pragma unroll
            for (int ni = 0; ni < 4; ni++) {
                const int nb = ni >> 1, p = (ni & 1) << 1;
                MMA_F16(acc[mi][ni], ah, bh[nb][p], bh[nb][p + 1]);
                MMA_F16(acc[mi][ni], al, bh[nb][p], bh[nb][p + 1]);
            }
        }
    }
}

__device__ __forceinline__ void issue_chunk32_pv(
    uint32_t sbase, int c, int t,
    const __half* Ph, const __half* Pl, size_t sA,
    const __half* Vv, size_t sB)
{
    const uint32_t sst = sbase + (uint32_t)(c % 3) * STG24;
    const __half* ph = Ph + (c << 5);
    const __half* pl = Pl + (c << 5);
    const __half* vp = Vv + (c << 5);
#pragma unroll
    for (int i = 0; i < 2; i++) {
        int u = t + (i << 8), r = u >> 2, cu = u & 3;
        uint32_t d = sst + SWZ64((r << 6) + (cu << 4));
        const size_t so = (size_t)r * sA + (cu << 3);
        CP_ASYNC16(d, ph + so);
        CP_ASYNC16(d + 8192, pl + so);
    }
#pragma unroll
    for (int i = 0; i < 2; i++) {
        int u = t + (i << 8), r = u >> 2, cu = u & 3;
        uint32_t d = sst + 16384 + SWZ64((r << 6) + (cu << 4));
        CP_ASYNC16(d, vp + (size_t)r * sB + (cu << 3));
    }
    CP_COMMIT();
}

__device__ __forceinline__ void gemm_mma_pv(
    const __half* Ph, const __half* Pl, size_t sA,
    const __half* Vv, size_t sB,
    int K, uint32_t sbase, float (&acc)[4][4][4])
{
    const int t = threadIdx.x;
    const int lane = t & 31, w = t >> 5, wm = w & 1, wn = w >> 1;
#pragma unroll
    for (int mi = 0; mi < 4; mi++)
#pragma unroll
        for (int ni = 0; ni < 4; ni++)
#pragma unroll
            for (int r = 0; r < 4; r++) acc[mi][ni][r] = 0.f;

    const int NC = K >> 5;
    issue_chunk32_pv(sbase, 0, t, Ph, Pl, sA, Vv, sB);
    if (NC > 1) issue_chunk32_pv(sbase, 1, t, Ph, Pl, sA, Vv, sB);
    for (int c = 0; c < NC; c++) {
        if (c + 1 < NC) CP_WAIT1(); else CP_WAIT0();
        __syncthreads();
        if (c + 2 < NC) issue_chunk32_pv(sbase, c + 2, t, Ph, Pl, sA, Vv, sB);
        mma_chunk32_pv(sbase + (uint32_t)(c % 3) * STG24, lane, wm, wn, acc);
    }
}

// ======================= prep kernels =======================================
__global__ __launch_bounds__(256) void xc_kernel(const float* __restrict__ x) {
    int i = blockIdx.x * 256 + threadIdx.x;
    float4 v = ((const float4*)x)[i];
    unsigned h0, l0, h1, l1;
    split_pair(v.x, v.y, h0, l0);
    split_pair(v.z, v.w, h1, l1);
    ((uint2*)g_Xh)[i] = make_uint2(h0, h1);
    ((uint2*)g_Xl)[i] = make_uint2(l0, l1);
}

__global__ void wt_kernel(const float* __restrict__ src, __nv_bfloat16* dh,
                          __nv_bfloat16* dl, int K, int NC) {
    __shared__ float tile[32][33];
    int n0 = blockIdx.x * 32, k0 = blockIdx.y * 32;
    int tx = threadIdx.x, ty = threadIdx.y;        // ty 0..7
#pragma unroll
    for (int r = 0; r < 4; r++)
        tile[ty + 8 * r][tx] = src[(size_t)(k0 + ty + 8 * r) * NC + n0 + tx];
    __syncthreads();
#pragma unroll
    for (int r = 0; r < 4; r++) {
        float v = tile[tx][ty + 8 * r];
        __nv_bfloat16 h, l;
        split1(v, h, l);
        size_t di = (size_t)(n0 + ty + 8 * r) * K + k0 + tx;
        dh[di] = h; dl[di] = l;
    }
}

// V [b][tok][F] (head slice) -> VT[bh][f][tok] fp16 single
__global__ void vt_kernel() {
    __shared__ float tile[32][33];
    int tok0 = blockIdx.x * 32, f0 = blockIdx.y * 32;
    int bh = blockIdx.z, b = bh >> 3, h = bh & 7;
    int tx = threadIdx.x, ty = threadIdx.y;        // ty 0..7
#pragma unroll
    for (int r = 0; r < 4; r++)
        tile[ty + 8 * r][tx] = g_V[(size_t)(b * Nseq + tok0 + ty + 8 * r) * Ff + h * DHd + f0 + tx];
    __syncthreads();
#pragma unroll
    for (int r = 0; r < 4; r++) {
        float v = tile[tx][ty + 8 * r];
        size_t di = (size_t)bh * DHd * Nseq + (size_t)(f0 + ty + 8 * r) * Nseq + tok0 + tx;
        g_VT[di] = __float2half_rn(v);
    }
}

// ======================= 1) QKV projection GEMM + RoPE/bias epilogue ========
__global__ __launch_bounds__(256, 2) void mm_proj_kernel(
    const float* __restrict__ cosr, const float* __restrict__ sinr,
    const float* __restrict__ bv)
{
    extern __shared__ __align__(128) char smem[];
    uint32_t sb = smem_to_u32(smem);
    const int mode = blockIdx.z;
    const int bm = blockIdx.y * 128, bn = blockIdx.x * 128;
    const __nv_bfloat16* Ah = g_Xh + (size_t)bm * Dm;
    const __nv_bfloat16* Al = g_Xl + (size_t)bm * Dm;
    const __nv_bfloat16* Bh = g_WTh + ((size_t)mode * Ff + bn) * Dm;
    const __nv_bfloat16* Bl = g_WTl + ((size_t)mode * Ff + bn) * Dm;
    float acc[4][4][4];
    gemm_mma(Ah, Al, Dm, Bh, Bl, Dm, Dm, sb, acc);

    const int t = threadIdx.x, lane = t & 31, w = t >> 5, wm = w & 1, wn = w >> 1;
    if (mode == 2) {
#pragma unroll
        for (int mi = 0; mi < 4; mi++)
#pragma unroll
            for (int ni = 0; ni < 4; ni++) {
                int m = bm + wm * 64 + mi * 16 + (lane >> 2);
                int c = bn + wn * 32 + ni * 8 + ((lane & 3) << 1);
                float b0 = bv[c], b1 = bv[c + 1];
                *(float2*)&g_V[(size_t)m * Ff + c] =
                    make_float2(acc[mi][ni][0] + b0, acc[mi][ni][1] + b1);
                *(float2*)&g_V[(size_t)(m + 8) * Ff + c] =
                    make_float2(acc[mi][ni][2] + b0, acc[mi][ni][3] + b1);
            }
    } else {
        __nv_bfloat16* OH = (mode == 0) ? g_Qh : g_Kh;
        __nv_bfloat16* OL = (mode == 0) ? g_Ql : g_Kl;
#pragma unroll
        for (int mi = 0; mi < 4; mi++)
#pragma unroll
            for (int ni = 0; ni < 4; ni++) {
                int m0 = bm + wm * 64 + mi * 16 + (lane >> 2);
                int c = bn + wn * 32 + ni * 8 + ((lane & 3) << 1);
#pragma unroll
                for (int half = 0; half < 2; half++) {
                    int m = m0 + half * 8;
                    int n = m & (Nseq - 1);
                    float cr0 = cosr[(size_t)n * Ff + c];
                    float sr0 = sinr[(size_t)n * Ff + c];
                    float cr1 = cosr[(size_t)n * Ff + c + 1];
                    float sr1 = sinr[(size_t)n * Ff + c + 1];
                    float e = acc[mi][ni][half * 2];
                    float o = acc[mi][ni][half * 2 + 1];
                    float oe = e * cr0 - o * sr0;
                    float oo = o * cr1 + e * sr1;
                    unsigned hw, lw;
                    split_pair(oe, oo, hw, lw);
                    *(unsigned*)&OH[(size_t)m * Ff + c] = hw;
                    *(unsigned*)&OL[(size_t)m * Ff + c] = lw;
                }
            }
    }
}

// ======================= 2) S = Q K^T ======================================
__global__ __launch_bounds__(256, 2) void mm_score_kernel() {
    if (blockIdx.x > blockIdx.y) return;
    extern __shared__ __align__(128) char smem[];
    uint32_t sb = smem_to_u32(smem);
    const int bh = blockIdx.z, b = bh >> 3, h = bh & 7;
    const int i0 = blockIdx.y * 128, j0 = blockIdx.x * 128;
    const __nv_bfloat16* Ah = g_Qh + (size_t)(b * Nseq + i0) * Ff + h * DHd;
    const __nv_bfloat16* Al = g_Ql + (size_t)(b * Nseq + i0) * Ff + h * DHd;
    const __nv_bfloat16* Bh = g_Kh + (size_t)(b * Nseq + j0) * Ff + h * DHd;
    const __nv_bfloat16* Bl = g_Kl + (size_t)(b * Nseq + j0) * Ff + h * DHd;
    float acc[4][4][4];
    gemm_mma(Ah, Al, Ff, Bh, Bl, Ff, DHd, sb, acc);

    const int t = threadIdx.x, lane = t & 31, w = t >> 5, wm = w & 1, wn = w >> 1;
    float* Sp = g_S + (size_t)bh * Nseq * Nseq;
#pragma unroll
    for (int mi = 0; mi < 4; mi++)
#pragma unroll
        for (int ni = 0; ni < 4; ni++) {
            int m = i0 + wm * 64 + mi * 16 + (lane >> 2);
            int nn = j0 + wn * 32 + ni * 8 + ((lane & 3) << 1);
            *(float2*)&Sp[(size_t)m * Nseq + nn] = make_float2(acc[mi][ni][0], acc[mi][ni][1]);
            *(float2*)&Sp[(size_t)(m + 8) * Nseq + nn] = make_float2(acc[mi][ni][2], acc[mi][ni][3]);
        }
}

// ======================= 3) causal row softmax -> P fp16 hi/lo ==============
__global__ __launch_bounds__(256) void softmax_kernel() {
    const int rgl = blockIdx.x;
    const int bh = rgl >> 11, i = rgl & (Nseq - 1);
    const size_t base = (size_t)bh * Nseq * Nseq + (size_t)i * Nseq;
    const float* row = g_S + base;
    const int L = i + 1;
    const int Lz = ((i >> 7) + 1) << 7;
    const int t = threadIdx.x;

    float v[8];
    int cnt = 0;
    float mx = -1e30f;
    for (int j = t; j < L; j += 256) { float x = row[j]; v[cnt++] = x; mx = fmaxf(mx, x); }

    __shared__ float red[256];
    red[t] = mx; __syncthreads();
    for (int s = 128; s > 0; s >>= 1) { if (t < s) red[t] = fmaxf(red[t], red[t + s]); __syncthreads(); }
    mx = red[0]; __syncthreads();

    float sum = 0.f;
    for (int k = 0; k < cnt; k++) { v[k] = expf(v[k] - mx); sum += v[k]; }
    red[t] = sum; __syncthreads();
    for (int s = 128; s > 0; s >>= 1) { if (t < s) red[t] += red[t + s]; __syncthreads(); }
    const float inv = 1.0f / red[0];

    cnt = 0;
    for (int j = t; j < L; j += 256) {
        float p = v[cnt++] * inv;
        __half h, l;
        split1h(p, h, l);
        g_Ph[base + j] = h; g_Pl[base + j] = l;
    }
    const __half z = __float2half_rn(0.f);
    for (int j = t; j < Lz; j += 256)
        if (j >= L) { g_Ph[base + j] = z; g_Pl[base + j] = z; }
}

// ======================= 4) Yh = P @ V (fp16 2-pass) ========================
__global__ __launch_bounds__(256, 2) void mm_pv_kernel() {
    extern __shared__ __align__(128) char smem[];
    uint32_t sb = smem_to_u32(smem);
    const int bh = blockIdx.z;
    const int i0 = blockIdx.y * 128, n0 = blockIdx.x * 128;
    const __half* Ph = g_Ph + (size_t)bh * Nseq * Nseq + (size_t)i0 * Nseq;
    const __half* Pl = g_Pl + (size_t)bh * Nseq * Nseq + (size_t)i0 * Nseq;
    const __half* Vv = g_VT + (size_t)bh * DHd * Nseq + (size_t)n0 * Nseq;
    float acc[4][4][4];
    gemm_mma_pv(Ph, Pl, Nseq, Vv, Nseq, i0 + 128, sb, acc);

    const int t = threadIdx.x, lane = t & 31, w = t >> 5, wm = w & 1, wn = w >> 1;
    float* Yp = g_YH + (size_t)bh * Nseq * Dm;
#pragma unroll
    for (int mi = 0; mi < 4; mi++)
#pragma unroll
        for (int ni = 0; ni < 4; ni++) {
            int m = i0 + wm * 64 + mi * 16 + (lane >> 2);
            int nn = n0 + wn * 32 + ni * 8 + ((lane & 3) << 1);
            *(float2*)&Yp[(size_t)m * Dm + nn] = make_float2(acc[mi][ni][0], acc[mi][ni][1]);
            *(float2*)&Yp[(size_t)(m + 8) * Dm + nn] = make_float2(acc[mi][ni][2], acc[mi][ni][3]);
        }
}

// ======================= 5) head-sum + QuickGELU + split ====================
__global__ __launch_bounds__(256) void reduce_kernel() {
    int idx = blockIdx.x * 256 + threadIdx.x;
    int m = idx >> 7;
    int c4 = (idx & 127) * 4;
    int b = m >> 11, n = m & (Nseq - 1);
    float4 s = make_float4(0.f, 0.f, 0.f, 0.f);
#pragma unroll
    for (int h = 0; h < Hh; h++) {
        const float4 v = *(const float4*)(g_YH + (size_t)((b * Hh + h) * Nseq + n) * Dm + c4);
        s.x += v.x; s.y += v.y; s.z += v.z; s.w += v.w;
    }
    s.x = s.x / (1.f + expf(-1.702f * s.x));
    s.y = s.y / (1.f + expf(-1.702f * s.y));
    s.z = s.z / (1.f + expf(-1.702f * s.z));
    s.w = s.w / (1.f + expf(-1.702f * s.w));
    unsigned h0, l0, h1, l1;
    split_pair(s.x, s.y, h0, l0);
    split_pair(s.z, s.w, h1, l1);
    *(uint2*)(g_Gh + (size_t)m * Dm + c4) = make_uint2(h0, h1);
    *(uint2*)(g_Gl + (size_t)m * Dm + c4) = make_uint2(l0, l1);
}

// ======================= 6) output projection ===============================
__global__ __launch_bounds__(256, 2) void mm_out_kernel(const float* __restrict__ bo,
                                                        float* __restrict__ Outp) {
    extern __shared__ __align__(128) char smem[];
    uint32_t sb = smem_to_u32(smem);
    const int bm = blockIdx.y * 128, bn = blockIdx.x * 128;
    const __nv_bfloat16* Ah = g_Gh + (size_t)bm * Dm;
    const __nv_bfloat16* Al = g_Gl + (size_t)bm * Dm;
    const __nv_bfloat16* Bh = g_WoTh + (size_t)bn * Dm;
    const __nv_bfloat16* Bl = g_WoTl + (size_t)bn * Dm;
    float acc[4][4][4];
    gemm_mma(Ah, Al, Dm, Bh, Bl, Dm, Dm, sb, acc);

    const int t = threadIdx.x, lane = t & 31, w = t >> 5, wm = w & 1, wn = w >> 1;
#pragma unroll
    for (int mi = 0; mi < 4; mi++)
#pragma unroll
        for (int ni = 0; ni < 4; ni++) {
            int m = bm + wm * 64 + mi * 16 + (lane >> 2);
            int c = bn + wn * 32 + ni * 8 + ((lane & 3) << 1);
            float b0 = bo[c], b1 = bo[c + 1];
            *(float2*)&Outp[(size_t)m * Dm + c] =
                make_float2(acc[mi][ni][0] + b0, acc[mi][ni][1] + b1);
            *(float2*)&Outp[(size_t)(m + 8) * Dm + c] =
                make_float2(acc[mi][ni][2] + b0, acc[mi][ni][3] + b1);
        }
}

// ======================= launch =============================================
extern "C" void kernel_launch(void* const* d_in, const int* in_sizes, int n_in,
                              void* d_out, int out_size)
{
    const float* x    = (const float*)d_in[0];
    const float* cosr = (const float*)d_in[1];
    const float* sinr = (const float*)d_in[2];
    // d_in[3] = target_mask (causal tril; handled analytically)
    const float* Wq   = (const float*)d_in[4];
    const float* Wk   = (const float*)d_in[5];
    const float* Wv   = (const float*)d_in[6];
    const float* bv   = (const float*)d_in[7];
    const float* Wo   = (const float*)d_in[8];
    const float* bo   = (const float*)d_in[9];
    float* out = (float*)d_out;

    cudaFuncSetAttribute(mm_proj_kernel,  cudaFuncAttributeMaxDynamicSharedMemorySize, GEMM_SMEM);
    cudaFuncSetAttribute(mm_score_kernel, cudaFuncAttributeMaxDynamicSharedMemorySize, GEMM_SMEM);
    cudaFuncSetAttribute(mm_pv_kernel,    cudaFuncAttributeMaxDynamicSharedMemorySize, PV_SMEM);
    cudaFuncSetAttribute(mm_out_kernel,   cudaFuncAttributeMaxDynamicSharedMemorySize, GEMM_SMEM);

    __nv_bfloat16 *wth, *wtl, *woth, *wotl;
    cudaGetSymbolAddress((void**)&wth,  g_WTh);
    cudaGetSymbolAddress((void**)&wtl,  g_WTl);
    cudaGetSymbolAddress((void**)&woth, g_WoTh);
    cudaGetSymbolAddress((void**)&wotl, g_WoTl);

    xc_kernel<<<2048, 256>>>(x);
    wt_kernel<<<dim3(128, 16), dim3(32, 8)>>>(Wq, wth + 0 * (size_t)Ff * Dm,
                                              wtl + 0 * (size_t)Ff * Dm, Dm, Ff);
    wt_kernel<<<dim3(128, 16), dim3(32, 8)>>>(Wk, wth + 1 * (size_t)Ff * Dm,
                                              wtl + 1 * (size_t)Ff * Dm, Dm, Ff);
    wt_kernel<<<dim3(128, 16), dim3(32, 8)>>>(Wv, wth + 2 * (size_t)Ff * Dm,
                                              wtl + 2 * (size_t)Ff * Dm, Dm, Ff);
    mm_proj_kernel<<<dim3(32, 32, 3), 256, GEMM_SMEM>>>(cosr, sinr, bv);
    mm_score_kernel<<<dim3(16, 16, BH), 256, GEMM_SMEM>>>();
    vt_kernel<<<dim3(64, 16, BH), dim3(32, 8)>>>();
    softmax_kernel<<<BH * Nseq, 256>>>();
    mm_pv_kernel<<<dim3(4, 16, BH), 256, PV_SMEM>>>();
    reduce_kernel<<<2048, 256>>>();
    wt_kernel<<<dim3(16, 16), dim3(32, 8)>>>(Wo, woth, wotl, Dm, Dm);
    mm_out_kernel<<<dim3(4, 32), 256, GEMM_SMEM>>>(bo, out);
}

// round 13
// speedup vs baseline: 1.8084x; 1.0276x over previous
#include <cuda_runtime.h>
#include <cuda_bf16.h>
#include <cuda_fp16.h>
#include <cstdint>
#include <math.h>

#define Bsz  2
#define Nseq 2048
#define Dm   512
#define Hh   8
#define DHd  512
#define Ff   4096
#define Mrows 4096   // Bsz*Nseq
#define BH   16      // Bsz*Hh

// ======================= scratch (device globals) ===========================
__device__ __align__(16) __nv_bfloat16 g_Xh[(size_t)Mrows * Dm];
__device__ __align__(16) __nv_bfloat16 g_Xl[(size_t)Mrows * Dm];
__device__ __align__(16) __half        g_X16h[(size_t)Mrows * Dm];
__device__ __align__(16) __half        g_X16l[(size_t)Mrows * Dm];
__device__ __align__(16) __nv_bfloat16 g_WTh[2 * (size_t)Ff * Dm];   // [mode][n][k] Q,K
__device__ __align__(16) __nv_bfloat16 g_WTl[2 * (size_t)Ff * Dm];
__device__ __align__(16) __half        g_WvT16[(size_t)Ff * Dm];     // [n][k] fp16
__device__ __align__(16) __half        g_WoT16[(size_t)Dm * Dm];
__device__ __align__(16) __nv_bfloat16 g_Qh[(size_t)Mrows * Ff];
__device__ __align__(16) __nv_bfloat16 g_Ql[(size_t)Mrows * Ff];
__device__ __align__(16) __nv_bfloat16 g_Kh[(size_t)Mrows * Ff];
__device__ __align__(16) __nv_bfloat16 g_Kl[(size_t)Mrows * Ff];
__device__ __align__(16) float         g_V [(size_t)Mrows * Ff];
__device__ __align__(16) __half        g_VT[(size_t)BH * DHd * Nseq]; // [bh][f][tok], fp16
__device__ __align__(16) float         g_S [(size_t)BH * Nseq * Nseq];
__device__ __align__(16) __half        g_Ph[(size_t)BH * Nseq * Nseq];
__device__ __align__(16) __half        g_Pl[(size_t)BH * Nseq * Nseq];
__device__ __align__(16) float         g_YH[(size_t)BH * Nseq * Dm];
__device__ __align__(16) __half        g_G16h[(size_t)Mrows * Dm];
__device__ __align__(16) __half        g_G16l[(size_t)Mrows * Dm];

// ======================= helpers ===========================================
__device__ __forceinline__ uint32_t smem_to_u32(const void* p) {
    uint32_t a;
    asm("{ .reg .u64 t; cvta.to.shared.u64 t, %1; cvt.u32.u64 %0, t; }" : "=r"(a) : "l"(p));
    return a;
}
// SW64 swizzle for 64-byte rows (8 rows x 64B atom)
#define SWZ64(b) ((b) ^ (((b) >> 3) & 0x30))

#define LDSM_X4(r, addr) \
    asm volatile("ldmatrix.sync.aligned.m8n8.x4.shared.b16 {%0,%1,%2,%3}, [%4];" \
        : "=r"((r)[0]), "=r"((r)[1]), "=r"((r)[2]), "=r"((r)[3]) : "r"(addr))

#define MMA_BF16(d, a, b0, b1) \
    asm volatile("mma.sync.aligned.m16n8k16.row.col.f32.bf16.bf16.f32 " \
        "{%0,%1,%2,%3}, {%4,%5,%6,%7}, {%8,%9}, {%0,%1,%2,%3};" \
        : "+f"((d)[0]), "+f"((d)[1]), "+f"((d)[2]), "+f"((d)[3]) \
        : "r"((a)[0]), "r"((a)[1]), "r"((a)[2]), "r"((a)[3]), "r"(b0), "r"(b1))

#define MMA_F16(d, a, b0, b1) \
    asm volatile("mma.sync.aligned.m16n8k16.row.col.f32.f16.f16.f32 " \
        "{%0,%1,%2,%3}, {%4,%5,%6,%7}, {%8,%9}, {%0,%1,%2,%3};" \
        : "+f"((d)[0]), "+f"((d)[1]), "+f"((d)[2]), "+f"((d)[3]) \
        : "r"((a)[0]), "r"((a)[1]), "r"((a)[2]), "r"((a)[3]), "r"(b0), "r"(b1))

#define CP_ASYNC16(dst, src) \
    asm volatile("cp.async.cg.shared.global [%0], [%1], 16;" :: "r"(dst), "l"(src))
#define CP_COMMIT() asm volatile("cp.async.commit_group;")
#define CP_WAIT1()  asm volatile("cp.async.wait_group 1;")
#define CP_WAIT0()  asm volatile("cp.async.wait_group 0;")

// ======================= split helpers ======================================
__device__ __forceinline__ unsigned bf2(float a, float b) {
    return (unsigned)__bfloat16_as_ushort(__float2bfloat16(a)) |
           ((unsigned)__bfloat16_as_ushort(__float2bfloat16(b)) << 16);
}
__device__ __forceinline__ void split_pair(float a, float b, unsigned& h, unsigned& l) {
    __nv_bfloat16 ah = __float2bfloat16(a), bh = __float2bfloat16(b);
    h = (unsigned)__bfloat16_as_ushort(ah) | ((unsigned)__bfloat16_as_ushort(bh) << 16);
    l = bf2(a - __bfloat162float(ah), b - __bfloat162float(bh));
}
__device__ __forceinline__ void split_pair16(float a, float b, unsigned& h, unsigned& l) {
    __half ah = __float2half_rn(a), bh = __float2half_rn(b);
    h = (unsigned)__half_as_ushort(ah) | ((unsigned)__half_as_ushort(bh) << 16);
    __half al = __float2half_rn(a - __half2float(ah));
    __half bl = __float2half_rn(b - __half2float(bh));
    l = (unsigned)__half_as_ushort(al) | ((unsigned)__half_as_ushort(bl) << 16);
}
__device__ __forceinline__ void split1(float a, __nv_bfloat16& h, __nv_bfloat16& l) {
    h = __float2bfloat16(a);
    l = __float2bfloat16(a - __bfloat162float(h));
}
__device__ __forceinline__ void split1h(float a, __half& h, __half& l) {
    h = __float2half_rn(a);
    l = __float2half_rn(a - __half2float(h));
}

// ======================= mma.sync GEMM core (K-chunk 32, 3-stage) ===========
// C[128x128] = Ah*Bh + Ah*Bl + Al*Bh over K (bf16, 3-pass). Stage 32KB:
// aH|aL|bH|bL (8KB, 64B rows, SW64). 3 stages = 96KB -> 2 CTAs/SM.
// Pipeline: one __syncthreads per chunk; issue(c+2) overwrites stage (c-1)%3.
#define STG32 32768
#define GEMM_SMEM (3 * STG32)

__device__ __forceinline__ void mma_chunk32(uint32_t sst, int lane, int wm, int wn,
                                            float (&acc)[4][4][4]) {
    const uint32_t aH = sst, aL = sst + 8192, bB = sst + 16384, bL = sst + 24576;
#pragma unroll
    for (int kk = 0; kk < 2; kk++) {
        uint32_t bh[2][4], bl[2][4];
        const int brow = wn * 32 + (lane & 7) + ((lane >> 4) << 3);
        const int bcb = kk * 32 + (((lane >> 3) & 1) << 4);
#pragma unroll
        for (int nb = 0; nb < 2; nb++) {
            uint32_t off = SWZ64(((brow + nb * 16) << 6) + bcb);
            LDSM_X4(bh[nb], bB + off);
            LDSM_X4(bl[nb], bL + off);
        }
        const int acb = kk * 32 + ((lane >> 4) << 4);
#pragma unroll
        for (int mi = 0; mi < 4; mi++) {
            uint32_t ah[4], al[4];
            uint32_t off = SWZ64(((wm * 64 + mi * 16 + (lane & 15)) << 6) + acb);
            LDSM_X4(ah, aH + off);
            LDSM_X4(al, aL + off);
#pragma unroll
            for (int ni = 0; ni < 4; ni++) {
                const int nb = ni >> 1, p = (ni & 1) << 1;
                MMA_BF16(acc[mi][ni], ah, bh[nb][p], bh[nb][p + 1]);
                MMA_BF16(acc[mi][ni], ah, bl[nb][p], bl[nb][p + 1]);
                MMA_BF16(acc[mi][ni], al, bh[nb][p], bh[nb][p + 1]);
            }
        }
    }
}

__device__ __forceinline__ void issue_chunk32(
    uint32_t sbase, int c, int t,
    const __nv_bfloat16* Ah, const __nv_bfloat16* Al, size_t sA,
    const __nv_bfloat16* Bh, const __nv_bfloat16* Bl, size_t sB)
{
    const uint32_t sst = sbase + (uint32_t)(c % 3) * STG32;
    const __nv_bfloat16* ah = Ah + (c << 5);
    const __nv_bfloat16* al = Al + (c << 5);
    const __nv_bfloat16* bhp = Bh + (c << 5);
    const __nv_bfloat16* blp = Bl + (c << 5);
#pragma unroll
    for (int i = 0; i < 2; i++) {
        int u = t + (i << 8), r = u >> 2, cu = u & 3;
        uint32_t d = sst + SWZ64((r << 6) + (cu << 4));
        const size_t so = (size_t)r * sA + (cu << 3);
        CP_ASYNC16(d, ah + so);
        CP_ASYNC16(d + 8192, al + so);
    }
#pragma unroll
    for (int i = 0; i < 2; i++) {
        int u = t + (i << 8), r = u >> 2, cu = u & 3;
        uint32_t d = sst + 16384 + SWZ64((r << 6) + (cu << 4));
        const size_t so = (size_t)r * sB + (cu << 3);
        CP_ASYNC16(d, bhp + so);
        CP_ASYNC16(d + 8192, blp + so);
    }
    CP_COMMIT();
}

__device__ __forceinline__ void gemm_mma(
    const __nv_bfloat16* Ah, const __nv_bfloat16* Al, size_t sA,
    const __nv_bfloat16* Bh, const __nv_bfloat16* Bl, size_t sB,
    int K, uint32_t sbase, float (&acc)[4][4][4])
{
    const int t = threadIdx.x;
    const int lane = t & 31, w = t >> 5, wm = w & 1, wn = w >> 1;
#pragma unroll
    for (int mi = 0; mi < 4; mi++)
#pragma unroll
        for (int ni = 0; ni < 4; ni++)
#pragma unroll
            for (int r = 0; r < 4; r++) acc[mi][ni][r] = 0.f;

    const int NC = K >> 5;
    issue_chunk32(sbase, 0, t, Ah, Al, sA, Bh, Bl, sB);
    if (NC > 1) issue_chunk32(sbase, 1, t, Ah, Al, sA, Bh, Bl, sB);
    for (int c = 0; c < NC; c++) {
        if (c + 1 < NC) CP_WAIT1(); else CP_WAIT0();
        __syncthreads();
        if (c + 2 < NC) issue_chunk32(sbase, c + 2, t, Ah, Al, sA, Bh, Bl, sB);
        mma_chunk32(sbase + (uint32_t)(c % 3) * STG32, lane, wm, wn, acc);
    }
}

// ======================= fp16 2-pass core (stage 24KB: Ah|Al|B) =============
// C = (Ah + Al) * B, fp16 operands, fp32 accum. Used by PV, V-proj, out-proj.
#define STG24 24576
#define PV_SMEM (3 * STG24)

__device__ __forceinline__ void mma_chunk32_pv(uint32_t sst, int lane, int wm, int wn,
                                               float (&acc)[4][4][4]) {
    const uint32_t aH = sst, aL = sst + 8192, bB = sst + 16384;
#pragma unroll
    for (int kk = 0; kk < 2; kk++) {
        uint32_t bh[2][4];
        const int brow = wn * 32 + (lane & 7) + ((lane >> 4) << 3);
        const int bcb = kk * 32 + (((lane >> 3) & 1) << 4);
#pragma unroll
        for (int nb = 0; nb < 2; nb++) {
            uint32_t off = SWZ64(((brow + nb * 16) << 6) + bcb);
            LDSM_X4(bh[nb], bB + off);
        }
        const int acb = kk * 32 + ((lane >> 4) << 4);
#pragma unroll
        for (int mi = 0; mi < 4; mi++) {
            uint32_t ah[4], al[4];
            uint32_t off = SWZ64(((wm * 64 + mi * 16 + (lane & 15)) << 6) + acb);
            LDSM_X4(ah, aH + off);
            LDSM_X4(al, aL + off);
#pragma unroll
            for (int ni = 0; ni < 4; ni++) {
                const int nb = ni >> 1, p = (ni & 1) << 1;
                MMA_F16(acc[mi][ni], ah, bh[nb][p], bh[nb][p + 1]);
                MMA_F16(acc[mi][ni], al, bh[nb][p], bh[nb][p + 1]);
            }
        }
    }
}

__device__ __forceinline__ void issue_chunk32_pv(
    uint32_t sbase, int c, int t,
    const __half* Ph, const __half* Pl, size_t sA,
    const __half* Vv, size_t sB)
{
    const uint32_t sst = sbase + (uint32_t)(c % 3) * STG24;
    const __half* ph = Ph + (c << 5);
    const __half* pl = Pl + (c << 5);
    const __half* vp = Vv + (c << 5);
#pragma unroll
    for (int i = 0; i < 2; i++) {
        int u = t + (i << 8), r = u >> 2, cu = u & 3;
        uint32_t d = sst + SWZ64((r << 6) + (cu << 4));
        const size_t so = (size_t)r * sA + (cu << 3);
        CP_ASYNC16(d, ph + so);
        CP_ASYNC16(d + 8192, pl + so);
    }
#pragma unroll
    for (int i = 0; i < 2; i++) {
        int u = t + (i << 8), r = u >> 2, cu = u & 3;
        uint32_t d = sst + 16384 + SWZ64((r << 6) + (cu << 4));
        CP_ASYNC16(d, vp + (size_t)r * sB + (cu << 3));
    }
    CP_COMMIT();
}

__device__ __forceinline__ void gemm_mma_pv(
    const __half* Ph, const __half* Pl, size_t sA,
    const __half* Vv, size_t sB,
    int K, uint32_t sbase, float (&acc)[4][4][4])
{
    const int t = threadIdx.x;
    const int lane = t & 31, w = t >> 5, wm = w & 1, wn = w >> 1;
#pragma unroll
    for (int mi = 0; mi < 4; mi++)
#pragma unroll
        for (int ni = 0; ni < 4; ni++)
#pragma unroll
            for (int r = 0; r < 4; r++) acc[mi][ni][r] = 0.f;

    const int NC = K >> 5;
    issue_chunk32_pv(sbase, 0, t, Ph, Pl, sA, Vv, sB);
    if (NC > 1) issue_chunk32_pv(sbase, 1, t, Ph, Pl, sA, Vv, sB);
    for (int c = 0; c < NC; c++) {
        if (c + 1 < NC) CP_WAIT1(); else CP_WAIT0();
        __syncthreads();
        if (c + 2 < NC) issue_chunk32_pv(sbase, c + 2, t, Ph, Pl, sA, Vv, sB);
        mma_chunk32_pv(sbase + (uint32_t)(c % 3) * STG24, lane, wm, wn, acc);
    }
}

// ======================= prep kernels =======================================
__global__ __launch_bounds__(256) void xc_kernel(const float* __restrict__ x) {
    int i = blockIdx.x * 256 + threadIdx.x;
    float4 v = ((const float4*)x)[i];
    unsigned h0, l0, h1, l1;
    split_pair(v.x, v.y, h0, l0);
    split_pair(v.z, v.w, h1, l1);
    ((uint2*)g_Xh)[i] = make_uint2(h0, h1);
    ((uint2*)g_Xl)[i] = make_uint2(l0, l1);
    split_pair16(v.x, v.y, h0, l0);
    split_pair16(v.z, v.w, h1, l1);
    ((uint2*)g_X16h)[i] = make_uint2(h0, h1);
    ((uint2*)g_X16l)[i] = make_uint2(l0, l1);
}

__global__ void wt_kernel(const float* __restrict__ src, __nv_bfloat16* dh,
                          __nv_bfloat16* dl, int K, int NC) {
    __shared__ float tile[32][33];
    int n0 = blockIdx.x * 32, k0 = blockIdx.y * 32;
    int tx = threadIdx.x, ty = threadIdx.y;        // ty 0..7
#pragma unroll
    for (int r = 0; r < 4; r++)
        tile[ty + 8 * r][tx] = src[(size_t)(k0 + ty + 8 * r) * NC + n0 + tx];
    __syncthreads();
#pragma unroll
    for (int r = 0; r < 4; r++) {
        float v = tile[tx][ty + 8 * r];
        __nv_bfloat16 h, l;
        split1(v, h, l);
        size_t di = (size_t)(n0 + ty + 8 * r) * K + k0 + tx;
        dh[di] = h; dl[di] = l;
    }
}

// transpose to single fp16 (for Wv, Wo)
__global__ void wt16_kernel(const float* __restrict__ src, __half* dst,
                            int K, int NC) {
    __shared__ float tile[32][33];
    int n0 = blockIdx.x * 32, k0 = blockIdx.y * 32;
    int tx = threadIdx.x, ty = threadIdx.y;        // ty 0..7
#pragma unroll
    for (int r = 0; r < 4; r++)
        tile[ty + 8 * r][tx] = src[(size_t)(k0 + ty + 8 * r) * NC + n0 + tx];
    __syncthreads();
#pragma unroll
    for (int r = 0; r < 4; r++) {
        float v = tile[tx][ty + 8 * r];
        dst[(size_t)(n0 + ty + 8 * r) * K + k0 + tx] = __float2half_rn(v);
    }
}

// V [b][tok][F] (head slice) -> VT[bh][f][tok] fp16 single
__global__ void vt_kernel() {
    __shared__ float tile[32][33];
    int tok0 = blockIdx.x * 32, f0 = blockIdx.y * 32;
    int bh = blockIdx.z, b = bh >> 3, h = bh & 7;
    int tx = threadIdx.x, ty = threadIdx.y;        // ty 0..7
#pragma unroll
    for (int r = 0; r < 4; r++)
        tile[ty + 8 * r][tx] = g_V[(size_t)(b * Nseq + tok0 + ty + 8 * r) * Ff + h * DHd + f0 + tx];
    __syncthreads();
#pragma unroll
    for (int r = 0; r < 4; r++) {
        float v = tile[tx][ty + 8 * r];
        size_t di = (size_t)bh * DHd * Nseq + (size_t)(f0 + ty + 8 * r) * Nseq + tok0 + tx;
        g_VT[di] = __float2half_rn(v);
    }
}

// ======================= 1a) Q/K projection GEMM + RoPE epilogue ============
__global__ __launch_bounds__(256, 2) void mm_proj_kernel(
    const float* __restrict__ cosr, const float* __restrict__ sinr)
{
    extern __shared__ __align__(128) char smem[];
    uint32_t sb = smem_to_u32(smem);
    const int mode = blockIdx.z;   // 0=Q, 1=K
    const int bm = blockIdx.y * 128, bn = blockIdx.x * 128;
    const __nv_bfloat16* Ah = g_Xh + (size_t)bm * Dm;
    const __nv_bfloat16* Al = g_Xl + (size_t)bm * Dm;
    const __nv_bfloat16* Bh = g_WTh + ((size_t)mode * Ff + bn) * Dm;
    const __nv_bfloat16* Bl = g_WTl + ((size_t)mode * Ff + bn) * Dm;
    float acc[4][4][4];
    gemm_mma(Ah, Al, Dm, Bh, Bl, Dm, Dm, sb, acc);

    const int t = threadIdx.x, lane = t & 31, w = t >> 5, wm = w & 1, wn = w >> 1;
    __nv_bfloat16* OH = (mode == 0) ? g_Qh : g_Kh;
    __nv_bfloat16* OL = (mode == 0) ? g_Ql : g_Kl;
#pragma unroll
    for (int mi = 0; mi < 4; mi++)
#pragma unroll
        for (int ni = 0; ni < 4; ni++) {
            int m0 = bm + wm * 64 + mi * 16 + (lane >> 2);
            int c = bn + wn * 32 + ni * 8 + ((lane & 3) << 1);
#pragma unroll
            for (int half = 0; half < 2; half++) {
                int m = m0 + half * 8;
                int n = m & (Nseq - 1);
                float cr0 = cosr[(size_t)n * Ff + c];
                float sr0 = sinr[(size_t)n * Ff + c];
                float cr1 = cosr[(size_t)n * Ff + c + 1];
                float sr1 = sinr[(size_t)n * Ff + c + 1];
                float e = acc[mi][ni][half * 2];
                float o = acc[mi][ni][half * 2 + 1];
                float oe = e * cr0 - o * sr0;
                float oo = o * cr1 + e * sr1;
                unsigned hw, lw;
                split_pair(oe, oo, hw, lw);
                *(unsigned*)&OH[(size_t)m * Ff + c] = hw;
                *(unsigned*)&OL[(size_t)m * Ff + c] = lw;
            }
        }
}

// ======================= 1b) V projection (fp16 2-pass) + bias ==============
__global__ __launch_bounds__(256, 2) void mm_vproj_kernel(const float* __restrict__ bv)
{
    extern __shared__ __align__(128) char smem[];
    uint32_t sb = smem_to_u32(smem);
    const int bm = blockIdx.y * 128, bn = blockIdx.x * 128;
    const __half* Ah = g_X16h + (size_t)bm * Dm;
    const __half* Al = g_X16l + (size_t)bm * Dm;
    const __half* Bv = g_WvT16 + (size_t)bn * Dm;
    float acc[4][4][4];
    gemm_mma_pv(Ah, Al, Dm, Bv, Dm, Dm, sb, acc);

    const int t = threadIdx.x, lane = t & 31, w = t >> 5, wm = w & 1, wn = w >> 1;
#pragma unroll
    for (int mi = 0; mi < 4; mi++)
#pragma unroll
        for (int ni = 0; ni < 4; ni++) {
            int m = bm + wm * 64 + mi * 16 + (lane >> 2);
            int c = bn + wn * 32 + ni * 8 + ((lane & 3) << 1);
            float b0 = bv[c], b1 = bv[c + 1];
            *(float2*)&g_V[(size_t)m * Ff + c] =
                make_float2(acc[mi][ni][0] + b0, acc[mi][ni][1] + b1);
            *(float2*)&g_V[(size_t)(m + 8) * Ff + c] =
                make_float2(acc[mi][ni][2] + b0, acc[mi][ni][3] + b1);
        }
}

// ======================= 2) S = Q K^T ======================================
__global__ __launch_bounds__(256, 2) void mm_score_kernel() {
    if (blockIdx.x > blockIdx.y) return;
    extern __shared__ __align__(128) char smem[];
    uint32_t sb = smem_to_u32(smem);
    const int bh = blockIdx.z, b = bh >> 3, h = bh & 7;
    const int i0 = blockIdx.y * 128, j0 = blockIdx.x * 128;
    const __nv_bfloat16* Ah = g_Qh + (size_t)(b * Nseq + i0) * Ff + h * DHd;
    const __nv_bfloat16* Al = g_Ql + (size_t)(b * Nseq + i0) * Ff + h * DHd;
    const __nv_bfloat16* Bh = g_Kh + (size_t)(b * Nseq + j0) * Ff + h * DHd;
    const __nv_bfloat16* Bl = g_Kl + (size_t)(b * Nseq + j0) * Ff + h * DHd;
    float acc[4][4][4];
    gemm_mma(Ah, Al, Ff, Bh, Bl, Ff, DHd, sb, acc);

    const int t = threadIdx.x, lane = t & 31, w = t >> 5, wm = w & 1, wn = w >> 1;
    float* Sp = g_S + (size_t)bh * Nseq * Nseq;
#pragma unroll
    for (int mi = 0; mi < 4; mi++)
#pragma unroll
        for (int ni = 0; ni < 4; ni++) {
            int m = i0 + wm * 64 + mi * 16 + (lane >> 2);
            int nn = j0 + wn * 32 + ni * 8 + ((lane & 3) << 1);
            *(float2*)&Sp[(size_t)m * Nseq + nn] = make_float2(acc[mi][ni][0], acc[mi][ni][1]);
            *(float2*)&Sp[(size_t)(m + 8) * Nseq + nn] = make_float2(acc[mi][ni][2], acc[mi][ni][3]);
        }
}

// ======================= 3) causal row softmax -> P fp16 hi/lo ==============
__global__ __launch_bounds__(256) void softmax_kernel() {
    const int rgl = blockIdx.x;
    const int bh = rgl >> 11, i = rgl & (Nseq - 1);
    const size_t base = (size_t)bh * Nseq * Nseq + (size_t)i * Nseq;
    const float* row = g_S + base;
    const int L = i + 1;
    const int Lz = ((i >> 7) + 1) << 7;
    const int t = threadIdx.x;

    float v[8];
    int cnt = 0;
    float mx = -1e30f;
    for (int j = t; j < L; j += 256) { float x = row[j]; v[cnt++] = x; mx = fmaxf(mx, x); }

    __shared__ float red[256];
    red[t] = mx; __syncthreads();
    for (int s = 128; s > 0; s >>= 1) { if (t < s) red[t] = fmaxf(red[t], red[t + s]); __syncthreads(); }
    mx = red[0]; __syncthreads();

    float sum = 0.f;
    for (int k = 0; k < cnt; k++) { v[k] = expf(v[k] - mx); sum += v[k]; }
    red[t] = sum; __syncthreads();
    for (int s = 128; s > 0; s >>= 1) { if (t < s) red[t] += red[t + s]; __syncthreads(); }
    const float inv = 1.0f / red[0];

    cnt = 0;
    for (int j = t; j < L; j += 256) {
        float p = v[cnt++] * inv;
        __half h, l;
        split1h(p, h, l);
        g_Ph[base + j] = h; g_Pl[base + j] = l;
    }
    const __half z = __float2half_rn(0.f);
    for (int j = t; j < Lz; j += 256)
        if (j >= L) { g_Ph[base + j] = z; g_Pl[base + j] = z; }
}

// ======================= 4) Yh = P @ V (fp16 2-pass) ========================
__global__ __launch_bounds__(256, 2) void mm_pv_kernel() {
    extern __shared__ __align__(128) char smem[];
    uint32_t sb = smem_to_u32(smem);
    const int bh = blockIdx.z;
    const int i0 = blockIdx.y * 128, n0 = blockIdx.x * 128;
    const __half* Ph = g_Ph + (size_t)bh * Nseq * Nseq + (size_t)i0 * Nseq;
    const __half* Pl = g_Pl + (size_t)bh * Nseq * Nseq + (size_t)i0 * Nseq;
    const __half* Vv = g_VT + (size_t)bh * DHd * Nseq + (size_t)n0 * Nseq;
    float acc[4][4][4];
    gemm_mma_pv(Ph, Pl, Nseq, Vv, Nseq, i0 + 128, sb, acc);

    const int t = threadIdx.x, lane = t & 31, w = t >> 5, wm = w & 1, wn = w >> 1;
    float* Yp = g_YH + (size_t)bh * Nseq * Dm;
#pragma unroll
    for (int mi = 0; mi < 4; mi++)
#pragma unroll
        for (int ni = 0; ni < 4; ni++) {
            int m = i0 + wm * 64 + mi * 16 + (lane >> 2);
            int nn = n0 + wn * 32 + ni * 8 + ((lane & 3) << 1);
            *(float2*)&Yp[(size_t)m * Dm + nn] = make_float2(acc[mi][ni][0], acc[mi][ni][1]);
            *(float2*)&Yp[(size_t)(m + 8) * Dm + nn] = make_float2(acc[mi][ni][2], acc[mi][ni][3]);
        }
}

// ======================= 5) head-sum + QuickGELU + fp16 split ===============
__global__ __launch_bounds__(256) void reduce_kernel() {
    int idx = blockIdx.x * 256 + threadIdx.x;
    int m = idx >> 7;
    int c4 = (idx & 127) * 4;
    int b = m >> 11, n = m & (Nseq - 1);
    float4 s = make_float4(0.f, 0.f, 0.f, 0.f);
#pragma unroll
    for (int h = 0; h < Hh; h++) {
        const float4 v = *(const float4*)(g_YH + (size_t)((b * Hh + h) * Nseq + n) * Dm + c4);
        s.x += v.x; s.y += v.y; s.z += v.z; s.w += v.w;
    }
    s.x = s.x / (1.f + expf(-1.702f * s.x));
    s.y = s.y / (1.f + expf(-1.702f * s.y));
    s.z = s.z / (1.f + expf(-1.702f * s.z));
    s.w = s.w / (1.f + expf(-1.702f * s.w));
    unsigned h0, l0, h1, l1;
    split_pair16(s.x, s.y, h0, l0);
    split_pair16(s.z, s.w, h1, l1);
    *(uint2*)(g_G16h + (size_t)m * Dm + c4) = make_uint2(h0, h1);
    *(uint2*)(g_G16l + (size_t)m * Dm + c4) = make_uint2(l0, l1);
}

// ======================= 6) output projection (fp16 2-pass) =================
__global__ __launch_bounds__(256, 2) void mm_out_kernel(const float* __restrict__ bo,
                                                        float* __restrict__ Outp) {
    extern __shared__ __align__(128) char smem[];
    uint32_t sb = smem_to_u32(smem);
    const int bm = blockIdx.y * 128, bn = blockIdx.x * 128;
    const __half* Ah = g_G16h + (size_t)bm * Dm;
    const __half* Al = g_G16l + (size_t)bm * Dm;
    const __half* Bo = g_WoT16 + (size_t)bn * Dm;
    float acc[4][4][4];
    gemm_mma_pv(Ah, Al, Dm, Bo, Dm, Dm, sb, acc);

    const int t = threadIdx.x, lane = t & 31, w = t >> 5, wm = w & 1, wn = w >> 1;
#pragma unroll
    for (int mi = 0; mi < 4; mi++)
#pragma unroll
        for (int ni = 0; ni < 4; ni++) {
            int m = bm + wm * 64 + mi * 16 + (lane >> 2);
            int c = bn + wn * 32 + ni * 8 + ((lane & 3) << 1);
            float b0 = bo[c], b1 = bo[c + 1];
            *(float2*)&Outp[(size_t)m * Dm + c] =
                make_float2(acc[mi][ni][0] + b0, acc[mi][ni][1] + b1);
            *(float2*)&Outp[(size_t)(m + 8) * Dm + c] =
                make_float2(acc[mi][ni][2] + b0, acc[mi][ni][3] + b1);
        }
}

// ======================= launch =============================================
extern "C" void kernel_launch(void* const* d_in, const int* in_sizes, int n_in,
                              void* d_out, int out_size)
{
    const float* x    = (const float*)d_in[0];
    const float* cosr = (const float*)d_in[1];
    const float* sinr = (const float*)d_in[2];
    // d_in[3] = target_mask (causal tril; handled analytically)
    const float* Wq   = (const float*)d_in[4];
    const float* Wk   = (const float*)d_in[5];
    const float* Wv   = (const float*)d_in[6];
    const float* bv   = (const float*)d_in[7];
    const float* Wo   = (const float*)d_in[8];
    const float* bo   = (const float*)d_in[9];
    float* out = (float*)d_out;

    cudaFuncSetAttribute(mm_proj_kernel,  cudaFuncAttributeMaxDynamicSharedMemorySize, GEMM_SMEM);
    cudaFuncSetAttribute(mm_vproj_kernel, cudaFuncAttributeMaxDynamicSharedMemorySize, PV_SMEM);
    cudaFuncSetAttribute(mm_score_kernel, cudaFuncAttributeMaxDynamicSharedMemorySize, GEMM_SMEM);
    cudaFuncSetAttribute(mm_pv_kernel,    cudaFuncAttributeMaxDynamicSharedMemorySize, PV_SMEM);
    cudaFuncSetAttribute(mm_out_kernel,   cudaFuncAttributeMaxDynamicSharedMemorySize, PV_SMEM);

    __nv_bfloat16 *wth, *wtl;
    __half *wvt16, *wot16;
    cudaGetSymbolAddress((void**)&wth,   g_WTh);
    cudaGetSymbolAddress((void**)&wtl,   g_WTl);
    cudaGetSymbolAddress((void**)&wvt16, g_WvT16);
    cudaGetSymbolAddress((void**)&wot16, g_WoT16);

    xc_kernel<<<2048, 256>>>(x);
    wt_kernel<<<dim3(128, 16), dim3(32, 8)>>>(Wq, wth + 0 * (size_t)Ff * Dm,
                                              wtl + 0 * (size_t)Ff * Dm, Dm, Ff);
    wt_kernel<<<dim3(128, 16), dim3(32, 8)>>>(Wk, wth + 1 * (size_t)Ff * Dm,
                                              wtl + 1 * (size_t)Ff * Dm, Dm, Ff);
    wt16_kernel<<<dim3(128, 16), dim3(32, 8)>>>(Wv, wvt16, Dm, Ff);
    mm_proj_kernel<<<dim3(32, 32, 2), 256, GEMM_SMEM>>>(cosr, sinr);
    mm_vproj_kernel<<<dim3(32, 32), 256, PV_SMEM>>>(bv);
    mm_score_kernel<<<dim3(16, 16, BH), 256, GEMM_SMEM>>>();
    vt_kernel<<<dim3(64, 16, BH), dim3(32, 8)>>>();
    softmax_kernel<<<BH * Nseq, 256>>>();
    mm_pv_kernel<<<dim3(4, 16, BH), 256, PV_SMEM>>>();
    reduce_kernel<<<2048, 256>>>();
    wt16_kernel<<<dim3(16, 16), dim3(32, 8)>>>(Wo, wot16, Dm, Dm);
    mm_out_kernel<<<dim3(4, 32), 256, PV_SMEM>>>(bo, out);
}

// round 14
// speedup vs baseline: 1.8276x; 1.0106x over previous
#include <cuda_runtime.h>
#include <cuda_bf16.h>
#include <cuda_fp16.h>
#include <cstdint>
#include <math.h>

#define Bsz  2
#define Nseq 2048
#define Dm   512
#define Hh   8
#define DHd  512
#define Ff   4096
#define Mrows 4096   // Bsz*Nseq
#define BH   16      // Bsz*Hh

// ======================= scratch (device globals) ===========================
__device__ __align__(16) __nv_bfloat16 g_Xh[(size_t)Mrows * Dm];
__device__ __align__(16) __nv_bfloat16 g_Xl[(size_t)Mrows * Dm];
__device__ __align__(16) __half        g_X16h[(size_t)Mrows * Dm];
__device__ __align__(16) __half        g_X16l[(size_t)Mrows * Dm];
__device__ __align__(16) __nv_bfloat16 g_WTh[2 * (size_t)Ff * Dm];   // [mode][n][k] Q,K
__device__ __align__(16) __nv_bfloat16 g_WTl[2 * (size_t)Ff * Dm];
__device__ __align__(16) __half        g_WvT16[(size_t)Ff * Dm];     // [n][k] fp16
__device__ __align__(16) __half        g_WoT16[(size_t)Dm * Dm];
__device__ __align__(16) __nv_bfloat16 g_Qh[(size_t)Mrows * Ff];
__device__ __align__(16) __nv_bfloat16 g_Ql[(size_t)Mrows * Ff];
__device__ __align__(16) __nv_bfloat16 g_Kh[(size_t)Mrows * Ff];
__device__ __align__(16) __nv_bfloat16 g_Kl[(size_t)Mrows * Ff];
__device__ __align__(16) __half        g_VT[(size_t)BH * DHd * Nseq]; // [bh][f][tok], fp16
__device__ __align__(16) float         g_S [(size_t)BH * Nseq * Nseq];
__device__ __align__(16) __half        g_Ph[(size_t)BH * Nseq * Nseq];
__device__ __align__(16) __half        g_Pl[(size_t)BH * Nseq * Nseq];
__device__ __align__(16) float         g_YH[(size_t)BH * Nseq * Dm];
__device__ __align__(16) __half        g_G16h[(size_t)Mrows * Dm];
__device__ __align__(16) __half        g_G16l[(size_t)Mrows * Dm];

// ======================= helpers ===========================================
__device__ __forceinline__ uint32_t smem_to_u32(const void* p) {
    uint32_t a;
    asm("{ .reg .u64 t; cvta.to.shared.u64 t, %1; cvt.u32.u64 %0, t; }" : "=r"(a) : "l"(p));
    return a;
}
// SW64 swizzle for 64-byte rows (8 rows x 64B atom)
#define SWZ64(b) ((b) ^ (((b) >> 3) & 0x30))

#define LDSM_X4(r, addr) \
    asm volatile("ldmatrix.sync.aligned.m8n8.x4.shared.b16 {%0,%1,%2,%3}, [%4];" \
        : "=r"((r)[0]), "=r"((r)[1]), "=r"((r)[2]), "=r"((r)[3]) : "r"(addr))

#define MMA_BF16(d, a, b0, b1) \
    asm volatile("mma.sync.aligned.m16n8k16.row.col.f32.bf16.bf16.f32 " \
        "{%0,%1,%2,%3}, {%4,%5,%6,%7}, {%8,%9}, {%0,%1,%2,%3};" \
        : "+f"((d)[0]), "+f"((d)[1]), "+f"((d)[2]), "+f"((d)[3]) \
        : "r"((a)[0]), "r"((a)[1]), "r"((a)[2]), "r"((a)[3]), "r"(b0), "r"(b1))

#define MMA_F16(d, a, b0, b1) \
    asm volatile("mma.sync.aligned.m16n8k16.row.col.f32.f16.f16.f32 " \
        "{%0,%1,%2,%3}, {%4,%5,%6,%7}, {%8,%9}, {%0,%1,%2,%3};" \
        : "+f"((d)[0]), "+f"((d)[1]), "+f"((d)[2]), "+f"((d)[3]) \
        : "r"((a)[0]), "r"((a)[1]), "r"((a)[2]), "r"((a)[3]), "r"(b0), "r"(b1))

#define CP_ASYNC16(dst, src) \
    asm volatile("cp.async.cg.shared.global [%0], [%1], 16;" :: "r"(dst), "l"(src))
#define CP_COMMIT() asm volatile("cp.async.commit_group;")
#define CP_WAIT1()  asm volatile("cp.async.wait_group 1;")
#define CP_WAIT0()  asm volatile("cp.async.wait_group 0;")

// ======================= split helpers ======================================
__device__ __forceinline__ unsigned bf2(float a, float b) {
    return (unsigned)__bfloat16_as_ushort(__float2bfloat16(a)) |
           ((unsigned)__bfloat16_as_ushort(__float2bfloat16(b)) << 16);
}
__device__ __forceinline__ void split_pair(float a, float b, unsigned& h, unsigned& l) {
    __nv_bfloat16 ah = __float2bfloat16(a), bh = __float2bfloat16(b);
    h = (unsigned)__bfloat16_as_ushort(ah) | ((unsigned)__bfloat16_as_ushort(bh) << 16);
    l = bf2(a - __bfloat162float(ah), b - __bfloat162float(bh));
}
__device__ __forceinline__ void split_pair16(float a, float b, unsigned& h, unsigned& l) {
    __half ah = __float2half_rn(a), bh = __float2half_rn(b);
    h = (unsigned)__half_as_ushort(ah) | ((unsigned)__half_as_ushort(bh) << 16);
    __half al = __float2half_rn(a - __half2float(ah));
    __half bl = __float2half_rn(b - __half2float(bh));
    l = (unsigned)__half_as_ushort(al) | ((unsigned)__half_as_ushort(bl) << 16);
}
__device__ __forceinline__ void split1(float a, __nv_bfloat16& h, __nv_bfloat16& l) {
    h = __float2bfloat16(a);
    l = __float2bfloat16(a - __bfloat162float(h));
}
__device__ __forceinline__ void split1h(float a, __half& h, __half& l) {
    h = __float2half_rn(a);
    l = __float2half_rn(a - __half2float(h));
}

// ======================= mma.sync GEMM core (K-chunk 32, 3-stage) ===========
// C[128x128] = Ah*Bh + Ah*Bl + Al*Bh over K (bf16, 3-pass). Stage 32KB:
// aH|aL|bH|bL (8KB, 64B rows, SW64). 3 stages = 96KB -> 2 CTAs/SM.
// Pipeline: one __syncthreads per chunk; issue(c+2) overwrites stage (c-1)%3.
#define STG32 32768
#define GEMM_SMEM (3 * STG32)

__device__ __forceinline__ void mma_chunk32(uint32_t sst, int lane, int wm, int wn,
                                            float (&acc)[4][4][4]) {
    const uint32_t aH = sst, aL = sst + 8192, bB = sst + 16384, bL = sst + 24576;
#pragma unroll
    for (int kk = 0; kk < 2; kk++) {
        uint32_t bh[2][4], bl[2][4];
        const int brow = wn * 32 + (lane & 7) + ((lane >> 4) << 3);
        const int bcb = kk * 32 + (((lane >> 3) & 1) << 4);
#pragma unroll
        for (int nb = 0; nb < 2; nb++) {
            uint32_t off = SWZ64(((brow + nb * 16) << 6) + bcb);
            LDSM_X4(bh[nb], bB + off);
            LDSM_X4(bl[nb], bL + off);
        }
        const int acb = kk * 32 + ((lane >> 4) << 4);
#pragma unroll
        for (int mi = 0; mi < 4; mi++) {
            uint32_t ah[4], al[4];
            uint32_t off = SWZ64(((wm * 64 + mi * 16 + (lane & 15)) << 6) + acb);
            LDSM_X4(ah, aH + off);
            LDSM_X4(al, aL + off);
#pragma unroll
            for (int ni = 0; ni < 4; ni++) {
                const int nb = ni >> 1, p = (ni & 1) << 1;
                MMA_BF16(acc[mi][ni], ah, bh[nb][p], bh[nb][p + 1]);
                MMA_BF16(acc[mi][ni], ah, bl[nb][p], bl[nb][p + 1]);
                MMA_BF16(acc[mi][ni], al, bh[nb][p], bh[nb][p + 1]);
            }
        }
    }
}

__device__ __forceinline__ void issue_chunk32(
    uint32_t sbase, int c, int t,
    const __nv_bfloat16* Ah, const __nv_bfloat16* Al, size_t sA,
    const __nv_bfloat16* Bh, const __nv_bfloat16* Bl, size_t sB)
{
    const uint32_t sst = sbase + (uint32_t)(c % 3) * STG32;
    const __nv_bfloat16* ah = Ah + (c << 5);
    const __nv_bfloat16* al = Al + (c << 5);
    const __nv_bfloat16* bhp = Bh + (c << 5);
    const __nv_bfloat16* blp = Bl + (c << 5);
#pragma unroll
    for (int i = 0; i < 2; i++) {
        int u = t + (i << 8), r = u >> 2, cu = u & 3;
        uint32_t d = sst + SWZ64((r << 6) + (cu << 4));
        const size_t so = (size_t)r * sA + (cu << 3);
        CP_ASYNC16(d, ah + so);
        CP_ASYNC16(d + 8192, al + so);
    }
#pragma unroll
    for (int i = 0; i < 2; i++) {
        int u = t + (i << 8), r = u >> 2, cu = u & 3;
        uint32_t d = sst + 16384 + SWZ64((r << 6) + (cu << 4));
        const size_t so = (size_t)r * sB + (cu << 3);
        CP_ASYNC16(d, bhp + so);
        CP_ASYNC16(d + 8192, blp + so);
    }
    CP_COMMIT();
}

__device__ __forceinline__ void gemm_mma(
    const __nv_bfloat16* Ah, const __nv_bfloat16* Al, size_t sA,
    const __nv_bfloat16* Bh, const __nv_bfloat16* Bl, size_t sB,
    int K, uint32_t sbase, float (&acc)[4][4][4])
{
    const int t = threadIdx.x;
    const int lane = t & 31, w = t >> 5, wm = w & 1, wn = w >> 1;
#pragma unroll
    for (int mi = 0; mi < 4; mi++)
#pragma unroll
        for (int ni = 0; ni < 4; ni++)
#pragma unroll
            for (int r = 0; r < 4; r++) acc[mi][ni][r] = 0.f;

    const int NC = K >> 5;
    issue_chunk32(sbase, 0, t, Ah, Al, sA, Bh, Bl, sB);
    if (NC > 1) issue_chunk32(sbase, 1, t, Ah, Al, sA, Bh, Bl, sB);
    for (int c = 0; c < NC; c++) {
        if (c + 1 < NC) CP_WAIT1(); else CP_WAIT0();
        __syncthreads();
        if (c + 2 < NC) issue_chunk32(sbase, c + 2, t, Ah, Al, sA, Bh, Bl, sB);
        mma_chunk32(sbase + (uint32_t)(c % 3) * STG32, lane, wm, wn, acc);
    }
}

// ======================= fp16 2-pass core (stage 24KB: Ah|Al|B) =============
// C = (Ah + Al) * B, fp16 operands, fp32 accum. Used by PV, V-proj, out-proj.
#define STG24 24576
#define PV_SMEM (3 * STG24)

__device__ __forceinline__ void mma_chunk32_pv(uint32_t sst, int lane, int wm, int wn,
                                               float (&acc)[4][4][4]) {
    const uint32_t aH = sst, aL = sst + 8192, bB = sst + 16384;
#pragma unroll
    for (int kk = 0; kk < 2; kk++) {
        uint32_t bh[2][4];
        const int brow = wn * 32 + (lane & 7) + ((lane >> 4) << 3);
        const int bcb = kk * 32 + (((lane >> 3) & 1) << 4);
#pragma unroll
        for (int nb = 0; nb < 2; nb++) {
            uint32_t off = SWZ64(((brow + nb * 16) << 6) + bcb);
            LDSM_X4(bh[nb], bB + off);
        }
        const int acb = kk * 32 + ((lane >> 4) << 4);
#pragma unroll
        for (int mi = 0; mi < 4; mi++) {
            uint32_t ah[4], al[4];
            uint32_t off = SWZ64(((wm * 64 + mi * 16 + (lane & 15)) << 6) + acb);
            LDSM_X4(ah, aH + off);
            LDSM_X4(al, aL + off);
#pragma unroll
            for (int ni = 0; ni < 4; ni++) {
                const int nb = ni >> 1, p = (ni & 1) << 1;
                MMA_F16(acc[mi][ni], ah, bh[nb][p], bh[nb][p + 1]);
                MMA_F16(acc[mi][ni], al, bh[nb][p], bh[nb][p + 1]);
            }
        }
    }
}

__device__ __forceinline__ void issue_chunk32_pv(
    uint32_t sbase, int c, int t,
    const __half* Ph, const __half* Pl, size_t sA,
    const __half* Vv, size_t sB)
{
    const uint32_t sst = sbase + (uint32_t)(c % 3) * STG24;
    const __half* ph = Ph + (c << 5);
    const __half* pl = Pl + (c << 5);
    const __half* vp = Vv + (c << 5);
#pragma unroll
    for (int i = 0; i < 2; i++) {
        int u = t + (i << 8), r = u >> 2, cu = u & 3;
        uint32_t d = sst + SWZ64((r << 6) + (cu << 4));
        const size_t so = (size_t)r * sA + (cu << 3);
        CP_ASYNC16(d, ph + so);
        CP_ASYNC16(d + 8192, pl + so);
    }
#pragma unroll
    for (int i = 0; i < 2; i++) {
        int u = t + (i << 8), r = u >> 2, cu = u & 3;
        uint32_t d = sst + 16384 + SWZ64((r << 6) + (cu << 4));
        CP_ASYNC16(d, vp + (size_t)r * sB + (cu << 3));
    }
    CP_COMMIT();
}

__device__ __forceinline__ void gemm_mma_pv(
    const __half* Ph, const __half* Pl, size_t sA,
    const __half* Vv, size_t sB,
    int K, uint32_t sbase, float (&acc)[4][4][4])
{
    const int t = threadIdx.x;
    const int lane = t & 31, w = t >> 5, wm = w & 1, wn = w >> 1;
#pragma unroll
    for (int mi = 0; mi < 4; mi++)
#pragma unroll
        for (int ni = 0; ni < 4; ni++)
#pragma unroll
            for (int r = 0; r < 4; r++) acc[mi][ni][r] = 0.f;

    const int NC = K >> 5;
    issue_chunk32_pv(sbase, 0, t, Ph, Pl, sA, Vv, sB);
    if (NC > 1) issue_chunk32_pv(sbase, 1, t, Ph, Pl, sA, Vv, sB);
    for (int c = 0; c < NC; c++) {
        if (c + 1 < NC) CP_WAIT1(); else CP_WAIT0();
        __syncthreads();
        if (c + 2 < NC) issue_chunk32_pv(sbase, c + 2, t, Ph, Pl, sA, Vv, sB);
        mma_chunk32_pv(sbase + (uint32_t)(c % 3) * STG24, lane, wm, wn, acc);
    }
}

// ======================= prep kernels =======================================
__global__ __launch_bounds__(256) void xc_kernel(const float* __restrict__ x) {
    int i = blockIdx.x * 256 + threadIdx.x;
    float4 v = ((const float4*)x)[i];
    unsigned h0, l0, h1, l1;
    split_pair(v.x, v.y, h0, l0);
    split_pair(v.z, v.w, h1, l1);
    ((uint2*)g_Xh)[i] = make_uint2(h0, h1);
    ((uint2*)g_Xl)[i] = make_uint2(l0, l1);
    split_pair16(v.x, v.y, h0, l0);
    split_pair16(v.z, v.w, h1, l1);
    ((uint2*)g_X16h)[i] = make_uint2(h0, h1);
    ((uint2*)g_X16l)[i] = make_uint2(l0, l1);
}

__global__ void wt_kernel(const float* __restrict__ src, __nv_bfloat16* dh,
                          __nv_bfloat16* dl, int K, int NC) {
    __shared__ float tile[32][33];
    int n0 = blockIdx.x * 32, k0 = blockIdx.y * 32;
    int tx = threadIdx.x, ty = threadIdx.y;        // ty 0..7
#pragma unroll
    for (int r = 0; r < 4; r++)
        tile[ty + 8 * r][tx] = src[(size_t)(k0 + ty + 8 * r) * NC + n0 + tx];
    __syncthreads();
#pragma unroll
    for (int r = 0; r < 4; r++) {
        float v = tile[tx][ty + 8 * r];
        __nv_bfloat16 h, l;
        split1(v, h, l);
        size_t di = (size_t)(n0 + ty + 8 * r) * K + k0 + tx;
        dh[di] = h; dl[di] = l;
    }
}

// transpose to single fp16 (for Wv, Wo)
__global__ void wt16_kernel(const float* __restrict__ src, __half* dst,
                            int K, int NC) {
    __shared__ float tile[32][33];
    int n0 = blockIdx.x * 32, k0 = blockIdx.y * 32;
    int tx = threadIdx.x, ty = threadIdx.y;        // ty 0..7
#pragma unroll
    for (int r = 0; r < 4; r++)
        tile[ty + 8 * r][tx] = src[(size_t)(k0 + ty + 8 * r) * NC + n0 + tx];
    __syncthreads();
#pragma unroll
    for (int r = 0; r < 4; r++) {
        float v = tile[tx][ty + 8 * r];
        dst[(size_t)(n0 + ty + 8 * r) * K + k0 + tx] = __float2half_rn(v);
    }
}

// ======================= 1a) Q/K projection GEMM + RoPE epilogue ============
__global__ __launch_bounds__(256, 2) void mm_proj_kernel(
    const float* __restrict__ cosr, const float* __restrict__ sinr)
{
    extern __shared__ __align__(128) char smem[];
    uint32_t sb = smem_to_u32(smem);
    const int mode = blockIdx.z;   // 0=Q, 1=K
    const int bm = blockIdx.y * 128, bn = blockIdx.x * 128;
    const __nv_bfloat16* Ah = g_Xh + (size_t)bm * Dm;
    const __nv_bfloat16* Al = g_Xl + (size_t)bm * Dm;
    const __nv_bfloat16* Bh = g_WTh + ((size_t)mode * Ff + bn) * Dm;
    const __nv_bfloat16* Bl = g_WTl + ((size_t)mode * Ff + bn) * Dm;
    float acc[4][4][4];
    gemm_mma(Ah, Al, Dm, Bh, Bl, Dm, Dm, sb, acc);

    const int t = threadIdx.x, lane = t & 31, w = t >> 5, wm = w & 1, wn = w >> 1;
    __nv_bfloat16* OH = (mode == 0) ? g_Qh : g_Kh;
    __nv_bfloat16* OL = (mode == 0) ? g_Ql : g_Kl;
#pragma unroll
    for (int mi = 0; mi < 4; mi++)
#pragma unroll
        for (int ni = 0; ni < 4; ni++) {
            int m0 = bm + wm * 64 + mi * 16 + (lane >> 2);
            int c = bn + wn * 32 + ni * 8 + ((lane & 3) << 1);
#pragma unroll
            for (int half = 0; half < 2; half++) {
                int m = m0 + half * 8;
                int n = m & (Nseq - 1);
                float cr0 = cosr[(size_t)n * Ff + c];
                float sr0 = sinr[(size_t)n * Ff + c];
                float cr1 = cosr[(size_t)n * Ff + c + 1];
                float sr1 = sinr[(size_t)n * Ff + c + 1];
                float e = acc[mi][ni][half * 2];
                float o = acc[mi][ni][half * 2 + 1];
                float oe = e * cr0 - o * sr0;
                float oo = o * cr1 + e * sr1;
                unsigned hw, lw;
                split_pair(oe, oo, hw, lw);
                *(unsigned*)&OH[(size_t)m * Ff + c] = hw;
                *(unsigned*)&OL[(size_t)m * Ff + c] = lw;
            }
        }
}

// ======================= 1b) V projection (fp16 2-pass) + bias + transpose ==
// Epilogue writes VT[bh][f][tok] fp16 directly via a smem transpose staging
// tile (row stride 136 halves -> conflict-free 2B writes), replacing the
// fp32 g_V round-trip + standalone vt transpose kernel.
__global__ __launch_bounds__(256, 2) void mm_vproj_kernel(const float* __restrict__ bv)
{
    extern __shared__ __align__(128) char smem[];
    uint32_t sb = smem_to_u32(smem);
    const int bm = blockIdx.y * 128, bn = blockIdx.x * 128;
    const __half* Ah = g_X16h + (size_t)bm * Dm;
    const __half* Al = g_X16l + (size_t)bm * Dm;
    const __half* Bv = g_WvT16 + (size_t)bn * Dm;
    float acc[4][4][4];
    gemm_mma_pv(Ah, Al, Dm, Bv, Dm, Dm, sb, acc);

    const int t = threadIdx.x, lane = t & 31, w = t >> 5, wm = w & 1, wn = w >> 1;
    __syncthreads();                    // all MMAs done -> reuse stage smem
    __half* s16 = (__half*)smem;        // [128 f][136 stride] transposed tile
#pragma unroll
    for (int mi = 0; mi < 4; mi++)
#pragma unroll
        for (int ni = 0; ni < 4; ni++) {
            int ml = wm * 64 + mi * 16 + (lane >> 2);
            int cl = wn * 32 + ni * 8 + ((lane & 3) << 1);
            float b0 = bv[bn + cl], b1 = bv[bn + cl + 1];
#pragma unroll
            for (int half = 0; half < 2; half++) {
                int m2 = ml + half * 8;
                s16[cl * 136 + m2]       = __float2half_rn(acc[mi][ni][half * 2] + b0);
                s16[(cl + 1) * 136 + m2] = __float2half_rn(acc[mi][ni][half * 2 + 1] + b1);
            }
        }
    __syncthreads();
    const int b = bm >> 11, tok0 = bm & (Nseq - 1);
    const int h = bn >> 9, f0 = bn & (DHd - 1);
    __half* dst = g_VT + ((size_t)(b * Hh + h) * DHd + f0) * Nseq + tok0;
#pragma unroll
    for (int i = 0; i < 8; i++) {
        int u = t + (i << 8);           // 0..2047
        int f = u >> 4, mg = (u & 15) << 3;
        uint4 v = *(uint4*)&s16[f * 136 + mg];
        *(uint4*)(dst + (size_t)f * Nseq + mg) = v;
    }
}

// ======================= 2) S = Q K^T ======================================
__global__ __launch_bounds__(256, 2) void mm_score_kernel() {
    if (blockIdx.x > blockIdx.y) return;
    extern __shared__ __align__(128) char smem[];
    uint32_t sb = smem_to_u32(smem);
    const int bh = blockIdx.z, b = bh >> 3, h = bh & 7;
    const int i0 = blockIdx.y * 128, j0 = blockIdx.x * 128;
    const __nv_bfloat16* Ah = g_Qh + (size_t)(b * Nseq + i0) * Ff + h * DHd;
    const __nv_bfloat16* Al = g_Ql + (size_t)(b * Nseq + i0) * Ff + h * DHd;
    const __nv_bfloat16* Bh = g_Kh + (size_t)(b * Nseq + j0) * Ff + h * DHd;
    const __nv_bfloat16* Bl = g_Kl + (size_t)(b * Nseq + j0) * Ff + h * DHd;
    float acc[4][4][4];
    gemm_mma(Ah, Al, Ff, Bh, Bl, Ff, DHd, sb, acc);

    const int t = threadIdx.x, lane = t & 31, w = t >> 5, wm = w & 1, wn = w >> 1;
    float* Sp = g_S + (size_t)bh * Nseq * Nseq;
#pragma unroll
    for (int mi = 0; mi < 4; mi++)
#pragma unroll
        for (int ni = 0; ni < 4; ni++) {
            int m = i0 + wm * 64 + mi * 16 + (lane >> 2);
            int nn = j0 + wn * 32 + ni * 8 + ((lane & 3) << 1);
            *(float2*)&Sp[(size_t)m * Nseq + nn] = make_float2(acc[mi][ni][0], acc[mi][ni][1]);
            *(float2*)&Sp[(size_t)(m + 8) * Nseq + nn] = make_float2(acc[mi][ni][2], acc[mi][ni][3]);
        }
}

// ======================= 3) causal row softmax -> P fp16 hi/lo ==============
__global__ __launch_bounds__(256) void softmax_kernel() {
    const int rgl = blockIdx.x;
    const int bh = rgl >> 11, i = rgl & (Nseq - 1);
    const size_t base = (size_t)bh * Nseq * Nseq + (size_t)i * Nseq;
    const float* row = g_S + base;
    const int L = i + 1;
    const int Lz = ((i >> 7) + 1) << 7;
    const int t = threadIdx.x;

    float v[8];
    int cnt = 0;
    float mx = -1e30f;
    for (int j = t; j < L; j += 256) { float x = row[j]; v[cnt++] = x; mx = fmaxf(mx, x); }

    __shared__ float red[256];
    red[t] = mx; __syncthreads();
    for (int s = 128; s > 0; s >>= 1) { if (t < s) red[t] = fmaxf(red[t], red[t + s]); __syncthreads(); }
    mx = red[0]; __syncthreads();

    float sum = 0.f;
    for (int k = 0; k < cnt; k++) { v[k] = expf(v[k] - mx); sum += v[k]; }
    red[t] = sum; __syncthreads();
    for (int s = 128; s > 0; s >>= 1) { if (t < s) red[t] += red[t + s]; __syncthreads(); }
    const float inv = 1.0f / red[0];

    cnt = 0;
    for (int j = t; j < L; j += 256) {
        float p = v[cnt++] * inv;
        __half h, l;
        split1h(p, h, l);
        g_Ph[base + j] = h; g_Pl[base + j] = l;
    }
    const __half z = __float2half_rn(0.f);
    for (int j = t; j < Lz; j += 256)
        if (j >= L) { g_Ph[base + j] = z; g_Pl[base + j] = z; }
}

// ======================= 4) Yh = P @ V (fp16 2-pass) ========================
__global__ __launch_bounds__(256, 2) void mm_pv_kernel() {
    extern __shared__ __align__(128) char smem[];
    uint32_t sb = smem_to_u32(smem);
    const int bh = blockIdx.z;
    const int i0 = blockIdx.y * 128, n0 = blockIdx.x * 128;
    const __half* Ph = g_Ph + (size_t)bh * Nseq * Nseq + (size_t)i0 * Nseq;
    const __half* Pl = g_Pl + (size_t)bh * Nseq * Nseq + (size_t)i0 * Nseq;
    const __half* Vv = g_VT + (size_t)bh * DHd * Nseq + (size_t)n0 * Nseq;
    float acc[4][4][4];
    gemm_mma_pv(Ph, Pl, Nseq, Vv, Nseq, i0 + 128, sb, acc);

    const int t = threadIdx.x, lane = t & 31, w = t >> 5, wm = w & 1, wn = w >> 1;
    float* Yp = g_YH + (size_t)bh * Nseq * Dm;
#pragma unroll
    for (int mi = 0; mi < 4; mi++)
#pragma unroll
        for (int ni = 0; ni < 4; ni++) {
            int m = i0 + wm * 64 + mi * 16 + (lane >> 2);
            int nn = n0 + wn * 32 + ni * 8 + ((lane & 3) << 1);
            *(float2*)&Yp[(size_t)m * Dm + nn] = make_float2(acc[mi][ni][0], acc[mi][ni][1]);
            *(float2*)&Yp[(size_t)(m + 8) * Dm + nn] = make_float2(acc[mi][ni][2], acc[mi][ni][3]);
        }
}

// ======================= 5) head-sum + QuickGELU + fp16 split ===============
__global__ __launch_bounds__(256) void reduce_kernel() {
    int idx = blockIdx.x * 256 + threadIdx.x;
    int m = idx >> 7;
    int c4 = (idx & 127) * 4;
    int b = m >> 11, n = m & (Nseq - 1);
    float4 s = make_float4(0.f, 0.f, 0.f, 0.f);
#pragma unroll
    for (int h = 0; h < Hh; h++) {
        const float4 v = *(const float4*)(g_YH + (size_t)((b * Hh + h) * Nseq + n) * Dm + c4);
        s.x += v.x; s.y += v.y; s.z += v.z; s.w += v.w;
    }
    s.x = s.x / (1.f + expf(-1.702f * s.x));
    s.y = s.y / (1.f + expf(-1.702f * s.y));
    s.z = s.z / (1.f + expf(-1.702f * s.z));
    s.w = s.w / (1.f + expf(-1.702f * s.w));
    unsigned h0, l0, h1, l1;
    split_pair16(s.x, s.y, h0, l0);
    split_pair16(s.z, s.w, h1, l1);
    *(uint2*)(g_G16h + (size_t)m * Dm + c4) = make_uint2(h0, h1);
    *(uint2*)(g_G16l + (size_t)m * Dm + c4) = make_uint2(l0, l1);
}

// ======================= 6) output projection (fp16 2-pass) =================
__global__ __launch_bounds__(256, 2) void mm_out_kernel(const float* __restrict__ bo,
                                                        float* __restrict__ Outp) {
    extern __shared__ __align__(128) char smem[];
    uint32_t sb = smem_to_u32(smem);
    const int bm = blockIdx.y * 128, bn = blockIdx.x * 128;
    const __half* Ah = g_G16h + (size_t)bm * Dm;
    const __half* Al = g_G16l + (size_t)bm * Dm;
    const __half* Bo = g_WoT16 + (size_t)bn * Dm;
    float acc[4][4][4];
    gemm_mma_pv(Ah, Al, Dm, Bo, Dm, Dm, sb, acc);

    const int t = threadIdx.x, lane = t & 31, w = t >> 5, wm = w & 1, wn = w >> 1;
#pragma unroll
    for (int mi = 0; mi < 4; mi++)
#pragma unroll
        for (int ni = 0; ni < 4; ni++) {
            int m = bm + wm * 64 + mi * 16 + (lane >> 2);
            int c = bn + wn * 32 + ni * 8 + ((lane & 3) << 1);
            float b0 = bo[c], b1 = bo[c + 1];
            *(float2*)&Outp[(size_t)m * Dm + c] =
                make_float2(acc[mi][ni][0] + b0, acc[mi][ni][1] + b1);
            *(float2*)&Outp[(size_t)(m + 8) * Dm + c] =
                make_float2(acc[mi][ni][2] + b0, acc[mi][ni][3] + b1);
        }
}

// ======================= launch =============================================
extern "C" void kernel_launch(void* const* d_in, const int* in_sizes, int n_in,
                              void* d_out, int out_size)
{
    const float* x    = (const float*)d_in[0];
    const float* cosr = (const float*)d_in[1];
    const float* sinr = (const float*)d_in[2];
    // d_in[3] = target_mask (causal tril; handled analytically)
    const float* Wq   = (const float*)d_in[4];
    const float* Wk   = (const float*)d_in[5];
    const float* Wv   = (const float*)d_in[6];
    const float* bv   = (const float*)d_in[7];
    const float* Wo   = (const float*)d_in[8];
    const float* bo   = (const float*)d_in[9];
    float* out = (float*)d_out;

    cudaFuncSetAttribute(mm_proj_kernel,  cudaFuncAttributeMaxDynamicSharedMemorySize, GEMM_SMEM);
    cudaFuncSetAttribute(mm_vproj_kernel, cudaFuncAttributeMaxDynamicSharedMemorySize, PV_SMEM);
    cudaFuncSetAttribute(mm_score_kernel, cudaFuncAttributeMaxDynamicSharedMemorySize, GEMM_SMEM);
    cudaFuncSetAttribute(mm_pv_kernel,    cudaFuncAttributeMaxDynamicSharedMemorySize, PV_SMEM);
    cudaFuncSetAttribute(mm_out_kernel,   cudaFuncAttributeMaxDynamicSharedMemorySize, PV_SMEM);

    __nv_bfloat16 *wth, *wtl;
    __half *wvt16, *wot16;
    cudaGetSymbolAddress((void**)&wth,   g_WTh);
    cudaGetSymbolAddress((void**)&wtl,   g_WTl);
    cudaGetSymbolAddress((void**)&wvt16, g_WvT16);
    cudaGetSymbolAddress((void**)&wot16, g_WoT16);

    xc_kernel<<<2048, 256>>>(x);
    wt_kernel<<<dim3(128, 16), dim3(32, 8)>>>(Wq, wth + 0 * (size_t)Ff * Dm,
                                              wtl + 0 * (size_t)Ff * Dm, Dm, Ff);
    wt_kernel<<<dim3(128, 16), dim3(32, 8)>>>(Wk, wth + 1 * (size_t)Ff * Dm,
                                              wtl + 1 * (size_t)Ff * Dm, Dm, Ff);
    wt16_kernel<<<dim3(128, 16), dim3(32, 8)>>>(Wv, wvt16, Dm, Ff);
    mm_proj_kernel<<<dim3(32, 32, 2), 256, GEMM_SMEM>>>(cosr, sinr);
    mm_vproj_kernel<<<dim3(32, 32), 256, PV_SMEM>>>(bv);
    mm_score_kernel<<<dim3(16, 16, BH), 256, GEMM_SMEM>>>();
    softmax_kernel<<<BH * Nseq, 256>>>();
    mm_pv_kernel<<<dim3(4, 16, BH), 256, PV_SMEM>>>();
    reduce_kernel<<<2048, 256>>>();
    wt16_kernel<<<dim3(16, 16), dim3(32, 8)>>>(Wo, wot16, Dm, Dm);
    mm_out_kernel<<<dim3(4, 32), 256, PV_SMEM>>>(bo, out);
}

// round 15
// speedup vs baseline: 1.9567x; 1.0707x over previous
#include <cuda_runtime.h>
#include <cuda_bf16.h>
#include <cuda_fp16.h>
#include <cstdint>
#include <math.h>

#define Bsz  2
#define Nseq 2048
#define Dm   512
#define Hh   8
#define DHd  512
#define Ff   4096
#define Mrows 4096   // Bsz*Nseq
#define BH   16      // Bsz*Hh

// ======================= scratch (device globals) ===========================
__device__ __align__(16) __nv_bfloat16 g_Xh[(size_t)Mrows * Dm];
__device__ __align__(16) __nv_bfloat16 g_Xl[(size_t)Mrows * Dm];
__device__ __align__(16) __half        g_X16h[(size_t)Mrows * Dm];
__device__ __align__(16) __half        g_X16l[(size_t)Mrows * Dm];
__device__ __align__(16) __nv_bfloat16 g_WTh[2 * (size_t)Ff * Dm];   // [mode][n][k] Q,K
__device__ __align__(16) __nv_bfloat16 g_WTl[2 * (size_t)Ff * Dm];
__device__ __align__(16) __half        g_WvT16[(size_t)Ff * Dm];     // [n][k] fp16
__device__ __align__(16) __half        g_WoT16[(size_t)Dm * Dm];
__device__ __align__(16) __nv_bfloat16 g_Qh[(size_t)Mrows * Ff];
__device__ __align__(16) __nv_bfloat16 g_Ql[(size_t)Mrows * Ff];
__device__ __align__(16) __nv_bfloat16 g_Kh[(size_t)Mrows * Ff];
__device__ __align__(16) __nv_bfloat16 g_Kl[(size_t)Mrows * Ff];
__device__ __align__(16) __half        g_VT[(size_t)BH * DHd * Nseq]; // [bh][f][tok], fp16
__device__ __align__(16) float         g_S [(size_t)BH * Nseq * Nseq];
__device__ __align__(16) __half        g_Ph[(size_t)BH * Nseq * Nseq];
__device__ __align__(16) __half        g_Pl[(size_t)BH * Nseq * Nseq];
__device__ __align__(16) float         g_YH[(size_t)BH * Nseq * Dm];
__device__ __align__(16) __half        g_G16h[(size_t)Mrows * Dm];
__device__ __align__(16) __half        g_G16l[(size_t)Mrows * Dm];

// ======================= helpers ===========================================
__device__ __forceinline__ uint32_t smem_to_u32(const void* p) {
    uint32_t a;
    asm("{ .reg .u64 t; cvta.to.shared.u64 t, %1; cvt.u32.u64 %0, t; }" : "=r"(a) : "l"(p));
    return a;
}
// SW64 swizzle for 64-byte rows (8 rows x 64B atom)
#define SWZ64(b) ((b) ^ (((b) >> 3) & 0x30))

#define LDSM_X4(r, addr) \
    asm volatile("ldmatrix.sync.aligned.m8n8.x4.shared.b16 {%0,%1,%2,%3}, [%4];" \
        : "=r"((r)[0]), "=r"((r)[1]), "=r"((r)[2]), "=r"((r)[3]) : "r"(addr))

#define MMA_BF16(d, a, b0, b1) \
    asm volatile("mma.sync.aligned.m16n8k16.row.col.f32.bf16.bf16.f32 " \
        "{%0,%1,%2,%3}, {%4,%5,%6,%7}, {%8,%9}, {%0,%1,%2,%3};" \
        : "+f"((d)[0]), "+f"((d)[1]), "+f"((d)[2]), "+f"((d)[3]) \
        : "r"((a)[0]), "r"((a)[1]), "r"((a)[2]), "r"((a)[3]), "r"(b0), "r"(b1))

#define MMA_F16(d, a, b0, b1) \
    asm volatile("mma.sync.aligned.m16n8k16.row.col.f32.f16.f16.f32 " \
        "{%0,%1,%2,%3}, {%4,%5,%6,%7}, {%8,%9}, {%0,%1,%2,%3};" \
        : "+f"((d)[0]), "+f"((d)[1]), "+f"((d)[2]), "+f"((d)[3]) \
        : "r"((a)[0]), "r"((a)[1]), "r"((a)[2]), "r"((a)[3]), "r"(b0), "r"(b1))

#define CP_ASYNC16(dst, src) \
    asm volatile("cp.async.cg.shared.global [%0], [%1], 16;" :: "r"(dst), "l"(src))
#define CP_COMMIT() asm volatile("cp.async.commit_group;")
#define CP_WAIT1()  asm volatile("cp.async.wait_group 1;")
#define CP_WAIT0()  asm volatile("cp.async.wait_group 0;")

// ======================= split helpers ======================================
__device__ __forceinline__ unsigned bf2(float a, float b) {
    return (unsigned)__bfloat16_as_ushort(__float2bfloat16(a)) |
           ((unsigned)__bfloat16_as_ushort(__float2bfloat16(b)) << 16);
}
__device__ __forceinline__ void split_pair(float a, float b, unsigned& h, unsigned& l) {
    __nv_bfloat16 ah = __float2bfloat16(a), bh = __float2bfloat16(b);
    h = (unsigned)__bfloat16_as_ushort(ah) | ((unsigned)__bfloat16_as_ushort(bh) << 16);
    l = bf2(a - __bfloat162float(ah), b - __bfloat162float(bh));
}
__device__ __forceinline__ void split_pair16(float a, float b, unsigned& h, unsigned& l) {
    __half ah = __float2half_rn(a), bh = __float2half_rn(b);
    h = (unsigned)__half_as_ushort(ah) | ((unsigned)__half_as_ushort(bh) << 16);
    __half al = __float2half_rn(a - __half2float(ah));
    __half bl = __float2half_rn(b - __half2float(bh));
    l = (unsigned)__half_as_ushort(al) | ((unsigned)__half_as_ushort(bl) << 16);
}
__device__ __forceinline__ void split1(float a, __nv_bfloat16& h, __nv_bfloat16& l) {
    h = __float2bfloat16(a);
    l = __float2bfloat16(a - __bfloat162float(h));
}

// ======================= mma.sync GEMM core (K-chunk 32, 3-stage) ===========
// C[128x128] = Ah*Bh + Ah*Bl + Al*Bh over K (bf16, 3-pass). Stage 32KB:
// aH|aL|bH|bL (8KB, 64B rows, SW64). 3 stages = 96KB -> 2 CTAs/SM.
// Pipeline: one __syncthreads per chunk; issue(c+2) overwrites stage (c-1)%3.
#define STG32 32768
#define GEMM_SMEM (3 * STG32)

__device__ __forceinline__ void mma_chunk32(uint32_t sst, int lane, int wm, int wn,
                                            float (&acc)[4][4][4]) {
    const uint32_t aH = sst, aL = sst + 8192, bB = sst + 16384, bL = sst + 24576;
#pragma unroll
    for (int kk = 0; kk < 2; kk++) {
        uint32_t bh[2][4], bl[2][4];
        const int brow = wn * 32 + (lane & 7) + ((lane >> 4) << 3);
        const int bcb = kk * 32 + (((lane >> 3) & 1) << 4);
#pragma unroll
        for (int nb = 0; nb < 2; nb++) {
            uint32_t off = SWZ64(((brow + nb * 16) << 6) + bcb);
            LDSM_X4(bh[nb], bB + off);
            LDSM_X4(bl[nb], bL + off);
        }
        const int acb = kk * 32 + ((lane >> 4) << 4);
#pragma unroll
        for (int mi = 0; mi < 4; mi++) {
            uint32_t ah[4], al[4];
            uint32_t off = SWZ64(((wm * 64 + mi * 16 + (lane & 15)) << 6) + acb);
            LDSM_X4(ah, aH + off);
            LDSM_X4(al, aL + off);
#pragma unroll
            for (int ni = 0; ni < 4; ni++) {
                const int nb = ni >> 1, p = (ni & 1) << 1;
                MMA_BF16(acc[mi][ni], ah, bh[nb][p], bh[nb][p + 1]);
                MMA_BF16(acc[mi][ni], ah, bl[nb][p], bl[nb][p + 1]);
                MMA_BF16(acc[mi][ni], al, bh[nb][p], bh[nb][p + 1]);
            }
        }
    }
}

__device__ __forceinline__ void issue_chunk32(
    uint32_t sbase, int c, int t,
    const __nv_bfloat16* Ah, const __nv_bfloat16* Al, size_t sA,
    const __nv_bfloat16* Bh, const __nv_bfloat16* Bl, size_t sB)
{
    const uint32_t sst = sbase + (uint32_t)(c % 3) * STG32;
    const __nv_bfloat16* ah = Ah + (c << 5);
    const __nv_bfloat16* al = Al + (c << 5);
    const __nv_bfloat16* bhp = Bh + (c << 5);
    const __nv_bfloat16* blp = Bl + (c << 5);
#pragma unroll
    for (int i = 0; i < 2; i++) {
        int u = t + (i << 8), r = u >> 2, cu = u & 3;
        uint32_t d = sst + SWZ64((r << 6) + (cu << 4));
        const size_t so = (size_t)r * sA + (cu << 3);
        CP_ASYNC16(d, ah + so);
        CP_ASYNC16(d + 8192, al + so);
    }
#pragma unroll
    for (int i = 0; i < 2; i++) {
        int u = t + (i << 8), r = u >> 2, cu = u & 3;
        uint32_t d = sst + 16384 + SWZ64((r << 6) + (cu << 4));
        const size_t so = (size_t)r * sB + (cu << 3);
        CP_ASYNC16(d, bhp + so);
        CP_ASYNC16(d + 8192, blp + so);
    }
    CP_COMMIT();
}

__device__ __forceinline__ void gemm_mma(
    const __nv_bfloat16* Ah, const __nv_bfloat16* Al, size_t sA,
    const __nv_bfloat16* Bh, const __nv_bfloat16* Bl, size_t sB,
    int K, uint32_t sbase, float (&acc)[4][4][4])
{
    const int t = threadIdx.x;
    const int lane = t & 31, w = t >> 5, wm = w & 1, wn = w >> 1;
#pragma unroll
    for (int mi = 0; mi < 4; mi++)
#pragma unroll
        for (int ni = 0; ni < 4; ni++)
#pragma unroll
            for (int r = 0; r < 4; r++) acc[mi][ni][r] = 0.f;

    const int NC = K >> 5;
    issue_chunk32(sbase, 0, t, Ah, Al, sA, Bh, Bl, sB);
    if (NC > 1) issue_chunk32(sbase, 1, t, Ah, Al, sA, Bh, Bl, sB);
    for (int c = 0; c < NC; c++) {
        if (c + 1 < NC) CP_WAIT1(); else CP_WAIT0();
        __syncthreads();
        if (c + 2 < NC) issue_chunk32(sbase, c + 2, t, Ah, Al, sA, Bh, Bl, sB);
        mma_chunk32(sbase + (uint32_t)(c % 3) * STG32, lane, wm, wn, acc);
    }
}

// ======================= fp16 2-pass core (stage 24KB: Ah|Al|B) =============
// C = (Ah + Al) * B, fp16 operands, fp32 accum. Used by PV, V-proj, out-proj.
#define STG24 24576
#define PV_SMEM (3 * STG24)

__device__ __forceinline__ void mma_chunk32_pv(uint32_t sst, int lane, int wm, int wn,
                                               float (&acc)[4][4][4]) {
    const uint32_t aH = sst, aL = sst + 8192, bB = sst + 16384;
#pragma unroll
    for (int kk = 0; kk < 2; kk++) {
        uint32_t bh[2][4];
        const int brow = wn * 32 + (lane & 7) + ((lane >> 4) << 3);
        const int bcb = kk * 32 + (((lane >> 3) & 1) << 4);
#pragma unroll
        for (int nb = 0; nb < 2; nb++) {
            uint32_t off = SWZ64(((brow + nb * 16) << 6) + bcb);
            LDSM_X4(bh[nb], bB + off);
        }
        const int acb = kk * 32 + ((lane >> 4) << 4);
#pragma unroll
        for (int mi = 0; mi < 4; mi++) {
            uint32_t ah[4], al[4];
            uint32_t off = SWZ64(((wm * 64 + mi * 16 + (lane & 15)) << 6) + acb);
            LDSM_X4(ah, aH + off);
            LDSM_X4(al, aL + off);
#pragma unroll
            for (int ni = 0; ni < 4; ni++) {
                const int nb = ni >> 1, p = (ni & 1) << 1;
                MMA_F16(acc[mi][ni], ah, bh[nb][p], bh[nb][p + 1]);
                MMA_F16(acc[mi][ni], al, bh[nb][p], bh[nb][p + 1]);
            }
        }
    }
}

__device__ __forceinline__ void issue_chunk32_pv(
    uint32_t sbase, int c, int t,
    const __half* Ph, const __half* Pl, size_t sA,
    const __half* Vv, size_t sB)
{
    const uint32_t sst = sbase + (uint32_t)(c % 3) * STG24;
    const __half* ph = Ph + (c << 5);
    const __half* pl = Pl + (c << 5);
    const __half* vp = Vv + (c << 5);
#pragma unroll
    for (int i = 0; i < 2; i++) {
        int u = t + (i << 8), r = u >> 2, cu = u & 3;
        uint32_t d = sst + SWZ64((r << 6) + (cu << 4));
        const size_t so = (size_t)r * sA + (cu << 3);
        CP_ASYNC16(d, ph + so);
        CP_ASYNC16(d + 8192, pl + so);
    }
#pragma unroll
    for (int i = 0; i < 2; i++) {
        int u = t + (i << 8), r = u >> 2, cu = u & 3;
        uint32_t d = sst + 16384 + SWZ64((r << 6) + (cu << 4));
        CP_ASYNC16(d, vp + (size_t)r * sB + (cu << 3));
    }
    CP_COMMIT();
}

__device__ __forceinline__ void gemm_mma_pv(
    const __half* Ph, const __half* Pl, size_t sA,
    const __half* Vv, size_t sB,
    int K, uint32_t sbase, float (&acc)[4][4][4])
{
    const int t = threadIdx.x;
    const int lane = t & 31, w = t >> 5, wm = w & 1, wn = w >> 1;
#pragma unroll
    for (int mi = 0; mi < 4; mi++)
#pragma unroll
        for (int ni = 0; ni < 4; ni++)
#pragma unroll
            for (int r = 0; r < 4; r++) acc[mi][ni][r] = 0.f;

    const int NC = K >> 5;
    issue_chunk32_pv(sbase, 0, t, Ph, Pl, sA, Vv, sB);
    if (NC > 1) issue_chunk32_pv(sbase, 1, t, Ph, Pl, sA, Vv, sB);
    for (int c = 0; c < NC; c++) {
        if (c + 1 < NC) CP_WAIT1(); else CP_WAIT0();
        __syncthreads();
        if (c + 2 < NC) issue_chunk32_pv(sbase, c + 2, t, Ph, Pl, sA, Vv, sB);
        mma_chunk32_pv(sbase + (uint32_t)(c % 3) * STG24, lane, wm, wn, acc);
    }
}

// ======================= prep kernels =======================================
__global__ __launch_bounds__(256) void xc_kernel(const float* __restrict__ x) {
    int i = blockIdx.x * 256 + threadIdx.x;
    float4 v = ((const float4*)x)[i];
    unsigned h0, l0, h1, l1;
    split_pair(v.x, v.y, h0, l0);
    split_pair(v.z, v.w, h1, l1);
    ((uint2*)g_Xh)[i] = make_uint2(h0, h1);
    ((uint2*)g_Xl)[i] = make_uint2(l0, l1);
    split_pair16(v.x, v.y, h0, l0);
    split_pair16(v.z, v.w, h1, l1);
    ((uint2*)g_X16h)[i] = make_uint2(h0, h1);
    ((uint2*)g_X16l)[i] = make_uint2(l0, l1);
}

__global__ void wt_kernel(const float* __restrict__ src, __nv_bfloat16* dh,
                          __nv_bfloat16* dl, int K, int NC) {
    __shared__ float tile[32][33];
    int n0 = blockIdx.x * 32, k0 = blockIdx.y * 32;
    int tx = threadIdx.x, ty = threadIdx.y;        // ty 0..7
#pragma unroll
    for (int r = 0; r < 4; r++)
        tile[ty + 8 * r][tx] = src[(size_t)(k0 + ty + 8 * r) * NC + n0 + tx];
    __syncthreads();
#pragma unroll
    for (int r = 0; r < 4; r++) {
        float v = tile[tx][ty + 8 * r];
        __nv_bfloat16 h, l;
        split1(v, h, l);
        size_t di = (size_t)(n0 + ty + 8 * r) * K + k0 + tx;
        dh[di] = h; dl[di] = l;
    }
}

// transpose to single fp16 (for Wv, Wo)
__global__ void wt16_kernel(const float* __restrict__ src, __half* dst,
                            int K, int NC) {
    __shared__ float tile[32][33];
    int n0 = blockIdx.x * 32, k0 = blockIdx.y * 32;
    int tx = threadIdx.x, ty = threadIdx.y;        // ty 0..7
#pragma unroll
    for (int r = 0; r < 4; r++)
        tile[ty + 8 * r][tx] = src[(size_t)(k0 + ty + 8 * r) * NC + n0 + tx];
    __syncthreads();
#pragma unroll
    for (int r = 0; r < 4; r++) {
        float v = tile[tx][ty + 8 * r];
        dst[(size_t)(n0 + ty + 8 * r) * K + k0 + tx] = __float2half_rn(v);
    }
}

// ======================= 1a) Q/K projection GEMM + RoPE epilogue ============
__global__ __launch_bounds__(256, 2) void mm_proj_kernel(
    const float* __restrict__ cosr, const float* __restrict__ sinr)
{
    extern __shared__ __align__(128) char smem[];
    uint32_t sb = smem_to_u32(smem);
    const int mode = blockIdx.z;   // 0=Q, 1=K
    const int bm = blockIdx.y * 128, bn = blockIdx.x * 128;
    const __nv_bfloat16* Ah = g_Xh + (size_t)bm * Dm;
    const __nv_bfloat16* Al = g_Xl + (size_t)bm * Dm;
    const __nv_bfloat16* Bh = g_WTh + ((size_t)mode * Ff + bn) * Dm;
    const __nv_bfloat16* Bl = g_WTl + ((size_t)mode * Ff + bn) * Dm;
    float acc[4][4][4];
    gemm_mma(Ah, Al, Dm, Bh, Bl, Dm, Dm, sb, acc);

    const int t = threadIdx.x, lane = t & 31, w = t >> 5, wm = w & 1, wn = w >> 1;
    __nv_bfloat16* OH = (mode == 0) ? g_Qh : g_Kh;
    __nv_bfloat16* OL = (mode == 0) ? g_Ql : g_Kl;
#pragma unroll
    for (int mi = 0; mi < 4; mi++)
#pragma unroll
        for (int ni = 0; ni < 4; ni++) {
            int m0 = bm + wm * 64 + mi * 16 + (lane >> 2);
            int c = bn + wn * 32 + ni * 8 + ((lane & 3) << 1);
#pragma unroll
            for (int half = 0; half < 2; half++) {
                int m = m0 + half * 8;
                int n = m & (Nseq - 1);
                float cr0 = cosr[(size_t)n * Ff + c];
                float sr0 = sinr[(size_t)n * Ff + c];
                float cr1 = cosr[(size_t)n * Ff + c + 1];
                float sr1 = sinr[(size_t)n * Ff + c + 1];
                float e = acc[mi][ni][half * 2];
                float o = acc[mi][ni][half * 2 + 1];
                float oe = e * cr0 - o * sr0;
                float oo = o * cr1 + e * sr1;
                unsigned hw, lw;
                split_pair(oe, oo, hw, lw);
                *(unsigned*)&OH[(size_t)m * Ff + c] = hw;
                *(unsigned*)&OL[(size_t)m * Ff + c] = lw;
            }
        }
}

// ======================= 1b) V projection (fp16 2-pass) + bias + transpose ==
__global__ __launch_bounds__(256, 2) void mm_vproj_kernel(const float* __restrict__ bv)
{
    extern __shared__ __align__(128) char smem[];
    uint32_t sb = smem_to_u32(smem);
    const int bm = blockIdx.y * 128, bn = blockIdx.x * 128;
    const __half* Ah = g_X16h + (size_t)bm * Dm;
    const __half* Al = g_X16l + (size_t)bm * Dm;
    const __half* Bv = g_WvT16 + (size_t)bn * Dm;
    float acc[4][4][4];
    gemm_mma_pv(Ah, Al, Dm, Bv, Dm, Dm, sb, acc);

    const int t = threadIdx.x, lane = t & 31, w = t >> 5, wm = w & 1, wn = w >> 1;
    __syncthreads();                    // all MMAs done -> reuse stage smem
    __half* s16 = (__half*)smem;        // [128 f][136 stride] transposed tile
#pragma unroll
    for (int mi = 0; mi < 4; mi++)
#pragma unroll
        for (int ni = 0; ni < 4; ni++) {
            int ml = wm * 64 + mi * 16 + (lane >> 2);
            int cl = wn * 32 + ni * 8 + ((lane & 3) << 1);
            float b0 = bv[bn + cl], b1 = bv[bn + cl + 1];
#pragma unroll
            for (int half = 0; half < 2; half++) {
                int m2 = ml + half * 8;
                s16[cl * 136 + m2]       = __float2half_rn(acc[mi][ni][half * 2] + b0);
                s16[(cl + 1) * 136 + m2] = __float2half_rn(acc[mi][ni][half * 2 + 1] + b1);
            }
        }
    __syncthreads();
    const int b = bm >> 11, tok0 = bm & (Nseq - 1);
    const int h = bn >> 9, f0 = bn & (DHd - 1);
    __half* dst = g_VT + ((size_t)(b * Hh + h) * DHd + f0) * Nseq + tok0;
#pragma unroll
    for (int i = 0; i < 8; i++) {
        int u = t + (i << 8);           // 0..2047
        int f = u >> 4, mg = (u & 15) << 3;
        uint4 v = *(uint4*)&s16[f * 136 + mg];
        *(uint4*)(dst + (size_t)f * Nseq + mg) = v;
    }
}

// ======================= 2) S = Q K^T ======================================
__global__ __launch_bounds__(256, 2) void mm_score_kernel() {
    if (blockIdx.x > blockIdx.y) return;
    extern __shared__ __align__(128) char smem[];
    uint32_t sb = smem_to_u32(smem);
    const int bh = blockIdx.z, b = bh >> 3, h = bh & 7;
    const int i0 = blockIdx.y * 128, j0 = blockIdx.x * 128;
    const __nv_bfloat16* Ah = g_Qh + (size_t)(b * Nseq + i0) * Ff + h * DHd;
    const __nv_bfloat16* Al = g_Ql + (size_t)(b * Nseq + i0) * Ff + h * DHd;
    const __nv_bfloat16* Bh = g_Kh + (size_t)(b * Nseq + j0) * Ff + h * DHd;
    const __nv_bfloat16* Bl = g_Kl + (size_t)(b * Nseq + j0) * Ff + h * DHd;
    float acc[4][4][4];
    gemm_mma(Ah, Al, Ff, Bh, Bl, Ff, DHd, sb, acc);

    const int t = threadIdx.x, lane = t & 31, w = t >> 5, wm = w & 1, wn = w >> 1;
    float* Sp = g_S + (size_t)bh * Nseq * Nseq;
#pragma unroll
    for (int mi = 0; mi < 4; mi++)
#pragma unroll
        for (int ni = 0; ni < 4; ni++) {
            int m = i0 + wm * 64 + mi * 16 + (lane >> 2);
            int nn = j0 + wn * 32 + ni * 8 + ((lane & 3) << 1);
            *(float2*)&Sp[(size_t)m * Nseq + nn] = make_float2(acc[mi][ni][0], acc[mi][ni][1]);
            *(float2*)&Sp[(size_t)(m + 8) * Nseq + nn] = make_float2(acc[mi][ni][2], acc[mi][ni][3]);
        }
}

// ======================= 3) causal row softmax -> P fp16 hi/lo ==============
// Vectorized: float4 S loads over [0,Lz) (all 128-aligned blocks are score-
// written; j>i masked in-register), uint2 (2x half2) P stores.
__global__ __launch_bounds__(256) void softmax_kernel() {
    const int rgl = blockIdx.x;
    const int bh = rgl >> 11, i = rgl & (Nseq - 1);
    const size_t base = (size_t)bh * Nseq * Nseq + (size_t)i * Nseq;
    const float* row = g_S + base;
    const int Lz = ((i >> 7) + 1) << 7;         // row span actually written
    const int t = threadIdx.x;

    float v[8];
    float mx = -1e30f;
    int nit = 0;
#pragma unroll
    for (int it = 0; it < 2; it++) {
        int j = (t << 2) + (it << 10);
        if (j < Lz) {
            float4 x4 = *(const float4*)(row + j);
            v[it * 4 + 0] = (j + 0 <= i) ? x4.x : -1e30f;
            v[it * 4 + 1] = (j + 1 <= i) ? x4.y : -1e30f;
            v[it * 4 + 2] = (j + 2 <= i) ? x4.z : -1e30f;
            v[it * 4 + 3] = (j + 3 <= i) ? x4.w : -1e30f;
#pragma unroll
            for (int q = 0; q < 4; q++) mx = fmaxf(mx, v[it * 4 + q]);
            nit = it + 1;
        }
    }

    __shared__ float red[256];
    red[t] = mx; __syncthreads();
    for (int s = 128; s > 0; s >>= 1) { if (t < s) red[t] = fmaxf(red[t], red[t + s]); __syncthreads(); }
    mx = red[0]; __syncthreads();

    float sum = 0.f;
    for (int it = 0; it < nit; it++)
#pragma unroll
        for (int q = 0; q < 4; q++) {
            float p = (v[it * 4 + q] > -1e29f) ? __expf(v[it * 4 + q] - mx) : 0.f;
            v[it * 4 + q] = p;
            sum += p;
        }
    red[t] = sum; __syncthreads();
    for (int s = 128; s > 0; s >>= 1) { if (t < s) red[t] += red[t + s]; __syncthreads(); }
    const float inv = 1.0f / red[0];

    for (int it = 0; it < nit; it++) {
        int j = (t << 2) + (it << 10);
        float p0 = v[it * 4 + 0] * inv, p1 = v[it * 4 + 1] * inv;
        float p2 = v[it * 4 + 2] * inv, p3 = v[it * 4 + 3] * inv;
        unsigned h01, l01, h23, l23;
        split_pair16(p0, p1, h01, l01);
        split_pair16(p2, p3, h23, l23);
        *(uint2*)&g_Ph[base + j] = make_uint2(h01, h23);
        *(uint2*)&g_Pl[base + j] = make_uint2(l01, l23);
    }
}

// ======================= 4) Yh = P @ V (fp16 2-pass, heavy blocks first) ====
__global__ __launch_bounds__(256, 2) void mm_pv_kernel() {
    extern __shared__ __align__(128) char smem[];
    uint32_t sb = smem_to_u32(smem);
    const int bh = blockIdx.z;
    const int i0 = (15 - blockIdx.y) * 128;     // longest CTAs launch first
    const int n0 = blockIdx.x * 128;
    const __half* Ph = g_Ph + (size_t)bh * Nseq * Nseq + (size_t)i0 * Nseq;
    const __half* Pl = g_Pl + (size_t)bh * Nseq * Nseq + (size_t)i0 * Nseq;
    const __half* Vv = g_VT + (size_t)bh * DHd * Nseq + (size_t)n0 * Nseq;
    float acc[4][4][4];
    gemm_mma_pv(Ph, Pl, Nseq, Vv, Nseq, i0 + 128, sb, acc);

    const int t = threadIdx.x, lane = t & 31, w = t >> 5, wm = w & 1, wn = w >> 1;
    float* Yp = g_YH + (size_t)bh * Nseq * Dm;
#pragma unroll
    for (int mi = 0; mi < 4; mi++)
#pragma unroll
        for (int ni = 0; ni < 4; ni++) {
            int m = i0 + wm * 64 + mi * 16 + (lane >> 2);
            int nn = n0 + wn * 32 + ni * 8 + ((lane & 3) << 1);
            *(float2*)&Yp[(size_t)m * Dm + nn] = make_float2(acc[mi][ni][0], acc[mi][ni][1]);
            *(float2*)&Yp[(size_t)(m + 8) * Dm + nn] = make_float2(acc[mi][ni][2], acc[mi][ni][3]);
        }
}

// ======================= 5) head-sum + QuickGELU + fp16 split ===============
__global__ __launch_bounds__(256) void reduce_kernel() {
    int idx = blockIdx.x * 256 + threadIdx.x;
    int m = idx >> 7;
    int c4 = (idx & 127) * 4;
    int b = m >> 11, n = m & (Nseq - 1);
    float4 s = make_float4(0.f, 0.f, 0.f, 0.f);
#pragma unroll
    for (int h = 0; h < Hh; h++) {
        const float4 v = *(const float4*)(g_YH + (size_t)((b * Hh + h) * Nseq + n) * Dm + c4);
        s.x += v.x; s.y += v.y; s.z += v.z; s.w += v.w;
    }
    s.x = s.x / (1.f + __expf(-1.702f * s.x));
    s.y = s.y / (1.f + __expf(-1.702f * s.y));
    s.z = s.z / (1.f + __expf(-1.702f * s.z));
    s.w = s.w / (1.f + __expf(-1.702f * s.w));
    unsigned h0, l0, h1, l1;
    split_pair16(s.x, s.y, h0, l0);
    split_pair16(s.z, s.w, h1, l1);
    *(uint2*)(g_G16h + (size_t)m * Dm + c4) = make_uint2(h0, h1);
    *(uint2*)(g_G16l + (size_t)m * Dm + c4) = make_uint2(l0, l1);
}

// ======================= 6) output projection (fp16 2-pass) =================
__global__ __launch_bounds__(256, 2) void mm_out_kernel(const float* __restrict__ bo,
                                                        float* __restrict__ Outp) {
    extern __shared__ __align__(128) char smem[];
    uint32_t sb = smem_to_u32(smem);
    const int bm = blockIdx.y * 128, bn = blockIdx.x * 128;
    const __half* Ah = g_G16h + (size_t)bm * Dm;
    const __half* Al = g_G16l + (size_t)bm * Dm;
    const __half* Bo = g_WoT16 + (size_t)bn * Dm;
    float acc[4][4][4];
    gemm_mma_pv(Ah, Al, Dm, Bo, Dm, Dm, sb, acc);

    const int t = threadIdx.x, lane = t & 31, w = t >> 5, wm = w & 1, wn = w >> 1;
#pragma unroll
    for (int mi = 0; mi < 4; mi++)
#pragma unroll
        for (int ni = 0; ni < 4; ni++) {
            int m = bm + wm * 64 + mi * 16 + (lane >> 2);
            int c = bn + wn * 32 + ni * 8 + ((lane & 3) << 1);
            float b0 = bo[c], b1 = bo[c + 1];
            *(float2*)&Outp[(size_t)m * Dm + c] =
                make_float2(acc[mi][ni][0] + b0, acc[mi][ni][1] + b1);
            *(float2*)&Outp[(size_t)(m + 8) * Dm + c] =
                make_float2(acc[mi][ni][2] + b0, acc[mi][ni][3] + b1);
        }
}

// ======================= launch =============================================
extern "C" void kernel_launch(void* const* d_in, const int* in_sizes, int n_in,
                              void* d_out, int out_size)
{
    const float* x    = (const float*)d_in[0];
    const float* cosr = (const float*)d_in[1];
    const float* sinr = (const float*)d_in[2];
    // d_in[3] = target_mask (causal tril; handled analytically)
    const float* Wq   = (const float*)d_in[4];
    const float* Wk   = (const float*)d_in[5];
    const float* Wv   = (const float*)d_in[6];
    const float* bv   = (const float*)d_in[7];
    const float* Wo   = (const float*)d_in[8];
    const float* bo   = (const float*)d_in[9];
    float* out = (float*)d_out;

    cudaFuncSetAttribute(mm_proj_kernel,  cudaFuncAttributeMaxDynamicSharedMemorySize, GEMM_SMEM);
    cudaFuncSetAttribute(mm_vproj_kernel, cudaFuncAttributeMaxDynamicSharedMemorySize, PV_SMEM);
    cudaFuncSetAttribute(mm_score_kernel, cudaFuncAttributeMaxDynamicSharedMemorySize, GEMM_SMEM);
    cudaFuncSetAttribute(mm_pv_kernel,    cudaFuncAttributeMaxDynamicSharedMemorySize, PV_SMEM);
    cudaFuncSetAttribute(mm_out_kernel,   cudaFuncAttributeMaxDynamicSharedMemorySize, PV_SMEM);

    __nv_bfloat16 *wth, *wtl;
    __half *wvt16, *wot16;
    cudaGetSymbolAddress((void**)&wth,   g_WTh);
    cudaGetSymbolAddress((void**)&wtl,   g_WTl);
    cudaGetSymbolAddress((void**)&wvt16, g_WvT16);
    cudaGetSymbolAddress((void**)&wot16, g_WoT16);

    xc_kernel<<<2048, 256>>>(x);
    wt_kernel<<<dim3(128, 16), dim3(32, 8)>>>(Wq, wth + 0 * (size_t)Ff * Dm,
                                              wtl + 0 * (size_t)Ff * Dm, Dm, Ff);
    wt_kernel<<<dim3(128, 16), dim3(32, 8)>>>(Wk, wth + 1 * (size_t)Ff * Dm,
                                              wtl + 1 * (size_t)Ff * Dm, Dm, Ff);
    wt16_kernel<<<dim3(128, 16), dim3(32, 8)>>>(Wv, wvt16, Dm, Ff);
    mm_proj_kernel<<<dim3(32, 32, 2), 256, GEMM_SMEM>>>(cosr, sinr);
    mm_vproj_kernel<<<dim3(32, 32), 256, PV_SMEM>>>(bv);
    mm_score_kernel<<<dim3(16, 16, BH), 256, GEMM_SMEM>>>();
    softmax_kernel<<<BH * Nseq, 256>>>();
    mm_pv_kernel<<<dim3(4, 16, BH), 256, PV_SMEM>>>();
    reduce_kernel<<<2048, 256>>>();
    wt16_kernel<<<dim3(16, 16), dim3(32, 8)>>>(Wo, wot16, Dm, Dm);
    mm_out_kernel<<<dim3(4, 32), 256, PV_SMEM>>>(bo, out);
}